// round 3
// baseline (speedup 1.0000x reference)
#include <cuda_runtime.h>

// ---------------- problem constants ----------------
#define BATCH   128
#define LTOT    720
#define FEAT    128
#define SEGL    24
#define WINN    15
#define NPREDK  4
#define DDIM    128
#define HDIM    512
#define NROWS   (BATCH*FEAT)          // 16384
#define EPSC    1e-6f
#define EPS2    1e-12f
#define MAXNC   0.99999f              // 1 - 1e-5
#define CLIPC   0.99999988f           // float32(1 - 1e-7)
#define DECAYF  0.9f

// global scratch (static __device__, no allocs)
__device__ float g_t0[(size_t)NPREDK * NROWS * DDIM];   // t0 latents [k][bf][d]
__device__ float g_z [(size_t)WINN   * NROWS * DDIM];   // window z   [slot][bf][d]
__device__ float g_W2t[24 * HDIM];                      // W2 transposed [j][c]

// ---------------- f32x2 packed-FMA helpers ----------------
static __device__ __forceinline__ unsigned long long pack2(float x, float y) {
    unsigned long long r;
    asm("mov.b64 %0, {%1,%2};" : "=l"(r) : "f"(x), "f"(y));
    return r;
}
static __device__ __forceinline__ void unpack2(unsigned long long a, float &x, float &y) {
    asm("mov.b64 {%0,%1}, %2;" : "=f"(x), "=f"(y) : "l"(a));
}
static __device__ __forceinline__ void fma2(unsigned long long &a,
                                            unsigned long long b,
                                            unsigned long long c) {
    asm("fma.rn.f32x2 %0, %1, %2, %0;" : "+l"(a) : "l"(b), "l"(c));
}

// ---------------- warp math helpers ----------------
static __device__ __forceinline__ float wred(float v) {
#pragma unroll
    for (int o = 16; o > 0; o >>= 1) v += __shfl_xor_sync(0xffffffffu, v, o);
    return v;
}

struct F4 { float x, y, z, w; };

static __device__ __forceinline__ float dotred(const F4 &a, const F4 &b) {
    return wred(a.x*b.x + a.y*b.y + a.z*b.z + a.w*b.w);
}

// logmap(x, y) on the Poincare ball (C=1)
static __device__ __forceinline__ F4 logmap_f(const F4 &x, float sqx,
                                              const F4 &y, float sqy) {
    float xy  = dotred(x, y);
    float txy = -2.0f * xy;
    float cx  = 1.0f + txy + sqy;
    float cy  = 1.0f - sqx;
    float den = fmaxf(1.0f + txy + sqx*sqy, EPSC);
    float inv = 1.0f / den;
    F4 d;
    d.x = (cy*y.x - cx*x.x) * inv;
    d.y = (cy*y.y - cx*x.y) * inv;
    d.z = (cy*y.z - cx*x.z) * inv;
    d.w = (cy*y.w - cx*x.w) * inv;
    float sqd = dotred(d, d);
    float nd  = sqrtf(fmaxf(sqd, EPS2));
    float s   = fmaxf(cy, EPSC) * atanhf(fminf(nd, CLIPC)) / nd;
    F4 r = { d.x*s, d.y*s, d.z*s, d.w*s };
    return r;
}

// expmap0(v) followed by _project; returns z and ||z||^2
static __device__ __forceinline__ void expmap0_f(const F4 &t, F4 &z, float &sqz) {
    float sq = dotred(t, t);
    float n  = sqrtf(fmaxf(sq, EPS2));
    float sc = tanhf(n) / n;
    F4 r = { t.x*sc, t.y*sc, t.z*sc, t.w*sc };
    float sqr = dotred(r, r);
    float nr  = sqrtf(fmaxf(sqr, EPS2));
    if (nr > MAXNC) {
        float s = MAXNC / nr;
        r.x *= s; r.y *= s; r.z *= s; r.w *= s;
        sqr *= s * s;
    }
    z = r; sqz = sqr;
}

// expmap(x, v) followed by _project; returns z and ||z||^2
static __device__ __forceinline__ void expmap_f(const F4 &x, float sqx, const F4 &v,
                                                F4 &zout, float &sqout) {
    float m   = fmaxf(1.0f - sqx, EPSC);
    float sqv = dotred(v, v);
    float nv  = sqrtf(fmaxf(sqv, EPS2));
    float th  = tanhf(nv / m);
    float sc  = th / nv;
    F4 sec = { v.x*sc, v.y*sc, v.z*sc, v.w*sc };
    float xy = dotred(x, sec);
    float y2 = dotred(sec, sec);
    float ca  = 1.0f + 2.0f*xy + y2;
    float cb  = 1.0f - sqx;
    float den = fmaxf(1.0f + 2.0f*xy + sqx*y2, EPSC);
    float inv = 1.0f / den;
    F4 r = { (ca*x.x + cb*sec.x)*inv, (ca*x.y + cb*sec.y)*inv,
             (ca*x.z + cb*sec.z)*inv, (ca*x.w + cb*sec.w)*inv };
    float sqr = dotred(r, r);
    float nr  = sqrtf(fmaxf(sqr, EPS2));
    if (nr > MAXNC) {
        float s = MAXNC / nr;
        r.x *= s; r.y *= s; r.z *= s; r.w *= s;
        sqr *= s * s;
    }
    zout = r; sqout = sqr;
}

// ============================================================================
// Kernel 1a: tan-GEMV + expmap0 -> g_z.  One warp per row; 8 consecutive f per
// block so input loads are block-cooperative and coalesced.
// ============================================================================
#define SXP 484   // tile row pitch: 484 mod 32 = 4 -> 8 ff-rows hit distinct banks

__global__ void __launch_bounds__(256, 3)
gemv_kernel(const float* __restrict__ trend,  const float* __restrict__ scoarse,
            const float* __restrict__ sfine,  const float* __restrict__ resid,
            const float* __restrict__ W_t, const float* __restrict__ b_t,
            const float* __restrict__ W_c, const float* __restrict__ b_c,
            const float* __restrict__ W_f, const float* __restrict__ b_f,
            const float* __restrict__ W_r, const float* __restrict__ b_r)
{
    __shared__ float sX[8][SXP];   // per-warp-row: 4 streams x 120 timesteps

    const int tid  = threadIdx.x;
    const int wid  = tid >> 5;
    const int lane = tid & 31;

    const int row  = blockIdx.x * 8 + wid;
    const int b    = row >> 7;
    const int f0   = (blockIdx.x * 8) & 127;
    const size_t base_b = (size_t)b * LTOT * FEAT + f0;

    F4 bias;
    {
        float4 t1 = __ldg(reinterpret_cast<const float4*>(b_t) + lane);
        float4 t2 = __ldg(reinterpret_cast<const float4*>(b_c) + lane);
        float4 t3 = __ldg(reinterpret_cast<const float4*>(b_f) + lane);
        float4 t4 = __ldg(reinterpret_cast<const float4*>(b_r) + lane);
        bias.x = t1.x + t2.x + t3.x + t4.x;
        bias.y = t1.y + t2.y + t3.y + t4.y;
        bias.z = t1.z + t2.z + t3.z + t4.z;
        bias.w = t1.w + t2.w + t3.w + t4.w;
    }
    const unsigned long long bias01 = pack2(bias.x, bias.y);
    const unsigned long long bias23 = pack2(bias.z, bias.w);

    for (int p = 0; p < 3; ++p) {
        __syncthreads();
        const int l0 = 360 + p * 120;

        // block-cooperative coalesced load
#pragma unroll
        for (int st = 0; st < 4; ++st) {
            const float* src = (st == 0 ? trend : st == 1 ? scoarse :
                                st == 2 ? sfine : resid);
#pragma unroll
            for (int it = 0; it < 4; ++it) {
                int idx = tid + it * 256;
                if (idx < 960) {
                    int ff = idx & 7;
                    int i  = idx >> 3;
                    sX[ff][st * 120 + i] =
                        __ldg(&src[base_b + (size_t)(l0 + i) * FEAT + ff]);
                }
            }
        }
        __syncthreads();

        unsigned long long acc[5][2];
#pragma unroll
        for (int q = 0; q < 5; ++q) { acc[q][0] = bias01; acc[q][1] = bias23; }

#pragma unroll
        for (int st = 0; st < 4; ++st) {
            const float* W = (st == 0 ? W_t : st == 1 ? W_c : st == 2 ? W_f : W_r);
#pragma unroll 4
            for (int s = 0; s < SEGL; ++s) {
                ulonglong2 wv = __ldg(reinterpret_cast<const ulonglong2*>(W + s * DDIM) + lane);
#pragma unroll
                for (int q = 0; q < 5; ++q) {
                    float xv = sX[wid][st * 120 + q * SEGL + s];
                    unsigned long long xb = pack2(xv, xv);
                    fma2(acc[q][0], xb, wv.x);
                    fma2(acc[q][1], xb, wv.y);
                }
            }
        }

        // expmap0 per slot, write z to global
#pragma unroll
        for (int q = 0; q < 5; ++q) {
            F4 t;
            unpack2(acc[q][0], t.x, t.y);
            unpack2(acc[q][1], t.z, t.w);
            F4 z; float sqz;
            expmap0_f(t, z, sqz);
            const int slot = p * 5 + q;
            *reinterpret_cast<float4*>(
                &g_z[((size_t)slot * NROWS + row) * DDIM + lane * 4]) =
                make_float4(z.x, z.y, z.z, z.w);
        }
    }
}

// ============================================================================
// Kernel 1b: hyperbolic velocity chain + predictions -> g_t0.
// One warp per row; rolling 3-deep z window (low registers, high occupancy).
// ============================================================================
static __device__ __forceinline__ F4 ldz(int slot, int row, int lane) {
    float4 v = __ldg(reinterpret_cast<const float4*>(
        &g_z[((size_t)slot * NROWS + row) * DDIM + lane * 4]));
    F4 r = { v.x, v.y, v.z, v.w };
    return r;
}

__global__ void __launch_bounds__(256, 3)
chain_kernel(const float* __restrict__ alpha_p)
{
    const int tid  = threadIdx.x;
    const int wid  = tid >> 5;
    const int lane = tid & 31;
    const int row  = blockIdx.x * 8 + wid;

    // weights (replicates reference construction order)
    float s = 0.0f, wv = 1.0f;
#pragma unroll
    for (int j = 13; j >= 0; --j) { s += wv; if (j > 0) wv *= DECAYF; }
    // after loop wv = 0.9^13 = ws[0]
    const float w0  = wv / s;
    const float w13 = 1.0f / s;
    const float invd = 1.0f / DECAYF;

    F4 za = ldz(0, row, lane);
    F4 zb = ldz(1, row, lane);
    F4 zc = ldz(2, row, lane);
    float sqa = dotred(za, za);
    float sqb = dotred(zb, zb);

    F4 avg = {0,0,0,0};
    F4 vel0, vel1, vel2;
    float wj = w0;

#pragma unroll
    for (int j = 0; j < 14; ++j) {
        F4 vel = logmap_f(za, sqa, zb, sqb);
        avg.x += wj * vel.x; avg.y += wj * vel.y;
        avg.z += wj * vel.z; avg.w += wj * vel.w;
        if (j == 0) vel0 = vel;
        else if (j == 1) vel1 = vel;
        else if (j == 2) vel2 = vel;
        wj *= invd;
        // shift window
        za = zb; sqa = sqb;
        zb = zc; sqb = dotred(zb, zb);
        if (j + 3 < WINN) zc = ldz(j + 3, row, lane);
    }

    const float alpha = __ldg(alpha_p);
    F4 zl = za; float sql = sqa;   // after loop za == z[14] (last)
#pragma unroll
    for (int k = 0; k < NPREDK; ++k) {
        F4 v = { avg.x * alpha, avg.y * alpha, avg.z * alpha, avg.w * alpha };
        F4 zn; float sqn;
        expmap_f(zl, sql, v, zn, sqn);

        float n  = sqrtf(fmaxf(sqn, EPS2));
        float sc = atanhf(fminf(n, CLIPC)) / n;
        *reinterpret_cast<float4*>(
            &g_t0[((size_t)k * NROWS + row) * DDIM + lane * 4]) =
            make_float4(zn.x * sc, zn.y * sc, zn.z * sc, zn.w * sc);

        if (k < 3) {
            F4 vn = logmap_f(zl, sql, zn, sqn);
            F4 vk = (k == 0 ? vel0 : (k == 1 ? vel1 : vel2));
            avg.x = (avg.x - w0 * vk.x) * DECAYF + w13 * vn.x;
            avg.y = (avg.y - w0 * vk.y) * DECAYF + w13 * vn.y;
            avg.z = (avg.z - w0 * vk.z) * DECAYF + w13 * vn.z;
            avg.w = (avg.w - w0 * vk.w) * DECAYF + w13 * vn.w;
        }
        zl = zn; sql = sqn;
    }
}

// ============================================================================
// Kernel 2a: transpose W2 -> g_W2t[j][c] (one-time tiny kernel)
// ============================================================================
__global__ void w2t_kernel(const float* __restrict__ W2) {
    int idx = blockIdx.x * 256 + threadIdx.x;
    if (idx < 24 * HDIM) {
        int j = idx >> 9;          // / 512
        int c = idx & (HDIM - 1);
        g_W2t[idx] = __ldg(&W2[(size_t)c * 24 + j]);
    }
}

// ============================================================================
// Kernel 2b: batched MLP  out = relu(t0 @ W1 + b1) @ W2 + b2 (transposed write).
// 256 threads, M-tile 32 (4 rows x 8 cols per thread), N in 2 chunks of 256.
// smem 49.3KB, <=85 regs -> 3 blocks (24 warps) per SM.
// ============================================================================
__global__ void __launch_bounds__(256, 3)
mlp_kernel(const float* __restrict__ W1, const float* __restrict__ b1,
           const float* __restrict__ b2, float* __restrict__ out)
{
    __shared__ float As[32 * 128];      // A tile [r][k]        (16 KB)
    __shared__ float Hs[32 * 260];      // hidden chunk [r][c]  (33.3 KB, pitch 260)

    const int tid = threadIdx.x;
    const int m0  = blockIdx.x * 32;

    // load A tile (coalesced float4): 1024 float4 / 256 threads = 4 each
    {
        const float4* gsrc = reinterpret_cast<const float4*>(&g_t0[(size_t)m0 * DDIM]);
        float4* dst = reinterpret_cast<float4*>(As);
#pragma unroll
        for (int i = 0; i < 4; ++i)
            dst[tid + 256 * i] = __ldg(gsrc + tid + 256 * i);
    }
    __syncthreads();

    const int rg = tid >> 5;     // warp id: 4-row group (gemm1) / 3-j group (gemm2)
    const int cg = tid & 31;     // lane: 8 cols (gemm1, split 2x4) / out row (gemm2)

    unsigned long long accp[3] = {0ull, 0ull, 0ull};

#pragma unroll
    for (int nc = 0; nc < 2; ++nc) {
        const int cbase = nc * 256;

        // ---- GEMM1: H[r][c] = relu(sum_k A[r][k] * W1[k][c] + b1[c]) ----
        unsigned long long hacc[4][4];
        {
            float4 bA = __ldg(reinterpret_cast<const float4*>(b1 + cbase) + cg);
            float4 bB = __ldg(reinterpret_cast<const float4*>(b1 + cbase + 128) + cg);
            unsigned long long h0 = pack2(bA.x, bA.y), h1 = pack2(bA.z, bA.w);
            unsigned long long h2 = pack2(bB.x, bB.y), h3 = pack2(bB.z, bB.w);
#pragma unroll
            for (int i = 0; i < 4; ++i) {
                hacc[i][0] = h0; hacc[i][1] = h1; hacc[i][2] = h2; hacc[i][3] = h3;
            }
        }
        const float* w1p = W1 + cbase + cg * 4;
#pragma unroll 2
        for (int k4 = 0; k4 < 32; ++k4) {
            const int k = k4 * 4;
            float4 a4[4];
#pragma unroll
            for (int i = 0; i < 4; ++i)
                a4[i] = *reinterpret_cast<const float4*>(&As[(rg * 4 + i) * 128 + k]);
#pragma unroll
            for (int kk = 0; kk < 4; ++kk) {
                const float* wr = w1p + (size_t)(k + kk) * HDIM;
                ulonglong2 wA = __ldg(reinterpret_cast<const ulonglong2*>(wr));
                ulonglong2 wB = __ldg(reinterpret_cast<const ulonglong2*>(wr + 128));
#pragma unroll
                for (int i = 0; i < 4; ++i) {
                    float a = (kk == 0 ? a4[i].x : kk == 1 ? a4[i].y :
                               kk == 2 ? a4[i].z : a4[i].w);
                    unsigned long long ab = pack2(a, a);
                    fma2(hacc[i][0], ab, wA.x);
                    fma2(hacc[i][1], ab, wA.y);
                    fma2(hacc[i][2], ab, wB.x);
                    fma2(hacc[i][3], ab, wB.y);
                }
            }
        }
        __syncthreads();   // previous chunk's Hs readers done
        // relu + store hidden chunk (two halves: cols cg*4 and 128+cg*4)
#pragma unroll
        for (int i = 0; i < 4; ++i) {
            float h0, h1, h2, h3, h4, h5, h6, h7;
            unpack2(hacc[i][0], h0, h1);
            unpack2(hacc[i][1], h2, h3);
            unpack2(hacc[i][2], h4, h5);
            unpack2(hacc[i][3], h6, h7);
            int r = rg * 4 + i;
            *reinterpret_cast<float4*>(&Hs[r * 260 + cg * 4]) =
                make_float4(fmaxf(h0,0.f), fmaxf(h1,0.f), fmaxf(h2,0.f), fmaxf(h3,0.f));
            *reinterpret_cast<float4*>(&Hs[r * 260 + 128 + cg * 4]) =
                make_float4(fmaxf(h4,0.f), fmaxf(h5,0.f), fmaxf(h6,0.f), fmaxf(h7,0.f));
        }
        __syncthreads();

        // ---- GEMM2: out[r][j] += sum_c H[r][c] * W2t[j][c] ----
        const float* w2t = g_W2t + (size_t)(rg * 3) * HDIM + cbase;
#pragma unroll 4
        for (int c4 = 0; c4 < 64; ++c4) {
            const int c = c4 * 4;
            float4 h4 = *reinterpret_cast<const float4*>(&Hs[cg * 260 + c]);
            unsigned long long hA = pack2(h4.x, h4.y);
            unsigned long long hB = pack2(h4.z, h4.w);
#pragma unroll
            for (int jj = 0; jj < 3; ++jj) {
                ulonglong2 wv = __ldg(reinterpret_cast<const ulonglong2*>(
                    w2t + (size_t)jj * HDIM + c));
                fma2(accp[jj], hA, wv.x);
                fma2(accp[jj], hB, wv.y);
            }
        }
    }

    // write transposed output: out[b, kidx*24 + j, f]
    const int kidx = m0 >> 14;
    const int bf0  = m0 & 16383;
    const int bb   = bf0 >> 7;
    const int f    = (bf0 & 127) + cg;   // 32-row tiles never cross a b boundary
#pragma unroll
    for (int jj = 0; jj < 3; ++jj) {
        int j = rg * 3 + jj;
        float s0, s1;
        unpack2(accp[jj], s0, s1);
        float val = __ldg(&b2[j]) + s0 + s1;
        out[((size_t)bb * 96 + kidx * 24 + j) * 128 + f] = val;
    }
}

// ============================================================================
extern "C" void kernel_launch(void* const* d_in, const int* in_sizes, int n_in,
                              void* d_out, int out_size) {
    const float* trend   = (const float*)d_in[0];
    const float* scoarse = (const float*)d_in[1];
    const float* sfine   = (const float*)d_in[2];
    const float* resid   = (const float*)d_in[3];
    const float* W_t = (const float*)d_in[4];
    const float* b_t = (const float*)d_in[5];
    const float* W_c = (const float*)d_in[6];
    const float* b_c = (const float*)d_in[7];
    const float* W_f = (const float*)d_in[8];
    const float* b_f = (const float*)d_in[9];
    const float* W_r = (const float*)d_in[10];
    const float* b_r = (const float*)d_in[11];
    const float* alpha = (const float*)d_in[12];
    const float* W1 = (const float*)d_in[13];
    const float* b1 = (const float*)d_in[14];
    const float* W2 = (const float*)d_in[15];
    const float* b2 = (const float*)d_in[16];

    gemv_kernel<<<NROWS / 8, 256>>>(trend, scoarse, sfine, resid,
                                    W_t, b_t, W_c, b_c, W_f, b_f, W_r, b_r);
    w2t_kernel<<<48, 256>>>(W2);
    chain_kernel<<<NROWS / 8, 256>>>(alpha);
    mlp_kernel<<<(NPREDK * NROWS) / 32, 256>>>(W1, b1, b2, (float*)d_out);
}

// round 4
// speedup vs baseline: 1.0066x; 1.0066x over previous
#include <cuda_runtime.h>

// ---------------- problem constants ----------------
#define BATCH   128
#define LTOT    720
#define FEAT    128
#define SEGL    24
#define WINN    15
#define NPREDK  4
#define DDIM    128
#define HDIM    512
#define NROWS   (BATCH*FEAT)          // 16384
#define EPSC    1e-6f
#define EPS2    1e-12f
#define MAXNC   0.99999f              // 1 - 1e-5
#define CLIPC   0.99999988f           // float32(1 - 1e-7)
#define DECAYF  0.9f

// global scratch (static __device__, no allocs)
__device__ float g_t0[(size_t)NPREDK * NROWS * DDIM];   // t0 latents [k][bf][d]
__device__ float g_z [(size_t)WINN   * NROWS * DDIM];   // window z   [slot][bf][d]
__device__ float g_W2t[24 * HDIM];                      // W2 transposed [j][c]

// ---------------- f32x2 packed-FMA helpers ----------------
static __device__ __forceinline__ unsigned long long pack2(float x, float y) {
    unsigned long long r;
    asm("mov.b64 %0, {%1,%2};" : "=l"(r) : "f"(x), "f"(y));
    return r;
}
static __device__ __forceinline__ void unpack2(unsigned long long a, float &x, float &y) {
    asm("mov.b64 {%0,%1}, %2;" : "=f"(x), "=f"(y) : "l"(a));
}
static __device__ __forceinline__ void fma2(unsigned long long &a,
                                            unsigned long long b,
                                            unsigned long long c) {
    asm("fma.rn.f32x2 %0, %1, %2, %0;" : "+l"(a) : "l"(b), "l"(c));
}

// ---------------- warp math helpers ----------------
static __device__ __forceinline__ float wred(float v) {
#pragma unroll
    for (int o = 16; o > 0; o >>= 1) v += __shfl_xor_sync(0xffffffffu, v, o);
    return v;
}

struct F4 { float x, y, z, w; };

static __device__ __forceinline__ float dotred(const F4 &a, const F4 &b) {
    return wred(a.x*b.x + a.y*b.y + a.z*b.z + a.w*b.w);
}

// logmap(x, y) on the Poincare ball (C=1)
static __device__ __forceinline__ F4 logmap_f(const F4 &x, float sqx,
                                              const F4 &y, float sqy) {
    float xy  = dotred(x, y);
    float txy = -2.0f * xy;
    float cx  = 1.0f + txy + sqy;
    float cy  = 1.0f - sqx;
    float den = fmaxf(1.0f + txy + sqx*sqy, EPSC);
    float inv = 1.0f / den;
    F4 d;
    d.x = (cy*y.x - cx*x.x) * inv;
    d.y = (cy*y.y - cx*x.y) * inv;
    d.z = (cy*y.z - cx*x.z) * inv;
    d.w = (cy*y.w - cx*x.w) * inv;
    float sqd = dotred(d, d);
    float nd  = sqrtf(fmaxf(sqd, EPS2));
    float s   = fmaxf(cy, EPSC) * atanhf(fminf(nd, CLIPC)) / nd;
    F4 r = { d.x*s, d.y*s, d.z*s, d.w*s };
    return r;
}

// expmap0(v) followed by _project; returns z and ||z||^2
static __device__ __forceinline__ void expmap0_f(const F4 &t, F4 &z, float &sqz) {
    float sq = dotred(t, t);
    float n  = sqrtf(fmaxf(sq, EPS2));
    float sc = tanhf(n) / n;
    F4 r = { t.x*sc, t.y*sc, t.z*sc, t.w*sc };
    float sqr = dotred(r, r);
    float nr  = sqrtf(fmaxf(sqr, EPS2));
    if (nr > MAXNC) {
        float s = MAXNC / nr;
        r.x *= s; r.y *= s; r.z *= s; r.w *= s;
        sqr *= s * s;
    }
    z = r; sqz = sqr;
}

// expmap(x, v) followed by _project; returns z and ||z||^2
static __device__ __forceinline__ void expmap_f(const F4 &x, float sqx, const F4 &v,
                                                F4 &zout, float &sqout) {
    float m   = fmaxf(1.0f - sqx, EPSC);
    float sqv = dotred(v, v);
    float nv  = sqrtf(fmaxf(sqv, EPS2));
    float th  = tanhf(nv / m);
    float sc  = th / nv;
    F4 sec = { v.x*sc, v.y*sc, v.z*sc, v.w*sc };
    float xy = dotred(x, sec);
    float y2 = dotred(sec, sec);
    float ca  = 1.0f + 2.0f*xy + y2;
    float cb  = 1.0f - sqx;
    float den = fmaxf(1.0f + 2.0f*xy + sqx*y2, EPSC);
    float inv = 1.0f / den;
    F4 r = { (ca*x.x + cb*sec.x)*inv, (ca*x.y + cb*sec.y)*inv,
             (ca*x.z + cb*sec.z)*inv, (ca*x.w + cb*sec.w)*inv };
    float sqr = dotred(r, r);
    float nr  = sqrtf(fmaxf(sqr, EPS2));
    if (nr > MAXNC) {
        float s = MAXNC / nr;
        r.x *= s; r.y *= s; r.z *= s; r.w *= s;
        sqr *= s * s;
    }
    zout = r; sqout = sqr;
}

// ============================================================================
// Kernel 1a: tan-GEMV + expmap0 -> g_z.  One warp per row; 8 consecutive f per
// block so input loads are block-cooperative and coalesced.  x values are read
// 4-at-a-time via LDS.128; W rows held in registers across the 5-slot q loop.
// ============================================================================
#define SXP 484   // tile row pitch: 484 mod 32 = 4 -> conflict-free STS

__global__ void __launch_bounds__(256, 3)
gemv_kernel(const float* __restrict__ trend,  const float* __restrict__ scoarse,
            const float* __restrict__ sfine,  const float* __restrict__ resid,
            const float* __restrict__ W_t, const float* __restrict__ b_t,
            const float* __restrict__ W_c, const float* __restrict__ b_c,
            const float* __restrict__ W_f, const float* __restrict__ b_f,
            const float* __restrict__ W_r, const float* __restrict__ b_r)
{
    __shared__ float sX[8][SXP];   // per-warp-row: 4 streams x 120 timesteps

    const int tid  = threadIdx.x;
    const int wid  = tid >> 5;
    const int lane = tid & 31;

    const int row  = blockIdx.x * 8 + wid;
    const int b    = row >> 7;
    const int f0   = (blockIdx.x * 8) & 127;
    const size_t base_b = (size_t)b * LTOT * FEAT + f0;

    F4 bias;
    {
        float4 t1 = __ldg(reinterpret_cast<const float4*>(b_t) + lane);
        float4 t2 = __ldg(reinterpret_cast<const float4*>(b_c) + lane);
        float4 t3 = __ldg(reinterpret_cast<const float4*>(b_f) + lane);
        float4 t4 = __ldg(reinterpret_cast<const float4*>(b_r) + lane);
        bias.x = t1.x + t2.x + t3.x + t4.x;
        bias.y = t1.y + t2.y + t3.y + t4.y;
        bias.z = t1.z + t2.z + t3.z + t4.z;
        bias.w = t1.w + t2.w + t3.w + t4.w;
    }
    const unsigned long long bias01 = pack2(bias.x, bias.y);
    const unsigned long long bias23 = pack2(bias.z, bias.w);

    for (int p = 0; p < 3; ++p) {
        __syncthreads();
        const int l0 = 360 + p * 120;

        // block-cooperative coalesced load
#pragma unroll
        for (int st = 0; st < 4; ++st) {
            const float* src = (st == 0 ? trend : st == 1 ? scoarse :
                                st == 2 ? sfine : resid);
#pragma unroll
            for (int it = 0; it < 4; ++it) {
                int idx = tid + it * 256;
                if (idx < 960) {
                    int ff = idx & 7;
                    int i  = idx >> 3;
                    sX[ff][st * 120 + i] =
                        __ldg(&src[base_b + (size_t)(l0 + i) * FEAT + ff]);
                }
            }
        }
        __syncthreads();

        unsigned long long acc[5][2];
#pragma unroll
        for (int q = 0; q < 5; ++q) { acc[q][0] = bias01; acc[q][1] = bias23; }

#pragma unroll
        for (int st = 0; st < 4; ++st) {
            const float* W = (st == 0 ? W_t : st == 1 ? W_c : st == 2 ? W_f : W_r);
#pragma unroll
            for (int s4 = 0; s4 < 6; ++s4) {
                // hold 4 W rows (this lane's 4 dims each) in registers
                ulonglong2 w0 = __ldg(reinterpret_cast<const ulonglong2*>(W + (s4*4+0) * DDIM) + lane);
                ulonglong2 w1 = __ldg(reinterpret_cast<const ulonglong2*>(W + (s4*4+1) * DDIM) + lane);
                ulonglong2 w2 = __ldg(reinterpret_cast<const ulonglong2*>(W + (s4*4+2) * DDIM) + lane);
                ulonglong2 w3 = __ldg(reinterpret_cast<const ulonglong2*>(W + (s4*4+3) * DDIM) + lane);
#pragma unroll
                for (int q = 0; q < 5; ++q) {
                    float4 xv = *reinterpret_cast<const float4*>(
                        &sX[wid][st * 120 + q * SEGL + s4 * 4]);
                    unsigned long long xb;
                    xb = pack2(xv.x, xv.x);
                    fma2(acc[q][0], xb, w0.x); fma2(acc[q][1], xb, w0.y);
                    xb = pack2(xv.y, xv.y);
                    fma2(acc[q][0], xb, w1.x); fma2(acc[q][1], xb, w1.y);
                    xb = pack2(xv.z, xv.z);
                    fma2(acc[q][0], xb, w2.x); fma2(acc[q][1], xb, w2.y);
                    xb = pack2(xv.w, xv.w);
                    fma2(acc[q][0], xb, w3.x); fma2(acc[q][1], xb, w3.y);
                }
            }
        }

        // expmap0 per slot, write z to global
#pragma unroll
        for (int q = 0; q < 5; ++q) {
            F4 t;
            unpack2(acc[q][0], t.x, t.y);
            unpack2(acc[q][1], t.z, t.w);
            F4 z; float sqz;
            expmap0_f(t, z, sqz);
            const int slot = p * 5 + q;
            *reinterpret_cast<float4*>(
                &g_z[((size_t)slot * NROWS + row) * DDIM + lane * 4]) =
                make_float4(z.x, z.y, z.z, z.w);
        }
    }
}

// ============================================================================
// Kernel 1b: hyperbolic velocity chain + predictions -> g_t0.
// One warp per row; rolling 3-deep z window (low registers, high occupancy).
// ============================================================================
static __device__ __forceinline__ F4 ldz(int slot, int row, int lane) {
    float4 v = __ldg(reinterpret_cast<const float4*>(
        &g_z[((size_t)slot * NROWS + row) * DDIM + lane * 4]));
    F4 r = { v.x, v.y, v.z, v.w };
    return r;
}

__global__ void __launch_bounds__(256, 3)
chain_kernel(const float* __restrict__ alpha_p)
{
    const int tid  = threadIdx.x;
    const int wid  = tid >> 5;
    const int lane = tid & 31;
    const int row  = blockIdx.x * 8 + wid;

    // weights (replicates reference construction order)
    float s = 0.0f, wv = 1.0f;
#pragma unroll
    for (int j = 13; j >= 0; --j) { s += wv; if (j > 0) wv *= DECAYF; }
    const float w0  = wv / s;       // ws[0]/sum = 0.9^13 / sum
    const float w13 = 1.0f / s;
    const float invd = 1.0f / DECAYF;

    F4 za = ldz(0, row, lane);
    F4 zb = ldz(1, row, lane);
    F4 zc = ldz(2, row, lane);
    float sqa = dotred(za, za);
    float sqb = dotred(zb, zb);

    F4 avg = {0,0,0,0};
    F4 vel0, vel1, vel2;
    float wj = w0;

#pragma unroll
    for (int j = 0; j < 14; ++j) {
        F4 vel = logmap_f(za, sqa, zb, sqb);
        avg.x += wj * vel.x; avg.y += wj * vel.y;
        avg.z += wj * vel.z; avg.w += wj * vel.w;
        if (j == 0) vel0 = vel;
        else if (j == 1) vel1 = vel;
        else if (j == 2) vel2 = vel;
        wj *= invd;
        za = zb; sqa = sqb;
        zb = zc; sqb = dotred(zb, zb);
        if (j + 3 < WINN) zc = ldz(j + 3, row, lane);
    }

    const float alpha = __ldg(alpha_p);
    F4 zl = za; float sql = sqa;   // za == z[14]
#pragma unroll
    for (int k = 0; k < NPREDK; ++k) {
        F4 v = { avg.x * alpha, avg.y * alpha, avg.z * alpha, avg.w * alpha };
        F4 zn; float sqn;
        expmap_f(zl, sql, v, zn, sqn);

        float n  = sqrtf(fmaxf(sqn, EPS2));
        float sc = atanhf(fminf(n, CLIPC)) / n;
        *reinterpret_cast<float4*>(
            &g_t0[((size_t)k * NROWS + row) * DDIM + lane * 4]) =
            make_float4(zn.x * sc, zn.y * sc, zn.z * sc, zn.w * sc);

        if (k < 3) {
            F4 vn = logmap_f(zl, sql, zn, sqn);
            F4 vk = (k == 0 ? vel0 : (k == 1 ? vel1 : vel2));
            avg.x = (avg.x - w0 * vk.x) * DECAYF + w13 * vn.x;
            avg.y = (avg.y - w0 * vk.y) * DECAYF + w13 * vn.y;
            avg.z = (avg.z - w0 * vk.z) * DECAYF + w13 * vn.z;
            avg.w = (avg.w - w0 * vk.w) * DECAYF + w13 * vn.w;
        }
        zl = zn; sql = sqn;
    }
}

// ============================================================================
// Kernel 2a: transpose W2 -> g_W2t[j][c] (one-time tiny kernel)
// ============================================================================
__global__ void w2t_kernel(const float* __restrict__ W2) {
    int idx = blockIdx.x * 256 + threadIdx.x;
    if (idx < 24 * HDIM) {
        int j = idx >> 9;          // / 512
        int c = idx & (HDIM - 1);
        g_W2t[idx] = __ldg(&W2[(size_t)c * 24 + j]);
    }
}

// ============================================================================
// Kernel 2b: batched MLP  out = relu(t0 @ W1 + b1) @ W2 + b2 (transposed write).
// 256 threads, M-tile 32.  A tile is stored PRE-PACKED as duplicated f32x2
// pairs, so the GEMM1 hot loop is pure LDS.128 + LDG.128 + fma2 (no packs).
// N in 2 chunks of 256 (8 cols/thread).  smem 65.3KB -> 3 blocks/SM.
// ============================================================================
__global__ void __launch_bounds__(256, 3)
mlp_kernel(const float* __restrict__ W1, const float* __restrict__ b1,
           const float* __restrict__ b2, float* __restrict__ out)
{
    __shared__ unsigned long long As2[32 * 128];  // packed (a,a) pairs (32 KB)
    __shared__ float Hs[32 * 260];                // hidden chunk, pitch 260 (33.3 KB)

    const int tid = threadIdx.x;
    const int m0  = blockIdx.x * 32;

    // load A tile and store as duplicated pairs: As2[r*128 + k] = (a,a)
    {
        const float4* gsrc = reinterpret_cast<const float4*>(&g_t0[(size_t)m0 * DDIM]);
#pragma unroll
        for (int i = 0; i < 4; ++i) {
            int idx = tid + 256 * i;            // float4 index; r = idx/32, k = (idx%32)*4
            float4 v = __ldg(gsrc + idx);
            ulonglong2 p0; p0.x = pack2(v.x, v.x); p0.y = pack2(v.y, v.y);
            ulonglong2 p1; p1.x = pack2(v.z, v.z); p1.y = pack2(v.w, v.w);
            *reinterpret_cast<ulonglong2*>(&As2[idx * 4])     = p0;
            *reinterpret_cast<ulonglong2*>(&As2[idx * 4 + 2]) = p1;
        }
    }
    __syncthreads();

    const int rg = tid >> 5;     // warp id: 4-row group (gemm1) / 3-j group (gemm2)
    const int cg = tid & 31;     // lane: 8 cols (gemm1) / out row (gemm2)

    unsigned long long accp[3] = {0ull, 0ull, 0ull};

#pragma unroll
    for (int nc = 0; nc < 2; ++nc) {
        const int cbase = nc * 256;

        // ---- GEMM1: H[r][c] = relu(sum_k A[r][k] * W1[k][c] + b1[c]) ----
        unsigned long long hacc[4][4];
        {
            float4 bA = __ldg(reinterpret_cast<const float4*>(b1 + cbase) + cg);
            float4 bB = __ldg(reinterpret_cast<const float4*>(b1 + cbase + 128) + cg);
            unsigned long long h0 = pack2(bA.x, bA.y), h1 = pack2(bA.z, bA.w);
            unsigned long long h2 = pack2(bB.x, bB.y), h3 = pack2(bB.z, bB.w);
#pragma unroll
            for (int i = 0; i < 4; ++i) {
                hacc[i][0] = h0; hacc[i][1] = h1; hacc[i][2] = h2; hacc[i][3] = h3;
            }
        }
        const float* w1p = W1 + cbase + cg * 4;
#pragma unroll 4
        for (int k2 = 0; k2 < 64; ++k2) {
            const int k = k2 * 2;
            const float* wr0 = w1p + (size_t)k * HDIM;
            ulonglong2 wA0 = __ldg(reinterpret_cast<const ulonglong2*>(wr0));
            ulonglong2 wB0 = __ldg(reinterpret_cast<const ulonglong2*>(wr0 + 128));
            ulonglong2 wA1 = __ldg(reinterpret_cast<const ulonglong2*>(wr0 + HDIM));
            ulonglong2 wB1 = __ldg(reinterpret_cast<const ulonglong2*>(wr0 + HDIM + 128));
#pragma unroll
            for (int i = 0; i < 4; ++i) {
                ulonglong2 a2 = *reinterpret_cast<const ulonglong2*>(
                    &As2[(rg * 4 + i) * 128 + k]);
                fma2(hacc[i][0], a2.x, wA0.x);
                fma2(hacc[i][1], a2.x, wA0.y);
                fma2(hacc[i][2], a2.x, wB0.x);
                fma2(hacc[i][3], a2.x, wB0.y);
                fma2(hacc[i][0], a2.y, wA1.x);
                fma2(hacc[i][1], a2.y, wA1.y);
                fma2(hacc[i][2], a2.y, wB1.x);
                fma2(hacc[i][3], a2.y, wB1.y);
            }
        }
        __syncthreads();   // previous chunk's Hs readers done
        // relu + store hidden chunk (cols cg*4 and 128+cg*4)
#pragma unroll
        for (int i = 0; i < 4; ++i) {
            float h0, h1, h2, h3, h4, h5, h6, h7;
            unpack2(hacc[i][0], h0, h1);
            unpack2(hacc[i][1], h2, h3);
            unpack2(hacc[i][2], h4, h5);
            unpack2(hacc[i][3], h6, h7);
            int r = rg * 4 + i;
            *reinterpret_cast<float4*>(&Hs[r * 260 + cg * 4]) =
                make_float4(fmaxf(h0,0.f), fmaxf(h1,0.f), fmaxf(h2,0.f), fmaxf(h3,0.f));
            *reinterpret_cast<float4*>(&Hs[r * 260 + 128 + cg * 4]) =
                make_float4(fmaxf(h4,0.f), fmaxf(h5,0.f), fmaxf(h6,0.f), fmaxf(h7,0.f));
        }
        __syncthreads();

        // ---- GEMM2: out[r][j] += sum_c H[r][c] * W2t[j][c] ----
        const float* w2t = g_W2t + (size_t)(rg * 3) * HDIM + cbase;
#pragma unroll 4
        for (int c4 = 0; c4 < 64; ++c4) {
            const int c = c4 * 4;
            float4 h4 = *reinterpret_cast<const float4*>(&Hs[cg * 260 + c]);
            unsigned long long hA = pack2(h4.x, h4.y);
            unsigned long long hB = pack2(h4.z, h4.w);
#pragma unroll
            for (int jj = 0; jj < 3; ++jj) {
                ulonglong2 wvv = __ldg(reinterpret_cast<const ulonglong2*>(
                    w2t + (size_t)jj * HDIM + c));
                fma2(accp[jj], hA, wvv.x);
                fma2(accp[jj], hB, wvv.y);
            }
        }
    }

    // write transposed output: out[b, kidx*24 + j, f]
    const int kidx = m0 >> 14;
    const int bf0  = m0 & 16383;
    const int bb   = bf0 >> 7;
    const int f    = (bf0 & 127) + cg;   // 32-row tiles never cross a b boundary
#pragma unroll
    for (int jj = 0; jj < 3; ++jj) {
        int j = rg * 3 + jj;
        float s0, s1;
        unpack2(accp[jj], s0, s1);
        float val = __ldg(&b2[j]) + s0 + s1;
        out[((size_t)bb * 96 + kidx * 24 + j) * 128 + f] = val;
    }
}

// ============================================================================
extern "C" void kernel_launch(void* const* d_in, const int* in_sizes, int n_in,
                              void* d_out, int out_size) {
    const float* trend   = (const float*)d_in[0];
    const float* scoarse = (const float*)d_in[1];
    const float* sfine   = (const float*)d_in[2];
    const float* resid   = (const float*)d_in[3];
    const float* W_t = (const float*)d_in[4];
    const float* b_t = (const float*)d_in[5];
    const float* W_c = (const float*)d_in[6];
    const float* b_c = (const float*)d_in[7];
    const float* W_f = (const float*)d_in[8];
    const float* b_f = (const float*)d_in[9];
    const float* W_r = (const float*)d_in[10];
    const float* b_r = (const float*)d_in[11];
    const float* alpha = (const float*)d_in[12];
    const float* W1 = (const float*)d_in[13];
    const float* b1 = (const float*)d_in[14];
    const float* W2 = (const float*)d_in[15];
    const float* b2 = (const float*)d_in[16];

    gemv_kernel<<<NROWS / 8, 256>>>(trend, scoarse, sfine, resid,
                                    W_t, b_t, W_c, b_c, W_f, b_f, W_r, b_r);
    w2t_kernel<<<48, 256>>>(W2);
    chain_kernel<<<NROWS / 8, 256>>>(alpha);
    mlp_kernel<<<(NPREDK * NROWS) / 32, 256>>>(W1, b1, b2, (float*)d_out);
}

// round 6
// speedup vs baseline: 1.3836x; 1.3745x over previous
#include <cuda_runtime.h>
#include <cuda_bf16.h>
#include <cstdint>

// ---------------- problem constants ----------------
#define BATCH   128
#define LTOT    720
#define FEAT    128
#define SEGL    24
#define WINN    15
#define NPREDK  4
#define DDIM    128
#define HDIM    512
#define NROWS   (BATCH*FEAT)          // 16384
#define MTOT    (NPREDK*NROWS)        // 65536
#define EPSC    1e-6f
#define EPS2    1e-12f
#define MAXNC   0.99999f
#define CLIPC   0.99999988f
#define DECAYF  0.9f

// global scratch (static __device__, no allocs)
__device__ float g_z[(size_t)WINN * NROWS * DDIM];                  // window z
__device__ __align__(16) __nv_bfloat16 g_Ah[(size_t)MTOT * DDIM];   // A hi (bf16)
__device__ __align__(16) __nv_bfloat16 g_Al[(size_t)MTOT * DDIM];   // A lo (bf16)
// W1 images: [nc][n=128][k pitch 136] bf16  (chunk = 34816 B)
__device__ __align__(16) __nv_bfloat16 g_Bh[4 * 128 * 136];
__device__ __align__(16) __nv_bfloat16 g_Bl[4 * 128 * 136];
__device__ __align__(16) unsigned long long g_W2p[HDIM * 12];       // W2 packed j-pairs

// ---------------- f32x2 packed-FMA helpers ----------------
static __device__ __forceinline__ unsigned long long pack2(float x, float y) {
    unsigned long long r;
    asm("mov.b64 %0, {%1,%2};" : "=l"(r) : "f"(x), "f"(y));
    return r;
}
static __device__ __forceinline__ void unpack2(unsigned long long a, float &x, float &y) {
    asm("mov.b64 {%0,%1}, %2;" : "=f"(x), "=f"(y) : "l"(a));
}
static __device__ __forceinline__ void fma2(unsigned long long &a,
                                            unsigned long long b,
                                            unsigned long long c) {
    asm("fma.rn.f32x2 %0, %1, %2, %0;" : "+l"(a) : "l"(b), "l"(c));
}

// ---------------- mma.sync / ldmatrix helpers ----------------
static __device__ __forceinline__ uint32_t smem_to_u32(const void* p) {
    uint32_t a;
    asm("{ .reg .u64 t; cvta.to.shared.u64 t, %1; cvt.u32.u64 %0, t; }"
        : "=r"(a) : "l"(p));
    return a;
}
static __device__ __forceinline__ void ldsm4(uint32_t r[4], uint32_t addr) {
    asm volatile("ldmatrix.sync.aligned.m8n8.x4.shared.b16 {%0,%1,%2,%3}, [%4];"
                 : "=r"(r[0]), "=r"(r[1]), "=r"(r[2]), "=r"(r[3]) : "r"(addr));
}
static __device__ __forceinline__ void mma_bf16(float d[4], const uint32_t a[4],
                                                uint32_t b0, uint32_t b1) {
    asm volatile(
        "mma.sync.aligned.m16n8k16.row.col.f32.bf16.bf16.f32 "
        "{%0,%1,%2,%3}, {%4,%5,%6,%7}, {%8,%9}, {%0,%1,%2,%3};"
        : "+f"(d[0]), "+f"(d[1]), "+f"(d[2]), "+f"(d[3])
        : "r"(a[0]), "r"(a[1]), "r"(a[2]), "r"(a[3]), "r"(b0), "r"(b1));
}

// ---------------- warp math helpers ----------------
static __device__ __forceinline__ float wred(float v) {
#pragma unroll
    for (int o = 16; o > 0; o >>= 1) v += __shfl_xor_sync(0xffffffffu, v, o);
    return v;
}

struct F4 { float x, y, z, w; };

static __device__ __forceinline__ float dotred(const F4 &a, const F4 &b) {
    return wred(a.x*b.x + a.y*b.y + a.z*b.z + a.w*b.w);
}

static __device__ __forceinline__ F4 logmap_f(const F4 &x, float sqx,
                                              const F4 &y, float sqy) {
    float xy  = dotred(x, y);
    float txy = -2.0f * xy;
    float cx  = 1.0f + txy + sqy;
    float cy  = 1.0f - sqx;
    float den = fmaxf(1.0f + txy + sqx*sqy, EPSC);
    float inv = 1.0f / den;
    F4 d;
    d.x = (cy*y.x - cx*x.x) * inv;
    d.y = (cy*y.y - cx*x.y) * inv;
    d.z = (cy*y.z - cx*x.z) * inv;
    d.w = (cy*y.w - cx*x.w) * inv;
    float sqd = dotred(d, d);
    float nd  = sqrtf(fmaxf(sqd, EPS2));
    float s   = fmaxf(cy, EPSC) * atanhf(fminf(nd, CLIPC)) / nd;
    F4 r = { d.x*s, d.y*s, d.z*s, d.w*s };
    return r;
}

static __device__ __forceinline__ void expmap0_f(const F4 &t, F4 &z, float &sqz) {
    float sq = dotred(t, t);
    float n  = sqrtf(fmaxf(sq, EPS2));
    float sc = tanhf(n) / n;
    F4 r = { t.x*sc, t.y*sc, t.z*sc, t.w*sc };
    float sqr = dotred(r, r);
    float nr  = sqrtf(fmaxf(sqr, EPS2));
    if (nr > MAXNC) {
        float s = MAXNC / nr;
        r.x *= s; r.y *= s; r.z *= s; r.w *= s;
        sqr *= s * s;
    }
    z = r; sqz = sqr;
}

static __device__ __forceinline__ void expmap_f(const F4 &x, float sqx, const F4 &v,
                                                F4 &zout, float &sqout) {
    float m   = fmaxf(1.0f - sqx, EPSC);
    float sqv = dotred(v, v);
    float nv  = sqrtf(fmaxf(sqv, EPS2));
    float th  = tanhf(nv / m);
    float sc  = th / nv;
    F4 sec = { v.x*sc, v.y*sc, v.z*sc, v.w*sc };
    float xy = dotred(x, sec);
    float y2 = dotred(sec, sec);
    float ca  = 1.0f + 2.0f*xy + y2;
    float cb  = 1.0f - sqx;
    float den = fmaxf(1.0f + 2.0f*xy + sqx*y2, EPSC);
    float inv = 1.0f / den;
    F4 r = { (ca*x.x + cb*sec.x)*inv, (ca*x.y + cb*sec.y)*inv,
             (ca*x.z + cb*sec.z)*inv, (ca*x.w + cb*sec.w)*inv };
    float sqr = dotred(r, r);
    float nr  = sqrtf(fmaxf(sqr, EPS2));
    if (nr > MAXNC) {
        float s = MAXNC / nr;
        r.x *= s; r.y *= s; r.z *= s; r.w *= s;
        sqr *= s * s;
    }
    zout = r; sqout = sqr;
}

// ============================================================================
// Kernel 1a: tan-GEMV + expmap0 -> g_z  (best-known configuration)
// ============================================================================
#define SXP 484

__global__ void __launch_bounds__(256, 3)
gemv_kernel(const float* __restrict__ trend,  const float* __restrict__ scoarse,
            const float* __restrict__ sfine,  const float* __restrict__ resid,
            const float* __restrict__ W_t, const float* __restrict__ b_t,
            const float* __restrict__ W_c, const float* __restrict__ b_c,
            const float* __restrict__ W_f, const float* __restrict__ b_f,
            const float* __restrict__ W_r, const float* __restrict__ b_r)
{
    __shared__ float sX[8][SXP];

    const int tid  = threadIdx.x;
    const int wid  = tid >> 5;
    const int lane = tid & 31;

    const int row  = blockIdx.x * 8 + wid;
    const int b    = row >> 7;
    const int f0   = (blockIdx.x * 8) & 127;
    const size_t base_b = (size_t)b * LTOT * FEAT + f0;

    F4 bias;
    {
        float4 t1 = __ldg(reinterpret_cast<const float4*>(b_t) + lane);
        float4 t2 = __ldg(reinterpret_cast<const float4*>(b_c) + lane);
        float4 t3 = __ldg(reinterpret_cast<const float4*>(b_f) + lane);
        float4 t4 = __ldg(reinterpret_cast<const float4*>(b_r) + lane);
        bias.x = t1.x + t2.x + t3.x + t4.x;
        bias.y = t1.y + t2.y + t3.y + t4.y;
        bias.z = t1.z + t2.z + t3.z + t4.z;
        bias.w = t1.w + t2.w + t3.w + t4.w;
    }
    const unsigned long long bias01 = pack2(bias.x, bias.y);
    const unsigned long long bias23 = pack2(bias.z, bias.w);

    for (int p = 0; p < 3; ++p) {
        __syncthreads();
        const int l0 = 360 + p * 120;

#pragma unroll
        for (int st = 0; st < 4; ++st) {
            const float* src = (st == 0 ? trend : st == 1 ? scoarse :
                                st == 2 ? sfine : resid);
#pragma unroll
            for (int it = 0; it < 4; ++it) {
                int idx = tid + it * 256;
                if (idx < 960) {
                    int ff = idx & 7;
                    int i  = idx >> 3;
                    sX[ff][st * 120 + i] =
                        __ldg(&src[base_b + (size_t)(l0 + i) * FEAT + ff]);
                }
            }
        }
        __syncthreads();

        unsigned long long acc[5][2];
#pragma unroll
        for (int q = 0; q < 5; ++q) { acc[q][0] = bias01; acc[q][1] = bias23; }

#pragma unroll
        for (int st = 0; st < 4; ++st) {
            const float* W = (st == 0 ? W_t : st == 1 ? W_c : st == 2 ? W_f : W_r);
#pragma unroll
            for (int s4 = 0; s4 < 6; ++s4) {
                ulonglong2 w0 = __ldg(reinterpret_cast<const ulonglong2*>(W + (s4*4+0) * DDIM) + lane);
                ulonglong2 w1 = __ldg(reinterpret_cast<const ulonglong2*>(W + (s4*4+1) * DDIM) + lane);
                ulonglong2 w2 = __ldg(reinterpret_cast<const ulonglong2*>(W + (s4*4+2) * DDIM) + lane);
                ulonglong2 w3 = __ldg(reinterpret_cast<const ulonglong2*>(W + (s4*4+3) * DDIM) + lane);
#pragma unroll
                for (int q = 0; q < 5; ++q) {
                    float4 xv = *reinterpret_cast<const float4*>(
                        &sX[wid][st * 120 + q * SEGL + s4 * 4]);
                    unsigned long long xb;
                    xb = pack2(xv.x, xv.x);
                    fma2(acc[q][0], xb, w0.x); fma2(acc[q][1], xb, w0.y);
                    xb = pack2(xv.y, xv.y);
                    fma2(acc[q][0], xb, w1.x); fma2(acc[q][1], xb, w1.y);
                    xb = pack2(xv.z, xv.z);
                    fma2(acc[q][0], xb, w2.x); fma2(acc[q][1], xb, w2.y);
                    xb = pack2(xv.w, xv.w);
                    fma2(acc[q][0], xb, w3.x); fma2(acc[q][1], xb, w3.y);
                }
            }
        }

#pragma unroll
        for (int q = 0; q < 5; ++q) {
            F4 t;
            unpack2(acc[q][0], t.x, t.y);
            unpack2(acc[q][1], t.z, t.w);
            F4 z; float sqz;
            expmap0_f(t, z, sqz);
            const int slot = p * 5 + q;
            *reinterpret_cast<float4*>(
                &g_z[((size_t)slot * NROWS + row) * DDIM + lane * 4]) =
                make_float4(z.x, z.y, z.z, z.w);
        }
    }
}

// ============================================================================
// Kernel 1b: hyperbolic chain; emits bf16 hi/lo split of t0 into g_Ah/g_Al.
// ============================================================================
static __device__ __forceinline__ F4 ldz(int slot, int row, int lane) {
    float4 v = __ldg(reinterpret_cast<const float4*>(
        &g_z[((size_t)slot * NROWS + row) * DDIM + lane * 4]));
    F4 r = { v.x, v.y, v.z, v.w };
    return r;
}

static __device__ __forceinline__ void store_split(float v0, float v1, float v2, float v3,
                                                   __nv_bfloat16* hi, __nv_bfloat16* lo,
                                                   size_t off) {
    __nv_bfloat162 h01 = __floats2bfloat162_rn(v0, v1);
    __nv_bfloat162 h23 = __floats2bfloat162_rn(v2, v3);
    float r0 = v0 - __bfloat162float(__low2bfloat16(h01));
    float r1 = v1 - __bfloat162float(__high2bfloat16(h01));
    float r2 = v2 - __bfloat162float(__low2bfloat16(h23));
    float r3 = v3 - __bfloat162float(__high2bfloat16(h23));
    __nv_bfloat162 l01 = __floats2bfloat162_rn(r0, r1);
    __nv_bfloat162 l23 = __floats2bfloat162_rn(r2, r3);
    uint2 uh = make_uint2(*reinterpret_cast<uint32_t*>(&h01),
                          *reinterpret_cast<uint32_t*>(&h23));
    uint2 ul = make_uint2(*reinterpret_cast<uint32_t*>(&l01),
                          *reinterpret_cast<uint32_t*>(&l23));
    *reinterpret_cast<uint2*>(hi + off) = uh;
    *reinterpret_cast<uint2*>(lo + off) = ul;
}

__global__ void __launch_bounds__(256, 3)
chain_kernel(const float* __restrict__ alpha_p)
{
    const int tid  = threadIdx.x;
    const int wid  = tid >> 5;
    const int lane = tid & 31;
    const int row  = blockIdx.x * 8 + wid;

    float s = 0.0f, wv = 1.0f;
#pragma unroll
    for (int j = 13; j >= 0; --j) { s += wv; if (j > 0) wv *= DECAYF; }
    const float w0  = wv / s;
    const float w13 = 1.0f / s;
    const float invd = 1.0f / DECAYF;

    F4 za = ldz(0, row, lane);
    F4 zb = ldz(1, row, lane);
    F4 zc = ldz(2, row, lane);
    float sqa = dotred(za, za);
    float sqb = dotred(zb, zb);

    F4 avg = {0,0,0,0};
    F4 vel0, vel1, vel2;
    float wj = w0;

#pragma unroll
    for (int j = 0; j < 14; ++j) {
        F4 vel = logmap_f(za, sqa, zb, sqb);
        avg.x += wj * vel.x; avg.y += wj * vel.y;
        avg.z += wj * vel.z; avg.w += wj * vel.w;
        if (j == 0) vel0 = vel;
        else if (j == 1) vel1 = vel;
        else if (j == 2) vel2 = vel;
        wj *= invd;
        za = zb; sqa = sqb;
        zb = zc; sqb = dotred(zb, zb);
        if (j + 3 < WINN) zc = ldz(j + 3, row, lane);
    }

    const float alpha = __ldg(alpha_p);
    F4 zl = za; float sql = sqa;
#pragma unroll
    for (int k = 0; k < NPREDK; ++k) {
        F4 v = { avg.x * alpha, avg.y * alpha, avg.z * alpha, avg.w * alpha };
        F4 zn; float sqn;
        expmap_f(zl, sql, v, zn, sqn);

        float n  = sqrtf(fmaxf(sqn, EPS2));
        float sc = atanhf(fminf(n, CLIPC)) / n;
        const size_t m = (size_t)k * NROWS + row;
        store_split(zn.x * sc, zn.y * sc, zn.z * sc, zn.w * sc,
                    g_Ah, g_Al, m * DDIM + lane * 4);

        if (k < 3) {
            F4 vn = logmap_f(zl, sql, zn, sqn);
            F4 vk = (k == 0 ? vel0 : (k == 1 ? vel1 : vel2));
            avg.x = (avg.x - w0 * vk.x) * DECAYF + w13 * vn.x;
            avg.y = (avg.y - w0 * vk.y) * DECAYF + w13 * vn.y;
            avg.z = (avg.z - w0 * vk.z) * DECAYF + w13 * vn.z;
            avg.w = (avg.w - w0 * vk.w) * DECAYF + w13 * vn.w;
        }
        zl = zn; sql = sqn;
    }
}

// ============================================================================
// Prep kernels: W1 -> bf16 hi/lo images [nc][n][pitch 136]; W2 packed pairs.
// ============================================================================
__global__ void w1split_kernel(const float* __restrict__ W1) {
    int idx = blockIdx.x * 256 + threadIdx.x;   // 65536 total
    if (idx >= 4 * 16384) return;
    int nc = idx >> 14;
    int n  = (idx >> 7) & 127;
    int k  = idx & 127;
    float v = __ldg(&W1[(size_t)k * HDIM + nc * 128 + n]);
    __nv_bfloat16 hi = __float2bfloat16(v);
    __nv_bfloat16 lo = __float2bfloat16(v - __bfloat162float(hi));
    size_t off = (size_t)(nc * 128 + n) * 136 + k;
    g_Bh[off] = hi;
    g_Bl[off] = lo;
}

__global__ void w2p_kernel(const float* __restrict__ W2) {
    int idx = blockIdx.x * 256 + threadIdx.x;   // 6144 total
    if (idx >= HDIM * 12) return;
    int c  = idx / 12;
    int jp = idx - c * 12;
    float a = __ldg(&W2[(size_t)c * 24 + 2 * jp]);
    float b = __ldg(&W2[(size_t)c * 24 + 2 * jp + 1]);
    g_W2p[idx] = pack2(a, b);
}

// ============================================================================
// Kernel 2: MLP via mma.sync (bf16 split, 3 terms) + FFMA2 GEMM2.
// Block: 256 thr / 8 warps; M-tile 128; N chunked by 128.
// smem: Ah,Al,Bh,Bl (pitch 136 bf16) + Hs (fp32, pitch 132, chunk-swizzled)
//       + W2s (12KB, reused as reduction buffer).
// ============================================================================
#define SM_AH 0
#define SM_AL 34816
#define SM_BH 69632
#define SM_BL 104448
#define SM_HS 139264
#define SM_W2 206848
#define MLP_SMEM (206848 + 12288)     // 219136 B

__global__ void __launch_bounds__(256)
mlp_mma_kernel(const float* __restrict__ b1, const float* __restrict__ b2,
               float* __restrict__ out)
{
    extern __shared__ char smem[];
    const uint32_t sbase = smem_to_u32(smem);
    const int tid  = threadIdx.x;
    const int lane = tid & 31;
    const int wid  = tid >> 5;
    const int mg   = wid >> 1;          // 0..3 : rows mg*32
    const int ng   = wid & 1;           // 0..1 : cols ng*64
    const int m0   = blockIdx.x * 128;

    // ---- stage A hi/lo (dense global -> pitch-136 smem) ----
    {
        const uint4* gah = reinterpret_cast<const uint4*>(&g_Ah[(size_t)m0 * DDIM]);
        const uint4* gal = reinterpret_cast<const uint4*>(&g_Al[(size_t)m0 * DDIM]);
#pragma unroll
        for (int i = tid; i < 2048; i += 256) {
            int r = i >> 4, kc = i & 15;
            *reinterpret_cast<uint4*>(smem + SM_AH + r * 272 + kc * 16) = __ldg(gah + i);
            *reinterpret_cast<uint4*>(smem + SM_AL + r * 272 + kc * 16) = __ldg(gal + i);
        }
    }
    // ---- stage B chunk 0 (dense image copy) ----
    {
        const uint4* gbh = reinterpret_cast<const uint4*>(g_Bh);
        const uint4* gbl = reinterpret_cast<const uint4*>(g_Bl);
        for (int i = tid; i < 2176; i += 256) {
            *reinterpret_cast<uint4*>(smem + SM_BH + i * 16) = __ldg(gbh + i);
            *reinterpret_cast<uint4*>(smem + SM_BL + i * 16) = __ldg(gbl + i);
        }
    }

    // ---- ldmatrix base addresses ----
    uint32_t aoffh[2], aoffl[2], boffh[4], boffl[4];
    {
        int rA   = lane & 15;
        int colA = (lane >> 4) << 3;
#pragma unroll
        for (int mt = 0; mt < 2; ++mt) {
            uint32_t off = (uint32_t)((mg * 32 + mt * 16 + rA) * 136 + colA) * 2;
            aoffh[mt] = sbase + SM_AH + off;
            aoffl[mt] = sbase + SM_AL + off;
        }
        int nB = ((lane >> 4) << 3) + (lane & 7);
        int kB = ((lane >> 3) & 1) << 3;
#pragma unroll
        for (int g4 = 0; g4 < 4; ++g4) {
            uint32_t off = (uint32_t)((ng * 64 + g4 * 16 + nB) * 136 + kB) * 2;
            boffh[g4] = sbase + SM_BH + off;
            boffl[g4] = sbase + SM_BL + off;
        }
    }

    float* Hs = reinterpret_cast<float*>(smem + SM_HS);
    unsigned long long* W2s = reinterpret_cast<unsigned long long*>(smem + SM_W2);

    unsigned long long outp[12];
#pragma unroll
    for (int q = 0; q < 12; ++q) outp[q] = 0ull;

    for (int nc = 0; nc < 4; ++nc) {
        __syncthreads();    // B(nc) staged; Hs free (prev GEMM2 done)

        float acc[2][8][4];
#pragma unroll
        for (int mt = 0; mt < 2; ++mt)
#pragma unroll
            for (int nt = 0; nt < 8; ++nt)
#pragma unroll
                for (int q = 0; q < 4; ++q) acc[mt][nt][q] = 0.0f;

        // ---- GEMM1 mma loop ----
#pragma unroll
        for (int ks = 0; ks < 8; ++ks) {
            uint32_t ah[2][4], al[2][4];
            ldsm4(ah[0], aoffh[0] + ks * 32);
            ldsm4(ah[1], aoffh[1] + ks * 32);
            ldsm4(al[0], aoffl[0] + ks * 32);
            ldsm4(al[1], aoffl[1] + ks * 32);
#pragma unroll
            for (int g4 = 0; g4 < 4; ++g4) {
                uint32_t bh[4], bl[4];
                ldsm4(bh, boffh[g4] + ks * 32);
                ldsm4(bl, boffl[g4] + ks * 32);
#pragma unroll
                for (int mt = 0; mt < 2; ++mt) {
                    mma_bf16(acc[mt][2*g4],   ah[mt], bh[0], bh[1]);
                    mma_bf16(acc[mt][2*g4+1], ah[mt], bh[2], bh[3]);
                    mma_bf16(acc[mt][2*g4],   al[mt], bh[0], bh[1]);
                    mma_bf16(acc[mt][2*g4+1], al[mt], bh[2], bh[3]);
                    mma_bf16(acc[mt][2*g4],   ah[mt], bl[0], bl[1]);
                    mma_bf16(acc[mt][2*g4+1], ah[mt], bl[2], bl[3]);
                }
            }
        }
        __syncthreads();    // all warps done reading B(nc)

        // ---- epilogue: bias + relu -> Hs (chunk-swizzled) ----
#pragma unroll
        for (int nt = 0; nt < 8; ++nt) {
            int cB = ng * 64 + nt * 8 + 2 * (lane & 3);
            float2 b1v = __ldg(reinterpret_cast<const float2*>(&b1[nc * 128 + cB]));
#pragma unroll
            for (int mt = 0; mt < 2; ++mt) {
                int r0 = mg * 32 + mt * 16 + (lane >> 2);
                float h00 = fmaxf(acc[mt][nt][0] + b1v.x, 0.0f);
                float h01 = fmaxf(acc[mt][nt][1] + b1v.y, 0.0f);
                float h10 = fmaxf(acc[mt][nt][2] + b1v.x, 0.0f);
                float h11 = fmaxf(acc[mt][nt][3] + b1v.y, 0.0f);
                int c4 = cB >> 2, ci = cB & 3;
                int sw0 = (r0 >> 3) & 3;
                int sw1 = ((r0 + 8) >> 3) & 3;
                *reinterpret_cast<float2*>(
                    &Hs[r0 * 132 + ((c4 ^ sw0) << 2) + ci]) = make_float2(h00, h01);
                *reinterpret_cast<float2*>(
                    &Hs[(r0 + 8) * 132 + ((c4 ^ sw1) << 2) + ci]) = make_float2(h10, h11);
            }
        }

        // ---- stage W2s(nc) and next B chunk ----
        {
            const ulonglong2* gw = reinterpret_cast<const ulonglong2*>(g_W2p + nc * 1536);
            ulonglong2* dw = reinterpret_cast<ulonglong2*>(W2s);
#pragma unroll
            for (int i = tid; i < 768; i += 256) dw[i] = __ldg(gw + i);
        }
        if (nc < 3) {
            const uint4* gbh = reinterpret_cast<const uint4*>(
                reinterpret_cast<const char*>(g_Bh) + (size_t)(nc + 1) * 34816);
            const uint4* gbl = reinterpret_cast<const uint4*>(
                reinterpret_cast<const char*>(g_Bl) + (size_t)(nc + 1) * 34816);
            for (int i = tid; i < 2176; i += 256) {
                *reinterpret_cast<uint4*>(smem + SM_BH + i * 16) = __ldg(gbh + i);
                *reinterpret_cast<uint4*>(smem + SM_BL + i * 16) = __ldg(gbl + i);
            }
        }
        __syncthreads();    // Hs + W2s ready

        // ---- GEMM2 partial: out[r][j] += sum_c H[r][c] * W2[c][j] ----
        {
            const int row  = tid & 127;
            const int half = tid >> 7;
            const int sw   = (row >> 3) & 3;
            const int srow = row * 132;
#pragma unroll 4
            for (int c4 = 0; c4 < 16; ++c4) {
                int cc4 = half * 16 + c4;
                float4 h4 = *reinterpret_cast<const float4*>(
                    &Hs[srow + ((cc4 ^ sw) << 2)]);
#pragma unroll
                for (int cc = 0; cc < 4; ++cc) {
                    float h = (cc == 0 ? h4.x : cc == 1 ? h4.y : cc == 2 ? h4.z : h4.w);
                    unsigned long long hh = pack2(h, h);
                    const ulonglong2* wp = reinterpret_cast<const ulonglong2*>(
                        &W2s[(cc4 * 4 + cc) * 12]);
#pragma unroll
                    for (int q = 0; q < 6; ++q) {
                        ulonglong2 wv = wp[q];
                        fma2(outp[2 * q],     hh, wv.x);
                        fma2(outp[2 * q + 1], hh, wv.y);
                    }
                }
            }
        }
    }

    // ---- cross-half reduction + output write ----
    __syncthreads();
    float* Rs = reinterpret_cast<float*>(smem + SM_W2);   // reuse (12 KB)
    const int row  = tid & 127;
    const int half = tid >> 7;
    if (half == 1) {
#pragma unroll
        for (int p = 0; p < 12; ++p) {
            float s0, s1;
            unpack2(outp[p], s0, s1);
            Rs[row * 24 + 2 * p]     = s0;
            Rs[row * 24 + 2 * p + 1] = s1;
        }
    }
    __syncthreads();
    if (half == 0) {
        int m    = m0 + row;
        int kidx = m >> 14;
        int bf   = m & 16383;
        int bb   = bf >> 7;       // 128-row tile => bb fixed, f == row
        float* obase = out + ((size_t)bb * 96 + kidx * 24) * 128 + row;
#pragma unroll
        for (int p = 0; p < 12; ++p) {
            float s0, s1;
            unpack2(outp[p], s0, s1);
            obase[(2 * p) * 128] =
                s0 + Rs[row * 24 + 2 * p]     + __ldg(&b2[2 * p]);
            obase[(2 * p + 1) * 128] =
                s1 + Rs[row * 24 + 2 * p + 1] + __ldg(&b2[2 * p + 1]);
        }
    }
}

// ============================================================================
extern "C" void kernel_launch(void* const* d_in, const int* in_sizes, int n_in,
                              void* d_out, int out_size) {
    const float* trend   = (const float*)d_in[0];
    const float* scoarse = (const float*)d_in[1];
    const float* sfine   = (const float*)d_in[2];
    const float* resid   = (const float*)d_in[3];
    const float* W_t = (const float*)d_in[4];
    const float* b_t = (const float*)d_in[5];
    const float* W_c = (const float*)d_in[6];
    const float* b_c = (const float*)d_in[7];
    const float* W_f = (const float*)d_in[8];
    const float* b_f = (const float*)d_in[9];
    const float* W_r = (const float*)d_in[10];
    const float* b_r = (const float*)d_in[11];
    const float* alpha = (const float*)d_in[12];
    const float* W1 = (const float*)d_in[13];
    const float* b1 = (const float*)d_in[14];
    const float* W2 = (const float*)d_in[15];
    const float* b2 = (const float*)d_in[16];

    cudaFuncSetAttribute(mlp_mma_kernel,
                         cudaFuncAttributeMaxDynamicSharedMemorySize, MLP_SMEM);

    w1split_kernel<<<256, 256>>>(W1);
    w2p_kernel<<<24, 256>>>(W2);
    gemv_kernel<<<NROWS / 8, 256>>>(trend, scoarse, sfine, resid,
                                    W_t, b_t, W_c, b_c, W_f, b_f, W_r, b_r);
    chain_kernel<<<NROWS / 8, 256>>>(alpha);
    mlp_mma_kernel<<<MTOT / 128, 256, MLP_SMEM>>>(b1, b2, (float*)d_out);
}

// round 7
// speedup vs baseline: 1.5146x; 1.0946x over previous
#include <cuda_runtime.h>
#include <cuda_bf16.h>
#include <cstdint>

// ---------------- problem constants ----------------
#define BATCH   128
#define LTOT    720
#define FEAT    128
#define SEGL    24
#define WINN    15
#define NPREDK  4
#define DDIM    128
#define HDIM    512
#define NROWS   (BATCH*FEAT)          // 16384
#define MTOT    (NPREDK*NROWS)        // 65536
#define EPSC    1e-6f
#define EPS2    1e-12f
#define MAXNC   0.99999f
#define CLIPC   0.99999988f
#define DECAYF  0.9f

// global scratch (static __device__, no allocs)
__device__ float g_z[(size_t)WINN * NROWS * DDIM];                  // window z
__device__ __align__(16) __nv_bfloat16 g_Ah[(size_t)MTOT * DDIM];   // MLP A hi
__device__ __align__(16) __nv_bfloat16 g_Al[(size_t)MTOT * DDIM];   // MLP A lo
// W1 images: [nc][n=128][k pitch 136] bf16  (chunk = 34816 B)
__device__ __align__(16) __nv_bfloat16 g_Bh[4 * 128 * 136];
__device__ __align__(16) __nv_bfloat16 g_Bl[4 * 128 * 136];
// combined tan weights Wc images: [d=128][k pitch 104] bf16
__device__ __align__(16) __nv_bfloat16 g_Gh[128 * 104];
__device__ __align__(16) __nv_bfloat16 g_Gl[128 * 104];
__device__ __align__(16) unsigned long long g_W2p[HDIM * 12];       // W2 packed j-pairs

// ---------------- f32x2 packed-FMA helpers ----------------
static __device__ __forceinline__ unsigned long long pack2(float x, float y) {
    unsigned long long r;
    asm("mov.b64 %0, {%1,%2};" : "=l"(r) : "f"(x), "f"(y));
    return r;
}
static __device__ __forceinline__ void unpack2(unsigned long long a, float &x, float &y) {
    asm("mov.b64 {%0,%1}, %2;" : "=f"(x), "=f"(y) : "l"(a));
}
static __device__ __forceinline__ void fma2(unsigned long long &a,
                                            unsigned long long b,
                                            unsigned long long c) {
    asm("fma.rn.f32x2 %0, %1, %2, %0;" : "+l"(a) : "l"(b), "l"(c));
}

// ---------------- mma.sync / ldmatrix helpers ----------------
static __device__ __forceinline__ uint32_t smem_to_u32(const void* p) {
    uint32_t a;
    asm("{ .reg .u64 t; cvta.to.shared.u64 t, %1; cvt.u32.u64 %0, t; }"
        : "=r"(a) : "l"(p));
    return a;
}
static __device__ __forceinline__ void ldsm4(uint32_t r[4], uint32_t addr) {
    asm volatile("ldmatrix.sync.aligned.m8n8.x4.shared.b16 {%0,%1,%2,%3}, [%4];"
                 : "=r"(r[0]), "=r"(r[1]), "=r"(r[2]), "=r"(r[3]) : "r"(addr));
}
static __device__ __forceinline__ void ldsm4t(uint32_t r[4], uint32_t addr) {
    asm volatile("ldmatrix.sync.aligned.m8n8.x4.trans.shared.b16 {%0,%1,%2,%3}, [%4];"
                 : "=r"(r[0]), "=r"(r[1]), "=r"(r[2]), "=r"(r[3]) : "r"(addr));
}
static __device__ __forceinline__ void mma_bf16(float d[4], const uint32_t a[4],
                                                uint32_t b0, uint32_t b1) {
    asm volatile(
        "mma.sync.aligned.m16n8k16.row.col.f32.bf16.bf16.f32 "
        "{%0,%1,%2,%3}, {%4,%5,%6,%7}, {%8,%9}, {%0,%1,%2,%3};"
        : "+f"(d[0]), "+f"(d[1]), "+f"(d[2]), "+f"(d[3])
        : "r"(a[0]), "r"(a[1]), "r"(a[2]), "r"(a[3]), "r"(b0), "r"(b1));
}

// ---------------- warp math helpers ----------------
static __device__ __forceinline__ float wred(float v) {
#pragma unroll
    for (int o = 16; o > 0; o >>= 1) v += __shfl_xor_sync(0xffffffffu, v, o);
    return v;
}

struct F4 { float x, y, z, w; };

static __device__ __forceinline__ float dotred(const F4 &a, const F4 &b) {
    return wred(a.x*b.x + a.y*b.y + a.z*b.z + a.w*b.w);
}

static __device__ __forceinline__ F4 logmap_f(const F4 &x, float sqx,
                                              const F4 &y, float sqy) {
    float xy  = dotred(x, y);
    float txy = -2.0f * xy;
    float cx  = 1.0f + txy + sqy;
    float cy  = 1.0f - sqx;
    float den = fmaxf(1.0f + txy + sqx*sqy, EPSC);
    float inv = 1.0f / den;
    F4 d;
    d.x = (cy*y.x - cx*x.x) * inv;
    d.y = (cy*y.y - cx*x.y) * inv;
    d.z = (cy*y.z - cx*x.z) * inv;
    d.w = (cy*y.w - cx*x.w) * inv;
    float sqd = dotred(d, d);
    float nd  = sqrtf(fmaxf(sqd, EPS2));
    float s   = fmaxf(cy, EPSC) * atanhf(fminf(nd, CLIPC)) / nd;
    F4 r = { d.x*s, d.y*s, d.z*s, d.w*s };
    return r;
}

static __device__ __forceinline__ void expmap_f(const F4 &x, float sqx, const F4 &v,
                                                F4 &zout, float &sqout) {
    float m   = fmaxf(1.0f - sqx, EPSC);
    float sqv = dotred(v, v);
    float nv  = sqrtf(fmaxf(sqv, EPS2));
    float th  = tanhf(nv / m);
    float sc  = th / nv;
    F4 sec = { v.x*sc, v.y*sc, v.z*sc, v.w*sc };
    float xy = dotred(x, sec);
    float y2 = dotred(sec, sec);
    float ca  = 1.0f + 2.0f*xy + y2;
    float cb  = 1.0f - sqx;
    float den = fmaxf(1.0f + 2.0f*xy + sqx*y2, EPSC);
    float inv = 1.0f / den;
    F4 r = { (ca*x.x + cb*sec.x)*inv, (ca*x.y + cb*sec.y)*inv,
             (ca*x.z + cb*sec.z)*inv, (ca*x.w + cb*sec.w)*inv };
    float sqr = dotred(r, r);
    float nr  = sqrtf(fmaxf(sqr, EPS2));
    if (nr > MAXNC) {
        float s = MAXNC / nr;
        r.x *= s; r.y *= s; r.z *= s; r.w *= s;
        sqr *= s * s;
    }
    zout = r; sqout = sqr;
}

// ============================================================================
// Prep: combined tan weights -> bf16 hi/lo images [d=128][k pitch 104]
// k = st*24 + s ;  Wc[k][d] = W_st[s][d]
// ============================================================================
__global__ void wcomb_kernel(const float* __restrict__ W_t, const float* __restrict__ W_c,
                             const float* __restrict__ W_f, const float* __restrict__ W_r)
{
    int idx = blockIdx.x * 256 + threadIdx.x;   // 12288 total
    if (idx >= 128 * 96) return;
    int d = idx / 96;
    int k = idx - d * 96;
    int st = k / 24, s = k - st * 24;
    const float* W = (st == 0 ? W_t : st == 1 ? W_c : st == 2 ? W_f : W_r);
    float v = __ldg(&W[s * DDIM + d]);
    __nv_bfloat16 hi = __float2bfloat16(v);
    __nv_bfloat16 lo = __float2bfloat16(v - __bfloat162float(hi));
    g_Gh[d * 104 + k] = hi;
    g_Gl[d * 104 + k] = lo;
}

// ============================================================================
// Kernel 1a (NEW): tan GEMM on tensor cores + fused expmap0 -> g_z.
// Block = 256 thr / 8 warps.  Tile: 128 rows (= all f of one b) x 128 d,
// K = 96.  Each block loops 3 slots, reusing the staged Wc images.
// ============================================================================
#define SM2_AH   0
#define SM2_AL   26112
#define SM2_BH   52224
#define SM2_BL   78848
#define SM2_D    105472
#define SM2_P    173056
#define SM2_BIAS 174080
#define GEMV_SMEM (174080 + 512)

__global__ void __launch_bounds__(256)
gemv_mma_kernel(const float* __restrict__ trend,  const float* __restrict__ scoarse,
                const float* __restrict__ sfine,  const float* __restrict__ resid,
                const float* __restrict__ b_t, const float* __restrict__ b_c,
                const float* __restrict__ b_f, const float* __restrict__ b_r)
{
    extern __shared__ char smem[];
    const uint32_t sbase = smem_to_u32(smem);
    const int tid  = threadIdx.x;
    const int lane = tid & 31;
    const int wid  = tid >> 5;
    const int mg   = wid >> 1;          // rows mg*32
    const int ng   = wid & 1;           // cols ng*64
    const int b    = blockIdx.x & 127;
    const int sg   = blockIdx.x >> 7;   // slot group 0..4

    float* sD    = reinterpret_cast<float*>(smem + SM2_D);     // [128][132]
    float* sPart = reinterpret_cast<float*>(smem + SM2_P);     // [128][2]
    float* sBias = reinterpret_cast<float*>(smem + SM2_BIAS);  // [128]

    // stage Wc images + combined bias
    {
        const uint4* gh = reinterpret_cast<const uint4*>(g_Gh);
        const uint4* gl = reinterpret_cast<const uint4*>(g_Gl);
        for (int i = tid; i < 1664; i += 256) {
            *reinterpret_cast<uint4*>(smem + SM2_BH + i * 16) = __ldg(gh + i);
            *reinterpret_cast<uint4*>(smem + SM2_BL + i * 16) = __ldg(gl + i);
        }
        if (tid < 128)
            sBias[tid] = __ldg(&b_t[tid]) + __ldg(&b_c[tid]) +
                         __ldg(&b_f[tid]) + __ldg(&b_r[tid]);
    }

    // ldmatrix addresses
    uint32_t aoffh[2], aoffl[2], boffh[4], boffl[4];
    {
        // A^T [k][f] pitch 136; trans-frag: lanes give rows k, col m0 or m8
        int kRow = (lane & 7) + ((lane >> 4) << 3);
        int mC8  = ((lane >> 3) & 1) << 3;
#pragma unroll
        for (int mt = 0; mt < 2; ++mt) {
            uint32_t off = (uint32_t)(kRow * 136 + mg * 32 + mt * 16 + mC8) * 2;
            aoffh[mt] = sbase + SM2_AH + off;
            aoffl[mt] = sbase + SM2_AL + off;
        }
        // B [d][k] pitch 104; plain frag (verified pattern)
        int nB = ((lane >> 4) << 3) + (lane & 7);
        int kB = ((lane >> 3) & 1) << 3;
#pragma unroll
        for (int g4 = 0; g4 < 4; ++g4) {
            uint32_t off = (uint32_t)((ng * 64 + g4 * 16 + nB) * 104 + kB) * 2;
            boffh[g4] = sbase + SM2_BH + off;
            boffl[g4] = sbase + SM2_BL + off;
        }
    }

    const size_t base_b = (size_t)b * LTOT * FEAT;

    for (int it = 0; it < 3; ++it) {
        const int slot = sg * 3 + it;
        __syncthreads();   // B staged (it=0) / previous sD copy done

        // ---- stage A^T hi/lo: row k = st*24+s is x_st[b][360+slot*24+s][:] ----
        for (int i = tid; i < 3072; i += 256) {
            int k  = i >> 5;
            int c4 = i & 31;
            int st = k / 24, s = k - st * 24;
            const float* src = (st == 0 ? trend : st == 1 ? scoarse :
                                st == 2 ? sfine : resid);
            float4 v = __ldg(reinterpret_cast<const float4*>(
                &src[base_b + (size_t)(360 + slot * 24 + s) * FEAT]) + c4);
            __nv_bfloat162 h01 = __floats2bfloat162_rn(v.x, v.y);
            __nv_bfloat162 h23 = __floats2bfloat162_rn(v.z, v.w);
            float r0 = v.x - __bfloat162float(__low2bfloat16(h01));
            float r1 = v.y - __bfloat162float(__high2bfloat16(h01));
            float r2 = v.z - __bfloat162float(__low2bfloat16(h23));
            float r3 = v.w - __bfloat162float(__high2bfloat16(h23));
            __nv_bfloat162 l01 = __floats2bfloat162_rn(r0, r1);
            __nv_bfloat162 l23 = __floats2bfloat162_rn(r2, r3);
            uint32_t off = (uint32_t)(k * 136 + c4 * 4) * 2;
            *reinterpret_cast<uint2*>(smem + SM2_AH + off) =
                make_uint2(*reinterpret_cast<uint32_t*>(&h01),
                           *reinterpret_cast<uint32_t*>(&h23));
            *reinterpret_cast<uint2*>(smem + SM2_AL + off) =
                make_uint2(*reinterpret_cast<uint32_t*>(&l01),
                           *reinterpret_cast<uint32_t*>(&l23));
        }
        __syncthreads();

        // ---- GEMM: 6 k-steps, 3-term bf16 split ----
        float acc[2][8][4];
#pragma unroll
        for (int mt = 0; mt < 2; ++mt)
#pragma unroll
            for (int nt = 0; nt < 8; ++nt)
#pragma unroll
                for (int q = 0; q < 4; ++q) acc[mt][nt][q] = 0.0f;

#pragma unroll
        for (int ks = 0; ks < 6; ++ks) {
            uint32_t ah[2][4], al[2][4];
            ldsm4t(ah[0], aoffh[0] + ks * 16 * 272);
            ldsm4t(ah[1], aoffh[1] + ks * 16 * 272);
            ldsm4t(al[0], aoffl[0] + ks * 16 * 272);
            ldsm4t(al[1], aoffl[1] + ks * 16 * 272);
#pragma unroll
            for (int g4 = 0; g4 < 4; ++g4) {
                uint32_t bh[4], bl[4];
                ldsm4(bh, boffh[g4] + ks * 32);
                ldsm4(bl, boffl[g4] + ks * 32);
#pragma unroll
                for (int mt = 0; mt < 2; ++mt) {
                    mma_bf16(acc[mt][2*g4],   ah[mt], bh[0], bh[1]);
                    mma_bf16(acc[mt][2*g4+1], ah[mt], bh[2], bh[3]);
                    mma_bf16(acc[mt][2*g4],   al[mt], bh[0], bh[1]);
                    mma_bf16(acc[mt][2*g4+1], al[mt], bh[2], bh[3]);
                    mma_bf16(acc[mt][2*g4],   ah[mt], bl[0], bl[1]);
                    mma_bf16(acc[mt][2*g4+1], ah[mt], bl[2], bl[3]);
                }
            }
        }

        // ---- + bias; row sum-of-squares partials ----
        float p[2][2];
#pragma unroll
        for (int mt = 0; mt < 2; ++mt) { p[mt][0] = 0.0f; p[mt][1] = 0.0f; }
#pragma unroll
        for (int nt = 0; nt < 8; ++nt) {
            int c = ng * 64 + nt * 8 + 2 * (lane & 3);
            float bx = sBias[c], by = sBias[c + 1];
#pragma unroll
            for (int mt = 0; mt < 2; ++mt) {
                acc[mt][nt][0] += bx; acc[mt][nt][1] += by;
                acc[mt][nt][2] += bx; acc[mt][nt][3] += by;
                p[mt][0] += acc[mt][nt][0]*acc[mt][nt][0] + acc[mt][nt][1]*acc[mt][nt][1];
                p[mt][1] += acc[mt][nt][2]*acc[mt][nt][2] + acc[mt][nt][3]*acc[mt][nt][3];
            }
        }
#pragma unroll
        for (int mt = 0; mt < 2; ++mt) {
#pragma unroll
            for (int h = 0; h < 2; ++h) {
                p[mt][h] += __shfl_xor_sync(0xffffffffu, p[mt][h], 1);
                p[mt][h] += __shfl_xor_sync(0xffffffffu, p[mt][h], 2);
            }
            if ((lane & 3) == 0) {
                int r0 = mg * 32 + mt * 16 + (lane >> 2);
                sPart[r0 * 2 + ng]       = p[mt][0];
                sPart[(r0 + 8) * 2 + ng] = p[mt][1];
            }
        }
        __syncthreads();   // partials ready; mma reads of A done

        // ---- scale (expmap0) and write to sD ----
#pragma unroll
        for (int mt = 0; mt < 2; ++mt) {
            int r0 = mg * 32 + mt * 16 + (lane >> 2);
            float sq0 = sPart[r0 * 2] + sPart[r0 * 2 + 1];
            float sq1 = sPart[(r0 + 8) * 2] + sPart[(r0 + 8) * 2 + 1];
            float n0 = sqrtf(fmaxf(sq0, EPS2));
            float n1 = sqrtf(fmaxf(sq1, EPS2));
            float t0 = tanhf(n0), t1 = tanhf(n1);
            float sc0 = (t0 > MAXNC ? MAXNC : t0) / n0;
            float sc1 = (t1 > MAXNC ? MAXNC : t1) / n1;
#pragma unroll
            for (int nt = 0; nt < 8; ++nt) {
                int c = ng * 64 + nt * 8 + 2 * (lane & 3);
                *reinterpret_cast<float2*>(&sD[r0 * 132 + c]) =
                    make_float2(acc[mt][nt][0] * sc0, acc[mt][nt][1] * sc0);
                *reinterpret_cast<float2*>(&sD[(r0 + 8) * 132 + c]) =
                    make_float2(acc[mt][nt][2] * sc1, acc[mt][nt][3] * sc1);
            }
        }
        __syncthreads();

        // ---- coalesced copy sD -> g_z[slot][b*128 + r][d] ----
        float* gz = &g_z[((size_t)slot * NROWS + (size_t)b * 128) * DDIM];
#pragma unroll
        for (int i = tid; i < 4096; i += 256) {
            int r = i >> 5, c4 = i & 31;
            float4 v = *reinterpret_cast<const float4*>(&sD[r * 132 + c4 * 4]);
            *reinterpret_cast<float4*>(&gz[r * 128 + c4 * 4]) = v;
        }
    }
}

// ============================================================================
// Kernel 1b: hyperbolic chain; emits bf16 hi/lo split of t0 into g_Ah/g_Al.
// ============================================================================
static __device__ __forceinline__ F4 ldz(int slot, int row, int lane) {
    float4 v = __ldg(reinterpret_cast<const float4*>(
        &g_z[((size_t)slot * NROWS + row) * DDIM + lane * 4]));
    F4 r = { v.x, v.y, v.z, v.w };
    return r;
}

static __device__ __forceinline__ void store_split(float v0, float v1, float v2, float v3,
                                                   __nv_bfloat16* hi, __nv_bfloat16* lo,
                                                   size_t off) {
    __nv_bfloat162 h01 = __floats2bfloat162_rn(v0, v1);
    __nv_bfloat162 h23 = __floats2bfloat162_rn(v2, v3);
    float r0 = v0 - __bfloat162float(__low2bfloat16(h01));
    float r1 = v1 - __bfloat162float(__high2bfloat16(h01));
    float r2 = v2 - __bfloat162float(__low2bfloat16(h23));
    float r3 = v3 - __bfloat162float(__high2bfloat16(h23));
    __nv_bfloat162 l01 = __floats2bfloat162_rn(r0, r1);
    __nv_bfloat162 l23 = __floats2bfloat162_rn(r2, r3);
    uint2 uh = make_uint2(*reinterpret_cast<uint32_t*>(&h01),
                          *reinterpret_cast<uint32_t*>(&h23));
    uint2 ul = make_uint2(*reinterpret_cast<uint32_t*>(&l01),
                          *reinterpret_cast<uint32_t*>(&l23));
    *reinterpret_cast<uint2*>(hi + off) = uh;
    *reinterpret_cast<uint2*>(lo + off) = ul;
}

__global__ void __launch_bounds__(256, 3)
chain_kernel(const float* __restrict__ alpha_p)
{
    const int tid  = threadIdx.x;
    const int wid  = tid >> 5;
    const int lane = tid & 31;
    const int row  = blockIdx.x * 8 + wid;

    float s = 0.0f, wv = 1.0f;
#pragma unroll
    for (int j = 13; j >= 0; --j) { s += wv; if (j > 0) wv *= DECAYF; }
    const float w0  = wv / s;
    const float w13 = 1.0f / s;
    const float invd = 1.0f / DECAYF;

    F4 za = ldz(0, row, lane);
    F4 zb = ldz(1, row, lane);
    F4 zc = ldz(2, row, lane);
    float sqa = dotred(za, za);
    float sqb = dotred(zb, zb);

    F4 avg = {0,0,0,0};
    F4 vel0, vel1, vel2;
    float wj = w0;

#pragma unroll
    for (int j = 0; j < 14; ++j) {
        F4 vel = logmap_f(za, sqa, zb, sqb);
        avg.x += wj * vel.x; avg.y += wj * vel.y;
        avg.z += wj * vel.z; avg.w += wj * vel.w;
        if (j == 0) vel0 = vel;
        else if (j == 1) vel1 = vel;
        else if (j == 2) vel2 = vel;
        wj *= invd;
        za = zb; sqa = sqb;
        zb = zc; sqb = dotred(zb, zb);
        if (j + 3 < WINN) zc = ldz(j + 3, row, lane);
    }

    const float alpha = __ldg(alpha_p);
    F4 zl = za; float sql = sqa;
#pragma unroll
    for (int k = 0; k < NPREDK; ++k) {
        F4 v = { avg.x * alpha, avg.y * alpha, avg.z * alpha, avg.w * alpha };
        F4 zn; float sqn;
        expmap_f(zl, sql, v, zn, sqn);

        float n  = sqrtf(fmaxf(sqn, EPS2));
        float sc = atanhf(fminf(n, CLIPC)) / n;
        const size_t m = (size_t)k * NROWS + row;
        store_split(zn.x * sc, zn.y * sc, zn.z * sc, zn.w * sc,
                    g_Ah, g_Al, m * DDIM + lane * 4);

        if (k < 3) {
            F4 vn = logmap_f(zl, sql, zn, sqn);
            F4 vk = (k == 0 ? vel0 : (k == 1 ? vel1 : vel2));
            avg.x = (avg.x - w0 * vk.x) * DECAYF + w13 * vn.x;
            avg.y = (avg.y - w0 * vk.y) * DECAYF + w13 * vn.y;
            avg.z = (avg.z - w0 * vk.z) * DECAYF + w13 * vn.z;
            avg.w = (avg.w - w0 * vk.w) * DECAYF + w13 * vn.w;
        }
        zl = zn; sql = sqn;
    }
}

// ============================================================================
// Prep kernels: W1 -> bf16 hi/lo images [nc][n][pitch 136]; W2 packed pairs.
// ============================================================================
__global__ void w1split_kernel(const float* __restrict__ W1) {
    int idx = blockIdx.x * 256 + threadIdx.x;   // 65536 total
    if (idx >= 4 * 16384) return;
    int nc = idx >> 14;
    int n  = (idx >> 7) & 127;
    int k  = idx & 127;
    float v = __ldg(&W1[(size_t)k * HDIM + nc * 128 + n]);
    __nv_bfloat16 hi = __float2bfloat16(v);
    __nv_bfloat16 lo = __float2bfloat16(v - __bfloat162float(hi));
    size_t off = (size_t)(nc * 128 + n) * 136 + k;
    g_Bh[off] = hi;
    g_Bl[off] = lo;
}

__global__ void w2p_kernel(const float* __restrict__ W2) {
    int idx = blockIdx.x * 256 + threadIdx.x;   // 6144 total
    if (idx >= HDIM * 12) return;
    int c  = idx / 12;
    int jp = idx - c * 12;
    float a = __ldg(&W2[(size_t)c * 24 + 2 * jp]);
    float b = __ldg(&W2[(size_t)c * 24 + 2 * jp + 1]);
    g_W2p[idx] = pack2(a, b);
}

// ============================================================================
// Kernel 2: MLP via mma.sync (bf16 split, 3 terms) + FFMA2 GEMM2.
// ============================================================================
#define SM_AH 0
#define SM_AL 34816
#define SM_BH 69632
#define SM_BL 104448
#define SM_HS 139264
#define SM_W2 206848
#define MLP_SMEM (206848 + 12288)     // 219136 B

__global__ void __launch_bounds__(256)
mlp_mma_kernel(const float* __restrict__ b1, const float* __restrict__ b2,
               float* __restrict__ out)
{
    extern __shared__ char smem[];
    const uint32_t sbase = smem_to_u32(smem);
    const int tid  = threadIdx.x;
    const int lane = tid & 31;
    const int wid  = tid >> 5;
    const int mg   = wid >> 1;
    const int ng   = wid & 1;
    const int m0   = blockIdx.x * 128;

    {
        const uint4* gah = reinterpret_cast<const uint4*>(&g_Ah[(size_t)m0 * DDIM]);
        const uint4* gal = reinterpret_cast<const uint4*>(&g_Al[(size_t)m0 * DDIM]);
#pragma unroll
        for (int i = tid; i < 2048; i += 256) {
            int r = i >> 4, kc = i & 15;
            *reinterpret_cast<uint4*>(smem + SM_AH + r * 272 + kc * 16) = __ldg(gah + i);
            *reinterpret_cast<uint4*>(smem + SM_AL + r * 272 + kc * 16) = __ldg(gal + i);
        }
    }
    {
        const uint4* gbh = reinterpret_cast<const uint4*>(g_Bh);
        const uint4* gbl = reinterpret_cast<const uint4*>(g_Bl);
        for (int i = tid; i < 2176; i += 256) {
            *reinterpret_cast<uint4*>(smem + SM_BH + i * 16) = __ldg(gbh + i);
            *reinterpret_cast<uint4*>(smem + SM_BL + i * 16) = __ldg(gbl + i);
        }
    }

    uint32_t aoffh[2], aoffl[2], boffh[4], boffl[4];
    {
        int rA   = lane & 15;
        int colA = (lane >> 4) << 3;
#pragma unroll
        for (int mt = 0; mt < 2; ++mt) {
            uint32_t off = (uint32_t)((mg * 32 + mt * 16 + rA) * 136 + colA) * 2;
            aoffh[mt] = sbase + SM_AH + off;
            aoffl[mt] = sbase + SM_AL + off;
        }
        int nB = ((lane >> 4) << 3) + (lane & 7);
        int kB = ((lane >> 3) & 1) << 3;
#pragma unroll
        for (int g4 = 0; g4 < 4; ++g4) {
            uint32_t off = (uint32_t)((ng * 64 + g4 * 16 + nB) * 136 + kB) * 2;
            boffh[g4] = sbase + SM_BH + off;
            boffl[g4] = sbase + SM_BL + off;
        }
    }

    float* Hs = reinterpret_cast<float*>(smem + SM_HS);
    unsigned long long* W2s = reinterpret_cast<unsigned long long*>(smem + SM_W2);

    unsigned long long outp[12];
#pragma unroll
    for (int q = 0; q < 12; ++q) outp[q] = 0ull;

    for (int nc = 0; nc < 4; ++nc) {
        __syncthreads();

        float acc[2][8][4];
#pragma unroll
        for (int mt = 0; mt < 2; ++mt)
#pragma unroll
            for (int nt = 0; nt < 8; ++nt)
#pragma unroll
                for (int q = 0; q < 4; ++q) acc[mt][nt][q] = 0.0f;

#pragma unroll
        for (int ks = 0; ks < 8; ++ks) {
            uint32_t ah[2][4], al[2][4];
            ldsm4(ah[0], aoffh[0] + ks * 32);
            ldsm4(ah[1], aoffh[1] + ks * 32);
            ldsm4(al[0], aoffl[0] + ks * 32);
            ldsm4(al[1], aoffl[1] + ks * 32);
#pragma unroll
            for (int g4 = 0; g4 < 4; ++g4) {
                uint32_t bh[4], bl[4];
                ldsm4(bh, boffh[g4] + ks * 32);
                ldsm4(bl, boffl[g4] + ks * 32);
#pragma unroll
                for (int mt = 0; mt < 2; ++mt) {
                    mma_bf16(acc[mt][2*g4],   ah[mt], bh[0], bh[1]);
                    mma_bf16(acc[mt][2*g4+1], ah[mt], bh[2], bh[3]);
                    mma_bf16(acc[mt][2*g4],   al[mt], bh[0], bh[1]);
                    mma_bf16(acc[mt][2*g4+1], al[mt], bh[2], bh[3]);
                    mma_bf16(acc[mt][2*g4],   ah[mt], bl[0], bl[1]);
                    mma_bf16(acc[mt][2*g4+1], ah[mt], bl[2], bl[3]);
                }
            }
        }
        __syncthreads();

#pragma unroll
        for (int nt = 0; nt < 8; ++nt) {
            int cB = ng * 64 + nt * 8 + 2 * (lane & 3);
            float2 b1v = __ldg(reinterpret_cast<const float2*>(&b1[nc * 128 + cB]));
#pragma unroll
            for (int mt = 0; mt < 2; ++mt) {
                int r0 = mg * 32 + mt * 16 + (lane >> 2);
                float h00 = fmaxf(acc[mt][nt][0] + b1v.x, 0.0f);
                float h01 = fmaxf(acc[mt][nt][1] + b1v.y, 0.0f);
                float h10 = fmaxf(acc[mt][nt][2] + b1v.x, 0.0f);
                float h11 = fmaxf(acc[mt][nt][3] + b1v.y, 0.0f);
                int c4 = cB >> 2, ci = cB & 3;
                int sw0 = (r0 >> 3) & 3;
                int sw1 = ((r0 + 8) >> 3) & 3;
                *reinterpret_cast<float2*>(
                    &Hs[r0 * 132 + ((c4 ^ sw0) << 2) + ci]) = make_float2(h00, h01);
                *reinterpret_cast<float2*>(
                    &Hs[(r0 + 8) * 132 + ((c4 ^ sw1) << 2) + ci]) = make_float2(h10, h11);
            }
        }

        {
            const ulonglong2* gw = reinterpret_cast<const ulonglong2*>(g_W2p + nc * 1536);
            ulonglong2* dw = reinterpret_cast<ulonglong2*>(W2s);
#pragma unroll
            for (int i = tid; i < 768; i += 256) dw[i] = __ldg(gw + i);
        }
        if (nc < 3) {
            const uint4* gbh = reinterpret_cast<const uint4*>(
                reinterpret_cast<const char*>(g_Bh) + (size_t)(nc + 1) * 34816);
            const uint4* gbl = reinterpret_cast<const uint4*>(
                reinterpret_cast<const char*>(g_Bl) + (size_t)(nc + 1) * 34816);
            for (int i = tid; i < 2176; i += 256) {
                *reinterpret_cast<uint4*>(smem + SM_BH + i * 16) = __ldg(gbh + i);
                *reinterpret_cast<uint4*>(smem + SM_BL + i * 16) = __ldg(gbl + i);
            }
        }
        __syncthreads();

        {
            const int row  = tid & 127;
            const int half = tid >> 7;
            const int sw   = (row >> 3) & 3;
            const int srow = row * 132;
#pragma unroll 4
            for (int c4 = 0; c4 < 16; ++c4) {
                int cc4 = half * 16 + c4;
                float4 h4 = *reinterpret_cast<const float4*>(
                    &Hs[srow + ((cc4 ^ sw) << 2)]);
#pragma unroll
                for (int cc = 0; cc < 4; ++cc) {
                    float h = (cc == 0 ? h4.x : cc == 1 ? h4.y : cc == 2 ? h4.z : h4.w);
                    unsigned long long hh = pack2(h, h);
                    const ulonglong2* wp = reinterpret_cast<const ulonglong2*>(
                        &W2s[(cc4 * 4 + cc) * 12]);
#pragma unroll
                    for (int q = 0; q < 6; ++q) {
                        ulonglong2 wv = wp[q];
                        fma2(outp[2 * q],     hh, wv.x);
                        fma2(outp[2 * q + 1], hh, wv.y);
                    }
                }
            }
        }
    }

    __syncthreads();
    float* Rs = reinterpret_cast<float*>(smem + SM_W2);
    const int row  = tid & 127;
    const int half = tid >> 7;
    if (half == 1) {
#pragma unroll
        for (int p = 0; p < 12; ++p) {
            float s0, s1;
            unpack2(outp[p], s0, s1);
            Rs[row * 24 + 2 * p]     = s0;
            Rs[row * 24 + 2 * p + 1] = s1;
        }
    }
    __syncthreads();
    if (half == 0) {
        int m    = m0 + row;
        int kidx = m >> 14;
        int bf   = m & 16383;
        int bb   = bf >> 7;
        float* obase = out + ((size_t)bb * 96 + kidx * 24) * 128 + row;
#pragma unroll
        for (int p = 0; p < 12; ++p) {
            float s0, s1;
            unpack2(outp[p], s0, s1);
            obase[(2 * p) * 128] =
                s0 + Rs[row * 24 + 2 * p]     + __ldg(&b2[2 * p]);
            obase[(2 * p + 1) * 128] =
                s1 + Rs[row * 24 + 2 * p + 1] + __ldg(&b2[2 * p + 1]);
        }
    }
}

// ============================================================================
extern "C" void kernel_launch(void* const* d_in, const int* in_sizes, int n_in,
                              void* d_out, int out_size) {
    const float* trend   = (const float*)d_in[0];
    const float* scoarse = (const float*)d_in[1];
    const float* sfine   = (const float*)d_in[2];
    const float* resid   = (const float*)d_in[3];
    const float* W_t = (const float*)d_in[4];
    const float* b_t = (const float*)d_in[5];
    const float* W_c = (const float*)d_in[6];
    const float* b_c = (const float*)d_in[7];
    const float* W_f = (const float*)d_in[8];
    const float* b_f = (const float*)d_in[9];
    const float* W_r = (const float*)d_in[10];
    const float* b_r = (const float*)d_in[11];
    const float* alpha = (const float*)d_in[12];
    const float* W1 = (const float*)d_in[13];
    const float* b1 = (const float*)d_in[14];
    const float* W2 = (const float*)d_in[15];
    const float* b2 = (const float*)d_in[16];

    cudaFuncSetAttribute(mlp_mma_kernel,
                         cudaFuncAttributeMaxDynamicSharedMemorySize, MLP_SMEM);
    cudaFuncSetAttribute(gemv_mma_kernel,
                         cudaFuncAttributeMaxDynamicSharedMemorySize, GEMV_SMEM);

    wcomb_kernel<<<48, 256>>>(W_t, W_c, W_f, W_r);
    w1split_kernel<<<256, 256>>>(W1);
    w2p_kernel<<<24, 256>>>(W2);
    gemv_mma_kernel<<<640, 256, GEMV_SMEM>>>(trend, scoarse, sfine, resid,
                                             b_t, b_c, b_f, b_r);
    chain_kernel<<<NROWS / 8, 256>>>(alpha);
    mlp_mma_kernel<<<MTOT / 128, 256, MLP_SMEM>>>(b1, b2, (float*)d_out);
}

// round 8
// speedup vs baseline: 2.0103x; 1.3273x over previous
#include <cuda_runtime.h>
#include <cuda_bf16.h>
#include <cstdint>

// ---------------- problem constants ----------------
#define BATCH   128
#define LTOT    720
#define FEAT    128
#define SEGL    24
#define WINN    15
#define NPREDK  4
#define DDIM    128
#define HDIM    512
#define NROWS   (BATCH*FEAT)          // 16384
#define MTOT    (NPREDK*NROWS)        // 65536
#define EPSC    1e-6f
#define EPS2    1e-12f
#define MAXNC   0.99999f
#define CLIPC   0.99999988f
#define DECAYF  0.9f

// global scratch (static __device__, no allocs)
__device__ float g_z[(size_t)WINN * NROWS * DDIM];                  // window z
__device__ __align__(16) __nv_bfloat16 g_Ah[(size_t)MTOT * DDIM];   // MLP A hi
__device__ __align__(16) __nv_bfloat16 g_Al[(size_t)MTOT * DDIM];   // MLP A lo
// W1 images: [nc][n=128][k pitch 136] bf16  (chunk = 34816 B)
__device__ __align__(16) __nv_bfloat16 g_Bh[4 * 128 * 136];
__device__ __align__(16) __nv_bfloat16 g_Bl[4 * 128 * 136];
// combined tan weights Wc images: [d=128][k pitch 104] bf16
__device__ __align__(16) __nv_bfloat16 g_Gh[128 * 104];
__device__ __align__(16) __nv_bfloat16 g_Gl[128 * 104];
__device__ __align__(16) unsigned long long g_W2p[HDIM * 12];       // W2 packed j-pairs

// ---------------- f32x2 packed-FMA helpers ----------------
static __device__ __forceinline__ unsigned long long pack2(float x, float y) {
    unsigned long long r;
    asm("mov.b64 %0, {%1,%2};" : "=l"(r) : "f"(x), "f"(y));
    return r;
}
static __device__ __forceinline__ void unpack2(unsigned long long a, float &x, float &y) {
    asm("mov.b64 {%0,%1}, %2;" : "=f"(x), "=f"(y) : "l"(a));
}
static __device__ __forceinline__ void fma2(unsigned long long &a,
                                            unsigned long long b,
                                            unsigned long long c) {
    asm("fma.rn.f32x2 %0, %1, %2, %0;" : "+l"(a) : "l"(b), "l"(c));
}

// ---------------- mma.sync / ldmatrix helpers ----------------
static __device__ __forceinline__ uint32_t smem_to_u32(const void* p) {
    uint32_t a;
    asm("{ .reg .u64 t; cvta.to.shared.u64 t, %1; cvt.u32.u64 %0, t; }"
        : "=r"(a) : "l"(p));
    return a;
}
static __device__ __forceinline__ void ldsm4(uint32_t r[4], uint32_t addr) {
    asm volatile("ldmatrix.sync.aligned.m8n8.x4.shared.b16 {%0,%1,%2,%3}, [%4];"
                 : "=r"(r[0]), "=r"(r[1]), "=r"(r[2]), "=r"(r[3]) : "r"(addr));
}
static __device__ __forceinline__ void ldsm4t(uint32_t r[4], uint32_t addr) {
    asm volatile("ldmatrix.sync.aligned.m8n8.x4.trans.shared.b16 {%0,%1,%2,%3}, [%4];"
                 : "=r"(r[0]), "=r"(r[1]), "=r"(r[2]), "=r"(r[3]) : "r"(addr));
}
static __device__ __forceinline__ void mma_bf16(float d[4], const uint32_t a[4],
                                                uint32_t b0, uint32_t b1) {
    asm volatile(
        "mma.sync.aligned.m16n8k16.row.col.f32.bf16.bf16.f32 "
        "{%0,%1,%2,%3}, {%4,%5,%6,%7}, {%8,%9}, {%0,%1,%2,%3};"
        : "+f"(d[0]), "+f"(d[1]), "+f"(d[2]), "+f"(d[3])
        : "r"(a[0]), "r"(a[1]), "r"(a[2]), "r"(a[3]), "r"(b0), "r"(b1));
}

// ---------------- warp math helpers ----------------
static __device__ __forceinline__ float wred(float v) {
#pragma unroll
    for (int o = 16; o > 0; o >>= 1) v += __shfl_xor_sync(0xffffffffu, v, o);
    return v;
}

struct F4 { float x, y, z, w; };

static __device__ __forceinline__ float dotred(const F4 &a, const F4 &b) {
    return wred(a.x*b.x + a.y*b.y + a.z*b.z + a.w*b.w);
}

static __device__ __forceinline__ F4 logmap_f(const F4 &x, float sqx,
                                              const F4 &y, float sqy) {
    float xy  = dotred(x, y);
    float txy = -2.0f * xy;
    float cx  = 1.0f + txy + sqy;
    float cy  = 1.0f - sqx;
    float den = fmaxf(1.0f + txy + sqx*sqy, EPSC);
    float inv = 1.0f / den;
    F4 d;
    d.x = (cy*y.x - cx*x.x) * inv;
    d.y = (cy*y.y - cx*x.y) * inv;
    d.z = (cy*y.z - cx*x.z) * inv;
    d.w = (cy*y.w - cx*x.w) * inv;
    float sqd = dotred(d, d);
    float nd  = sqrtf(fmaxf(sqd, EPS2));
    float s   = fmaxf(cy, EPSC) * atanhf(fminf(nd, CLIPC)) / nd;
    F4 r = { d.x*s, d.y*s, d.z*s, d.w*s };
    return r;
}

static __device__ __forceinline__ void expmap_f(const F4 &x, float sqx, const F4 &v,
                                                F4 &zout, float &sqout) {
    float m   = fmaxf(1.0f - sqx, EPSC);
    float sqv = dotred(v, v);
    float nv  = sqrtf(fmaxf(sqv, EPS2));
    float th  = tanhf(nv / m);
    float sc  = th / nv;
    F4 sec = { v.x*sc, v.y*sc, v.z*sc, v.w*sc };
    float xy = dotred(x, sec);
    float y2 = dotred(sec, sec);
    float ca  = 1.0f + 2.0f*xy + y2;
    float cb  = 1.0f - sqx;
    float den = fmaxf(1.0f + 2.0f*xy + sqx*y2, EPSC);
    float inv = 1.0f / den;
    F4 r = { (ca*x.x + cb*sec.x)*inv, (ca*x.y + cb*sec.y)*inv,
             (ca*x.z + cb*sec.z)*inv, (ca*x.w + cb*sec.w)*inv };
    float sqr = dotred(r, r);
    float nr  = sqrtf(fmaxf(sqr, EPS2));
    if (nr > MAXNC) {
        float s = MAXNC / nr;
        r.x *= s; r.y *= s; r.z *= s; r.w *= s;
        sqr *= s * s;
    }
    zout = r; sqout = sqr;
}

// ============================================================================
// Prep: combined tan weights -> bf16 hi/lo images [d=128][k pitch 104]
// ============================================================================
__global__ void wcomb_kernel(const float* __restrict__ W_t, const float* __restrict__ W_c,
                             const float* __restrict__ W_f, const float* __restrict__ W_r)
{
    int idx = blockIdx.x * 256 + threadIdx.x;   // 12288 total
    if (idx >= 128 * 96) return;
    int d = idx / 96;
    int k = idx - d * 96;
    int st = k / 24, s = k - st * 24;
    const float* W = (st == 0 ? W_t : st == 1 ? W_c : st == 2 ? W_f : W_r);
    float v = __ldg(&W[s * DDIM + d]);
    __nv_bfloat16 hi = __float2bfloat16(v);
    __nv_bfloat16 lo = __float2bfloat16(v - __bfloat162float(hi));
    g_Gh[d * 104 + k] = hi;
    g_Gl[d * 104 + k] = lo;
}

// ============================================================================
// Kernel 1a: tan GEMM on tensor cores + fused expmap0 -> g_z.
// Grid 1920 = 128 b x 15 slots; 256 thr / 8 warps; 2 CTAs per SM.
// Fragments are scaled in registers and written DIRECTLY to g_z (no sD).
// ============================================================================
#define SM2_AH   0
#define SM2_AL   26112
#define SM2_BH   52224
#define SM2_BL   78848
#define SM2_P    105472
#define SM2_BIAS 106496
#define GEMV_SMEM (106496 + 512)      // 107008 B -> 2 blocks/SM

__global__ void __launch_bounds__(256, 2)
gemv_mma_kernel(const float* __restrict__ trend,  const float* __restrict__ scoarse,
                const float* __restrict__ sfine,  const float* __restrict__ resid,
                const float* __restrict__ b_t, const float* __restrict__ b_c,
                const float* __restrict__ b_f, const float* __restrict__ b_r)
{
    extern __shared__ char smem[];
    const uint32_t sbase = smem_to_u32(smem);
    const int tid  = threadIdx.x;
    const int lane = tid & 31;
    const int wid  = tid >> 5;
    const int mg   = wid >> 1;          // rows mg*32
    const int ng   = wid & 1;           // cols ng*64
    const int b    = blockIdx.x / 15;
    const int slot = blockIdx.x - b * 15;

    float* sPart = reinterpret_cast<float*>(smem + SM2_P);     // [128][2]
    float* sBias = reinterpret_cast<float*>(smem + SM2_BIAS);  // [128]

    // stage Wc images + combined bias
    {
        const uint4* gh = reinterpret_cast<const uint4*>(g_Gh);
        const uint4* gl = reinterpret_cast<const uint4*>(g_Gl);
        for (int i = tid; i < 1664; i += 256) {
            *reinterpret_cast<uint4*>(smem + SM2_BH + i * 16) = __ldg(gh + i);
            *reinterpret_cast<uint4*>(smem + SM2_BL + i * 16) = __ldg(gl + i);
        }
        if (tid < 128)
            sBias[tid] = __ldg(&b_t[tid]) + __ldg(&b_c[tid]) +
                         __ldg(&b_f[tid]) + __ldg(&b_r[tid]);
    }

    // ---- stage A^T hi/lo: row k = st*24+s is x_st[b][360+slot*24+s][:] ----
    const size_t base_b = (size_t)b * LTOT * FEAT;
#pragma unroll
    for (int it = 0; it < 12; ++it) {
        int i  = tid + it * 256;
        int k  = i >> 5;
        int c4 = i & 31;
        int st = k / 24, s = k - st * 24;
        const float* src = (st == 0 ? trend : st == 1 ? scoarse :
                            st == 2 ? sfine : resid);
        float4 v = __ldg(reinterpret_cast<const float4*>(
            &src[base_b + (size_t)(360 + slot * 24 + s) * FEAT]) + c4);
        __nv_bfloat162 h01 = __floats2bfloat162_rn(v.x, v.y);
        __nv_bfloat162 h23 = __floats2bfloat162_rn(v.z, v.w);
        float r0 = v.x - __bfloat162float(__low2bfloat16(h01));
        float r1 = v.y - __bfloat162float(__high2bfloat16(h01));
        float r2 = v.z - __bfloat162float(__low2bfloat16(h23));
        float r3 = v.w - __bfloat162float(__high2bfloat16(h23));
        __nv_bfloat162 l01 = __floats2bfloat162_rn(r0, r1);
        __nv_bfloat162 l23 = __floats2bfloat162_rn(r2, r3);
        uint32_t off = (uint32_t)(k * 136 + c4 * 4) * 2;
        *reinterpret_cast<uint2*>(smem + SM2_AH + off) =
            make_uint2(*reinterpret_cast<uint32_t*>(&h01),
                       *reinterpret_cast<uint32_t*>(&h23));
        *reinterpret_cast<uint2*>(smem + SM2_AL + off) =
            make_uint2(*reinterpret_cast<uint32_t*>(&l01),
                       *reinterpret_cast<uint32_t*>(&l23));
    }
    __syncthreads();

    // ldmatrix addresses
    uint32_t aoffh[2], aoffl[2], boffh[4], boffl[4];
    {
        int kRow = (lane & 7) + ((lane >> 4) << 3);
        int mC8  = ((lane >> 3) & 1) << 3;
#pragma unroll
        for (int mt = 0; mt < 2; ++mt) {
            uint32_t off = (uint32_t)(kRow * 136 + mg * 32 + mt * 16 + mC8) * 2;
            aoffh[mt] = sbase + SM2_AH + off;
            aoffl[mt] = sbase + SM2_AL + off;
        }
        int nB = ((lane >> 4) << 3) + (lane & 7);
        int kB = ((lane >> 3) & 1) << 3;
#pragma unroll
        for (int g4 = 0; g4 < 4; ++g4) {
            uint32_t off = (uint32_t)((ng * 64 + g4 * 16 + nB) * 104 + kB) * 2;
            boffh[g4] = sbase + SM2_BH + off;
            boffl[g4] = sbase + SM2_BL + off;
        }
    }

    // ---- GEMM: 6 k-steps, 3-term bf16 split ----
    float acc[2][8][4];
#pragma unroll
    for (int mt = 0; mt < 2; ++mt)
#pragma unroll
        for (int nt = 0; nt < 8; ++nt)
#pragma unroll
            for (int q = 0; q < 4; ++q) acc[mt][nt][q] = 0.0f;

#pragma unroll
    for (int ks = 0; ks < 6; ++ks) {
        uint32_t ah[2][4], al[2][4];
        ldsm4t(ah[0], aoffh[0] + ks * 16 * 272);
        ldsm4t(ah[1], aoffh[1] + ks * 16 * 272);
        ldsm4t(al[0], aoffl[0] + ks * 16 * 272);
        ldsm4t(al[1], aoffl[1] + ks * 16 * 272);
#pragma unroll
        for (int g4 = 0; g4 < 4; ++g4) {
            uint32_t bh[4], bl[4];
            ldsm4(bh, boffh[g4] + ks * 32);
            ldsm4(bl, boffl[g4] + ks * 32);
#pragma unroll
            for (int mt = 0; mt < 2; ++mt) {
                mma_bf16(acc[mt][2*g4],   ah[mt], bh[0], bh[1]);
                mma_bf16(acc[mt][2*g4+1], ah[mt], bh[2], bh[3]);
                mma_bf16(acc[mt][2*g4],   al[mt], bh[0], bh[1]);
                mma_bf16(acc[mt][2*g4+1], al[mt], bh[2], bh[3]);
                mma_bf16(acc[mt][2*g4],   ah[mt], bl[0], bl[1]);
                mma_bf16(acc[mt][2*g4+1], ah[mt], bl[2], bl[3]);
            }
        }
    }

    // ---- + bias; row sum-of-squares partials ----
    float p[2][2];
#pragma unroll
    for (int mt = 0; mt < 2; ++mt) { p[mt][0] = 0.0f; p[mt][1] = 0.0f; }
#pragma unroll
    for (int nt = 0; nt < 8; ++nt) {
        int c = ng * 64 + nt * 8 + 2 * (lane & 3);
        float bx = sBias[c], by = sBias[c + 1];
#pragma unroll
        for (int mt = 0; mt < 2; ++mt) {
            acc[mt][nt][0] += bx; acc[mt][nt][1] += by;
            acc[mt][nt][2] += bx; acc[mt][nt][3] += by;
            p[mt][0] += acc[mt][nt][0]*acc[mt][nt][0] + acc[mt][nt][1]*acc[mt][nt][1];
            p[mt][1] += acc[mt][nt][2]*acc[mt][nt][2] + acc[mt][nt][3]*acc[mt][nt][3];
        }
    }
#pragma unroll
    for (int mt = 0; mt < 2; ++mt) {
#pragma unroll
        for (int h = 0; h < 2; ++h) {
            p[mt][h] += __shfl_xor_sync(0xffffffffu, p[mt][h], 1);
            p[mt][h] += __shfl_xor_sync(0xffffffffu, p[mt][h], 2);
        }
        if ((lane & 3) == 0) {
            int r0 = mg * 32 + mt * 16 + (lane >> 2);
            sPart[r0 * 2 + ng]       = p[mt][0];
            sPart[(r0 + 8) * 2 + ng] = p[mt][1];
        }
    }
    __syncthreads();

    // ---- scale (expmap0) in registers; direct write to g_z ----
    float* gz = &g_z[((size_t)slot * NROWS + (size_t)b * 128) * DDIM];
#pragma unroll
    for (int mt = 0; mt < 2; ++mt) {
        int r0 = mg * 32 + mt * 16 + (lane >> 2);
        float sq0 = sPart[r0 * 2] + sPart[r0 * 2 + 1];
        float sq1 = sPart[(r0 + 8) * 2] + sPart[(r0 + 8) * 2 + 1];
        float n0 = sqrtf(fmaxf(sq0, EPS2));
        float n1 = sqrtf(fmaxf(sq1, EPS2));
        float t0 = tanhf(n0), t1 = tanhf(n1);
        float sc0 = (t0 > MAXNC ? MAXNC : t0) / n0;
        float sc1 = (t1 > MAXNC ? MAXNC : t1) / n1;
#pragma unroll
        for (int nt = 0; nt < 8; ++nt) {
            int c = ng * 64 + nt * 8 + 2 * (lane & 3);
            *reinterpret_cast<float2*>(&gz[r0 * 128 + c]) =
                make_float2(acc[mt][nt][0] * sc0, acc[mt][nt][1] * sc0);
            *reinterpret_cast<float2*>(&gz[(r0 + 8) * 128 + c]) =
                make_float2(acc[mt][nt][2] * sc1, acc[mt][nt][3] * sc1);
        }
    }
}

// ============================================================================
// Kernel 1b: hyperbolic chain; emits bf16 hi/lo split of t0 into g_Ah/g_Al.
// ============================================================================
static __device__ __forceinline__ F4 ldz(int slot, int row, int lane) {
    float4 v = __ldg(reinterpret_cast<const float4*>(
        &g_z[((size_t)slot * NROWS + row) * DDIM + lane * 4]));
    F4 r = { v.x, v.y, v.z, v.w };
    return r;
}

static __device__ __forceinline__ void store_split(float v0, float v1, float v2, float v3,
                                                   __nv_bfloat16* hi, __nv_bfloat16* lo,
                                                   size_t off) {
    __nv_bfloat162 h01 = __floats2bfloat162_rn(v0, v1);
    __nv_bfloat162 h23 = __floats2bfloat162_rn(v2, v3);
    float r0 = v0 - __bfloat162float(__low2bfloat16(h01));
    float r1 = v1 - __bfloat162float(__high2bfloat16(h01));
    float r2 = v2 - __bfloat162float(__low2bfloat16(h23));
    float r3 = v3 - __bfloat162float(__high2bfloat16(h23));
    __nv_bfloat162 l01 = __floats2bfloat162_rn(r0, r1);
    __nv_bfloat162 l23 = __floats2bfloat162_rn(r2, r3);
    uint2 uh = make_uint2(*reinterpret_cast<uint32_t*>(&h01),
                          *reinterpret_cast<uint32_t*>(&h23));
    uint2 ul = make_uint2(*reinterpret_cast<uint32_t*>(&l01),
                          *reinterpret_cast<uint32_t*>(&l23));
    *reinterpret_cast<uint2*>(hi + off) = uh;
    *reinterpret_cast<uint2*>(lo + off) = ul;
}

__global__ void __launch_bounds__(256, 3)
chain_kernel(const float* __restrict__ alpha_p)
{
    const int tid  = threadIdx.x;
    const int wid  = tid >> 5;
    const int lane = tid & 31;
    const int row  = blockIdx.x * 8 + wid;

    float s = 0.0f, wv = 1.0f;
#pragma unroll
    for (int j = 13; j >= 0; --j) { s += wv; if (j > 0) wv *= DECAYF; }
    const float w0  = wv / s;
    const float w13 = 1.0f / s;
    const float invd = 1.0f / DECAYF;

    F4 za = ldz(0, row, lane);
    F4 zb = ldz(1, row, lane);
    F4 zc = ldz(2, row, lane);
    float sqa = dotred(za, za);
    float sqb = dotred(zb, zb);

    F4 avg = {0,0,0,0};
    F4 vel0, vel1, vel2;
    float wj = w0;

#pragma unroll
    for (int j = 0; j < 14; ++j) {
        F4 vel = logmap_f(za, sqa, zb, sqb);
        avg.x += wj * vel.x; avg.y += wj * vel.y;
        avg.z += wj * vel.z; avg.w += wj * vel.w;
        if (j == 0) vel0 = vel;
        else if (j == 1) vel1 = vel;
        else if (j == 2) vel2 = vel;
        wj *= invd;
        za = zb; sqa = sqb;
        zb = zc; sqb = dotred(zb, zb);
        if (j + 3 < WINN) zc = ldz(j + 3, row, lane);
    }

    const float alpha = __ldg(alpha_p);
    F4 zl = za; float sql = sqa;
#pragma unroll
    for (int k = 0; k < NPREDK; ++k) {
        F4 v = { avg.x * alpha, avg.y * alpha, avg.z * alpha, avg.w * alpha };
        F4 zn; float sqn;
        expmap_f(zl, sql, v, zn, sqn);

        float n  = sqrtf(fmaxf(sqn, EPS2));
        float sc = atanhf(fminf(n, CLIPC)) / n;
        const size_t m = (size_t)k * NROWS + row;
        store_split(zn.x * sc, zn.y * sc, zn.z * sc, zn.w * sc,
                    g_Ah, g_Al, m * DDIM + lane * 4);

        if (k < 3) {
            F4 vn = logmap_f(zl, sql, zn, sqn);
            F4 vk = (k == 0 ? vel0 : (k == 1 ? vel1 : vel2));
            avg.x = (avg.x - w0 * vk.x) * DECAYF + w13 * vn.x;
            avg.y = (avg.y - w0 * vk.y) * DECAYF + w13 * vn.y;
            avg.z = (avg.z - w0 * vk.z) * DECAYF + w13 * vn.z;
            avg.w = (avg.w - w0 * vk.w) * DECAYF + w13 * vn.w;
        }
        zl = zn; sql = sqn;
    }
}

// ============================================================================
// Prep kernels: W1 -> bf16 hi/lo images [nc][n][pitch 136]; W2 packed pairs.
// ============================================================================
__global__ void w1split_kernel(const float* __restrict__ W1) {
    int idx = blockIdx.x * 256 + threadIdx.x;   // 65536 total
    if (idx >= 4 * 16384) return;
    int nc = idx >> 14;
    int n  = (idx >> 7) & 127;
    int k  = idx & 127;
    float v = __ldg(&W1[(size_t)k * HDIM + nc * 128 + n]);
    __nv_bfloat16 hi = __float2bfloat16(v);
    __nv_bfloat16 lo = __float2bfloat16(v - __bfloat162float(hi));
    size_t off = (size_t)(nc * 128 + n) * 136 + k;
    g_Bh[off] = hi;
    g_Bl[off] = lo;
}

__global__ void w2p_kernel(const float* __restrict__ W2) {
    int idx = blockIdx.x * 256 + threadIdx.x;   // 6144 total
    if (idx >= HDIM * 12) return;
    int c  = idx / 12;
    int jp = idx - c * 12;
    float a = __ldg(&W2[(size_t)c * 24 + 2 * jp]);
    float b = __ldg(&W2[(size_t)c * 24 + 2 * jp + 1]);
    g_W2p[idx] = pack2(a, b);
}

// ============================================================================
// Kernel 2: MLP via mma.sync (bf16 split, 3 terms) + FFMA2 GEMM2.
// ============================================================================
#define SM_AH 0
#define SM_AL 34816
#define SM_BH 69632
#define SM_BL 104448
#define SM_HS 139264
#define SM_W2 206848
#define MLP_SMEM (206848 + 12288)     // 219136 B

__global__ void __launch_bounds__(256)
mlp_mma_kernel(const float* __restrict__ b1, const float* __restrict__ b2,
               float* __restrict__ out)
{
    extern __shared__ char smem[];
    const uint32_t sbase = smem_to_u32(smem);
    const int tid  = threadIdx.x;
    const int lane = tid & 31;
    const int wid  = tid >> 5;
    const int mg   = wid >> 1;
    const int ng   = wid & 1;
    const int m0   = blockIdx.x * 128;

    {
        const uint4* gah = reinterpret_cast<const uint4*>(&g_Ah[(size_t)m0 * DDIM]);
        const uint4* gal = reinterpret_cast<const uint4*>(&g_Al[(size_t)m0 * DDIM]);
#pragma unroll
        for (int i = tid; i < 2048; i += 256) {
            int r = i >> 4, kc = i & 15;
            *reinterpret_cast<uint4*>(smem + SM_AH + r * 272 + kc * 16) = __ldg(gah + i);
            *reinterpret_cast<uint4*>(smem + SM_AL + r * 272 + kc * 16) = __ldg(gal + i);
        }
    }
    {
        const uint4* gbh = reinterpret_cast<const uint4*>(g_Bh);
        const uint4* gbl = reinterpret_cast<const uint4*>(g_Bl);
        for (int i = tid; i < 2176; i += 256) {
            *reinterpret_cast<uint4*>(smem + SM_BH + i * 16) = __ldg(gbh + i);
            *reinterpret_cast<uint4*>(smem + SM_BL + i * 16) = __ldg(gbl + i);
        }
    }

    uint32_t aoffh[2], aoffl[2], boffh[4], boffl[4];
    {
        int rA   = lane & 15;
        int colA = (lane >> 4) << 3;
#pragma unroll
        for (int mt = 0; mt < 2; ++mt) {
            uint32_t off = (uint32_t)((mg * 32 + mt * 16 + rA) * 136 + colA) * 2;
            aoffh[mt] = sbase + SM_AH + off;
            aoffl[mt] = sbase + SM_AL + off;
        }
        int nB = ((lane >> 4) << 3) + (lane & 7);
        int kB = ((lane >> 3) & 1) << 3;
#pragma unroll
        for (int g4 = 0; g4 < 4; ++g4) {
            uint32_t off = (uint32_t)((ng * 64 + g4 * 16 + nB) * 136 + kB) * 2;
            boffh[g4] = sbase + SM_BH + off;
            boffl[g4] = sbase + SM_BL + off;
        }
    }

    float* Hs = reinterpret_cast<float*>(smem + SM_HS);
    unsigned long long* W2s = reinterpret_cast<unsigned long long*>(smem + SM_W2);

    unsigned long long outp[12];
#pragma unroll
    for (int q = 0; q < 12; ++q) outp[q] = 0ull;

    for (int nc = 0; nc < 4; ++nc) {
        __syncthreads();

        float acc[2][8][4];
#pragma unroll
        for (int mt = 0; mt < 2; ++mt)
#pragma unroll
            for (int nt = 0; nt < 8; ++nt)
#pragma unroll
                for (int q = 0; q < 4; ++q) acc[mt][nt][q] = 0.0f;

#pragma unroll
        for (int ks = 0; ks < 8; ++ks) {
            uint32_t ah[2][4], al[2][4];
            ldsm4(ah[0], aoffh[0] + ks * 32);
            ldsm4(ah[1], aoffh[1] + ks * 32);
            ldsm4(al[0], aoffl[0] + ks * 32);
            ldsm4(al[1], aoffl[1] + ks * 32);
#pragma unroll
            for (int g4 = 0; g4 < 4; ++g4) {
                uint32_t bh[4], bl[4];
                ldsm4(bh, boffh[g4] + ks * 32);
                ldsm4(bl, boffl[g4] + ks * 32);
#pragma unroll
                for (int mt = 0; mt < 2; ++mt) {
                    mma_bf16(acc[mt][2*g4],   ah[mt], bh[0], bh[1]);
                    mma_bf16(acc[mt][2*g4+1], ah[mt], bh[2], bh[3]);
                    mma_bf16(acc[mt][2*g4],   al[mt], bh[0], bh[1]);
                    mma_bf16(acc[mt][2*g4+1], al[mt], bh[2], bh[3]);
                    mma_bf16(acc[mt][2*g4],   ah[mt], bl[0], bl[1]);
                    mma_bf16(acc[mt][2*g4+1], ah[mt], bl[2], bl[3]);
                }
            }
        }
        __syncthreads();

#pragma unroll
        for (int nt = 0; nt < 8; ++nt) {
            int cB = ng * 64 + nt * 8 + 2 * (lane & 3);
            float2 b1v = __ldg(reinterpret_cast<const float2*>(&b1[nc * 128 + cB]));
#pragma unroll
            for (int mt = 0; mt < 2; ++mt) {
                int r0 = mg * 32 + mt * 16 + (lane >> 2);
                float h00 = fmaxf(acc[mt][nt][0] + b1v.x, 0.0f);
                float h01 = fmaxf(acc[mt][nt][1] + b1v.y, 0.0f);
                float h10 = fmaxf(acc[mt][nt][2] + b1v.x, 0.0f);
                float h11 = fmaxf(acc[mt][nt][3] + b1v.y, 0.0f);
                int c4 = cB >> 2, ci = cB & 3;
                int sw0 = (r0 >> 3) & 3;
                int sw1 = ((r0 + 8) >> 3) & 3;
                *reinterpret_cast<float2*>(
                    &Hs[r0 * 132 + ((c4 ^ sw0) << 2) + ci]) = make_float2(h00, h01);
                *reinterpret_cast<float2*>(
                    &Hs[(r0 + 8) * 132 + ((c4 ^ sw1) << 2) + ci]) = make_float2(h10, h11);
            }
        }

        {
            const ulonglong2* gw = reinterpret_cast<const ulonglong2*>(g_W2p + nc * 1536);
            ulonglong2* dw = reinterpret_cast<ulonglong2*>(W2s);
#pragma unroll
            for (int i = tid; i < 768; i += 256) dw[i] = __ldg(gw + i);
        }
        if (nc < 3) {
            const uint4* gbh = reinterpret_cast<const uint4*>(
                reinterpret_cast<const char*>(g_Bh) + (size_t)(nc + 1) * 34816);
            const uint4* gbl = reinterpret_cast<const uint4*>(
                reinterpret_cast<const char*>(g_Bl) + (size_t)(nc + 1) * 34816);
            for (int i = tid; i < 2176; i += 256) {
                *reinterpret_cast<uint4*>(smem + SM_BH + i * 16) = __ldg(gbh + i);
                *reinterpret_cast<uint4*>(smem + SM_BL + i * 16) = __ldg(gbl + i);
            }
        }
        __syncthreads();

        {
            const int row  = tid & 127;
            const int half = tid >> 7;
            const int sw   = (row >> 3) & 3;
            const int srow = row * 132;
#pragma unroll 4
            for (int c4 = 0; c4 < 16; ++c4) {
                int cc4 = half * 16 + c4;
                float4 h4 = *reinterpret_cast<const float4*>(
                    &Hs[srow + ((cc4 ^ sw) << 2)]);
#pragma unroll
                for (int cc = 0; cc < 4; ++cc) {
                    float h = (cc == 0 ? h4.x : cc == 1 ? h4.y : cc == 2 ? h4.z : h4.w);
                    unsigned long long hh = pack2(h, h);
                    const ulonglong2* wp = reinterpret_cast<const ulonglong2*>(
                        &W2s[(cc4 * 4 + cc) * 12]);
#pragma unroll
                    for (int q = 0; q < 6; ++q) {
                        ulonglong2 wv = wp[q];
                        fma2(outp[2 * q],     hh, wv.x);
                        fma2(outp[2 * q + 1], hh, wv.y);
                    }
                }
            }
        }
    }

    __syncthreads();
    float* Rs = reinterpret_cast<float*>(smem + SM_W2);
    const int row  = tid & 127;
    const int half = tid >> 7;
    if (half == 1) {
#pragma unroll
        for (int p = 0; p < 12; ++p) {
            float s0, s1;
            unpack2(outp[p], s0, s1);
            Rs[row * 24 + 2 * p]     = s0;
            Rs[row * 24 + 2 * p + 1] = s1;
        }
    }
    __syncthreads();
    if (half == 0) {
        int m    = m0 + row;
        int kidx = m >> 14;
        int bf   = m & 16383;
        int bb   = bf >> 7;
        float* obase = out + ((size_t)bb * 96 + kidx * 24) * 128 + row;
#pragma unroll
        for (int p = 0; p < 12; ++p) {
            float s0, s1;
            unpack2(outp[p], s0, s1);
            obase[(2 * p) * 128] =
                s0 + Rs[row * 24 + 2 * p]     + __ldg(&b2[2 * p]);
            obase[(2 * p + 1) * 128] =
                s1 + Rs[row * 24 + 2 * p + 1] + __ldg(&b2[2 * p + 1]);
        }
    }
}

// ============================================================================
extern "C" void kernel_launch(void* const* d_in, const int* in_sizes, int n_in,
                              void* d_out, int out_size) {
    const float* trend   = (const float*)d_in[0];
    const float* scoarse = (const float*)d_in[1];
    const float* sfine   = (const float*)d_in[2];
    const float* resid   = (const float*)d_in[3];
    const float* W_t = (const float*)d_in[4];
    const float* b_t = (const float*)d_in[5];
    const float* W_c = (const float*)d_in[6];
    const float* b_c = (const float*)d_in[7];
    const float* W_f = (const float*)d_in[8];
    const float* b_f = (const float*)d_in[9];
    const float* W_r = (const float*)d_in[10];
    const float* b_r = (const float*)d_in[11];
    const float* alpha = (const float*)d_in[12];
    const float* W1 = (const float*)d_in[13];
    const float* b1 = (const float*)d_in[14];
    const float* W2 = (const float*)d_in[15];
    const float* b2 = (const float*)d_in[16];

    cudaFuncSetAttribute(mlp_mma_kernel,
                         cudaFuncAttributeMaxDynamicSharedMemorySize, MLP_SMEM);
    cudaFuncSetAttribute(gemv_mma_kernel,
                         cudaFuncAttributeMaxDynamicSharedMemorySize, GEMV_SMEM);

    wcomb_kernel<<<48, 256>>>(W_t, W_c, W_f, W_r);
    w1split_kernel<<<256, 256>>>(W1);
    w2p_kernel<<<24, 256>>>(W2);
    gemv_mma_kernel<<<1920, 256, GEMV_SMEM>>>(trend, scoarse, sfine, resid,
                                              b_t, b_c, b_f, b_r);
    chain_kernel<<<NROWS / 8, 256>>>(alpha);
    mlp_mma_kernel<<<MTOT / 128, 256, MLP_SMEM>>>(b1, b2, (float*)d_out);
}

// round 9
// speedup vs baseline: 2.1199x; 1.0545x over previous
#include <cuda_runtime.h>
#include <cuda_bf16.h>
#include <cstdint>

// ---------------- problem constants ----------------
#define BATCH   128
#define LTOT    720
#define FEAT    128
#define SEGL    24
#define WINN    15
#define NPREDK  4
#define DDIM    128
#define HDIM    512
#define NROWS   (BATCH*FEAT)          // 16384
#define MTOT    (NPREDK*NROWS)        // 65536
#define EPSC    1e-6f
#define EPS2    1e-12f
#define MAXNC   0.99999f
#define CLIPC   0.99999988f
#define DECAYF  0.9f

// global scratch (static __device__, no allocs)
__device__ float g_z[(size_t)WINN * NROWS * DDIM];                  // window z
__device__ __align__(16) __nv_bfloat16 g_Ah[(size_t)MTOT * DDIM];   // MLP A hi
__device__ __align__(16) __nv_bfloat16 g_Al[(size_t)MTOT * DDIM];   // MLP A lo
// W1 chunk images, PRE-SWIZZLED dense [nc][n=128][k=128] bf16 (32KB chunks)
__device__ __align__(16) __nv_bfloat16 g_Bh[4 * 128 * 128];
__device__ __align__(16) __nv_bfloat16 g_Bl[4 * 128 * 128];
// combined tan weights Wc images: [d=128][k pitch 104] bf16
__device__ __align__(16) __nv_bfloat16 g_Gh[128 * 104];
__device__ __align__(16) __nv_bfloat16 g_Gl[128 * 104];
__device__ __align__(16) unsigned long long g_W2p[HDIM * 12];       // W2 packed j-pairs

// ---------------- f32x2 packed helpers ----------------
static __device__ __forceinline__ unsigned long long pack2(float x, float y) {
    unsigned long long r;
    asm("mov.b64 %0, {%1,%2};" : "=l"(r) : "f"(x), "f"(y));
    return r;
}
static __device__ __forceinline__ void unpack2(unsigned long long a, float &x, float &y) {
    asm("mov.b64 {%0,%1}, %2;" : "=f"(x), "=f"(y) : "l"(a));
}
static __device__ __forceinline__ void fma2(unsigned long long &a,
                                            unsigned long long b,
                                            unsigned long long c) {
    asm("fma.rn.f32x2 %0, %1, %2, %0;" : "+l"(a) : "l"(b), "l"(c));
}
static __device__ __forceinline__ void fadd2(unsigned long long &a,
                                             unsigned long long b) {
    asm("add.rn.f32x2 %0, %0, %1;" : "+l"(a) : "l"(b));
}

// ---------------- mma.sync / ldmatrix helpers ----------------
static __device__ __forceinline__ uint32_t smem_to_u32(const void* p) {
    uint32_t a;
    asm("{ .reg .u64 t; cvta.to.shared.u64 t, %1; cvt.u32.u64 %0, t; }"
        : "=r"(a) : "l"(p));
    return a;
}
static __device__ __forceinline__ void ldsm4(uint32_t r[4], uint32_t addr) {
    asm volatile("ldmatrix.sync.aligned.m8n8.x4.shared.b16 {%0,%1,%2,%3}, [%4];"
                 : "=r"(r[0]), "=r"(r[1]), "=r"(r[2]), "=r"(r[3]) : "r"(addr));
}
static __device__ __forceinline__ void ldsm4t(uint32_t r[4], uint32_t addr) {
    asm volatile("ldmatrix.sync.aligned.m8n8.x4.trans.shared.b16 {%0,%1,%2,%3}, [%4];"
                 : "=r"(r[0]), "=r"(r[1]), "=r"(r[2]), "=r"(r[3]) : "r"(addr));
}
static __device__ __forceinline__ void mma_bf16(float d[4], const uint32_t a[4],
                                                uint32_t b0, uint32_t b1) {
    asm volatile(
        "mma.sync.aligned.m16n8k16.row.col.f32.bf16.bf16.f32 "
        "{%0,%1,%2,%3}, {%4,%5,%6,%7}, {%8,%9}, {%0,%1,%2,%3};"
        : "+f"(d[0]), "+f"(d[1]), "+f"(d[2]), "+f"(d[3])
        : "r"(a[0]), "r"(a[1]), "r"(a[2]), "r"(a[3]), "r"(b0), "r"(b1));
}

// ---------------- warp math helpers ----------------
static __device__ __forceinline__ float wred(float v) {
#pragma unroll
    for (int o = 16; o > 0; o >>= 1) v += __shfl_xor_sync(0xffffffffu, v, o);
    return v;
}

struct F4 { float x, y, z, w; };

static __device__ __forceinline__ float dotred(const F4 &a, const F4 &b) {
    return wred(a.x*b.x + a.y*b.y + a.z*b.z + a.w*b.w);
}

static __device__ __forceinline__ F4 logmap_f(const F4 &x, float sqx,
                                              const F4 &y, float sqy) {
    float xy  = dotred(x, y);
    float txy = -2.0f * xy;
    float cx  = 1.0f + txy + sqy;
    float cy  = 1.0f - sqx;
    float den = fmaxf(1.0f + txy + sqx*sqy, EPSC);
    float inv = 1.0f / den;
    F4 d;
    d.x = (cy*y.x - cx*x.x) * inv;
    d.y = (cy*y.y - cx*x.y) * inv;
    d.z = (cy*y.z - cx*x.z) * inv;
    d.w = (cy*y.w - cx*x.w) * inv;
    float sqd = dotred(d, d);
    float nd  = sqrtf(fmaxf(sqd, EPS2));
    float s   = fmaxf(cy, EPSC) * atanhf(fminf(nd, CLIPC)) / nd;
    F4 r = { d.x*s, d.y*s, d.z*s, d.w*s };
    return r;
}

static __device__ __forceinline__ void expmap_f(const F4 &x, float sqx, const F4 &v,
                                                F4 &zout, float &sqout) {
    float m   = fmaxf(1.0f - sqx, EPSC);
    float sqv = dotred(v, v);
    float nv  = sqrtf(fmaxf(sqv, EPS2));
    float th  = tanhf(nv / m);
    float sc  = th / nv;
    F4 sec = { v.x*sc, v.y*sc, v.z*sc, v.w*sc };
    float xy = dotred(x, sec);
    float y2 = dotred(sec, sec);
    float ca  = 1.0f + 2.0f*xy + y2;
    float cb  = 1.0f - sqx;
    float den = fmaxf(1.0f + 2.0f*xy + sqx*y2, EPSC);
    float inv = 1.0f / den;
    F4 r = { (ca*x.x + cb*sec.x)*inv, (ca*x.y + cb*sec.y)*inv,
             (ca*x.z + cb*sec.z)*inv, (ca*x.w + cb*sec.w)*inv };
    float sqr = dotred(r, r);
    float nr  = sqrtf(fmaxf(sqr, EPS2));
    if (nr > MAXNC) {
        float s = MAXNC / nr;
        r.x *= s; r.y *= s; r.z *= s; r.w *= s;
        sqr *= s * s;
    }
    zout = r; sqout = sqr;
}

// ============================================================================
// Prep: combined tan weights -> bf16 hi/lo images [d=128][k pitch 104]
// ============================================================================
__global__ void wcomb_kernel(const float* __restrict__ W_t, const float* __restrict__ W_c,
                             const float* __restrict__ W_f, const float* __restrict__ W_r)
{
    int idx = blockIdx.x * 256 + threadIdx.x;   // 12288 total
    if (idx >= 128 * 96) return;
    int d = idx / 96;
    int k = idx - d * 96;
    int st = k / 24, s = k - st * 24;
    const float* W = (st == 0 ? W_t : st == 1 ? W_c : st == 2 ? W_f : W_r);
    float v = __ldg(&W[s * DDIM + d]);
    __nv_bfloat16 hi = __float2bfloat16(v);
    __nv_bfloat16 lo = __float2bfloat16(v - __bfloat162float(hi));
    g_Gh[d * 104 + k] = hi;
    g_Gl[d * 104 + k] = lo;
}

// ============================================================================
// Kernel 1a: tan GEMM on tensor cores + fused expmap0 -> g_z.  (unchanged)
// ============================================================================
#define SM2_AH   0
#define SM2_AL   26112
#define SM2_BH   52224
#define SM2_BL   78848
#define SM2_P    105472
#define SM2_BIAS 106496
#define GEMV_SMEM (106496 + 512)      // 107008 B -> 2 blocks/SM

__global__ void __launch_bounds__(256, 2)
gemv_mma_kernel(const float* __restrict__ trend,  const float* __restrict__ scoarse,
                const float* __restrict__ sfine,  const float* __restrict__ resid,
                const float* __restrict__ b_t, const float* __restrict__ b_c,
                const float* __restrict__ b_f, const float* __restrict__ b_r)
{
    extern __shared__ char smem[];
    const uint32_t sbase = smem_to_u32(smem);
    const int tid  = threadIdx.x;
    const int lane = tid & 31;
    const int wid  = tid >> 5;
    const int mg   = wid >> 1;
    const int ng   = wid & 1;
    const int b    = blockIdx.x / 15;
    const int slot = blockIdx.x - b * 15;

    float* sPart = reinterpret_cast<float*>(smem + SM2_P);
    float* sBias = reinterpret_cast<float*>(smem + SM2_BIAS);

    {
        const uint4* gh = reinterpret_cast<const uint4*>(g_Gh);
        const uint4* gl = reinterpret_cast<const uint4*>(g_Gl);
        for (int i = tid; i < 1664; i += 256) {
            *reinterpret_cast<uint4*>(smem + SM2_BH + i * 16) = __ldg(gh + i);
            *reinterpret_cast<uint4*>(smem + SM2_BL + i * 16) = __ldg(gl + i);
        }
        if (tid < 128)
            sBias[tid] = __ldg(&b_t[tid]) + __ldg(&b_c[tid]) +
                         __ldg(&b_f[tid]) + __ldg(&b_r[tid]);
    }

    const size_t base_b = (size_t)b * LTOT * FEAT;
#pragma unroll
    for (int it = 0; it < 12; ++it) {
        int i  = tid + it * 256;
        int k  = i >> 5;
        int c4 = i & 31;
        int st = k / 24, s = k - st * 24;
        const float* src = (st == 0 ? trend : st == 1 ? scoarse :
                            st == 2 ? sfine : resid);
        float4 v = __ldg(reinterpret_cast<const float4*>(
            &src[base_b + (size_t)(360 + slot * 24 + s) * FEAT]) + c4);
        __nv_bfloat162 h01 = __floats2bfloat162_rn(v.x, v.y);
        __nv_bfloat162 h23 = __floats2bfloat162_rn(v.z, v.w);
        float r0 = v.x - __bfloat162float(__low2bfloat16(h01));
        float r1 = v.y - __bfloat162float(__high2bfloat16(h01));
        float r2 = v.z - __bfloat162float(__low2bfloat16(h23));
        float r3 = v.w - __bfloat162float(__high2bfloat16(h23));
        __nv_bfloat162 l01 = __floats2bfloat162_rn(r0, r1);
        __nv_bfloat162 l23 = __floats2bfloat162_rn(r2, r3);
        uint32_t off = (uint32_t)(k * 136 + c4 * 4) * 2;
        *reinterpret_cast<uint2*>(smem + SM2_AH + off) =
            make_uint2(*reinterpret_cast<uint32_t*>(&h01),
                       *reinterpret_cast<uint32_t*>(&h23));
        *reinterpret_cast<uint2*>(smem + SM2_AL + off) =
            make_uint2(*reinterpret_cast<uint32_t*>(&l01),
                       *reinterpret_cast<uint32_t*>(&l23));
    }
    __syncthreads();

    uint32_t aoffh[2], aoffl[2], boffh[4], boffl[4];
    {
        int kRow = (lane & 7) + ((lane >> 4) << 3);
        int mC8  = ((lane >> 3) & 1) << 3;
#pragma unroll
        for (int mt = 0; mt < 2; ++mt) {
            uint32_t off = (uint32_t)(kRow * 136 + mg * 32 + mt * 16 + mC8) * 2;
            aoffh[mt] = sbase + SM2_AH + off;
            aoffl[mt] = sbase + SM2_AL + off;
        }
        int nB = ((lane >> 4) << 3) + (lane & 7);
        int kB = ((lane >> 3) & 1) << 3;
#pragma unroll
        for (int g4 = 0; g4 < 4; ++g4) {
            uint32_t off = (uint32_t)((ng * 64 + g4 * 16 + nB) * 104 + kB) * 2;
            boffh[g4] = sbase + SM2_BH + off;
            boffl[g4] = sbase + SM2_BL + off;
        }
    }

    float acc[2][8][4];
#pragma unroll
    for (int mt = 0; mt < 2; ++mt)
#pragma unroll
        for (int nt = 0; nt < 8; ++nt)
#pragma unroll
            for (int q = 0; q < 4; ++q) acc[mt][nt][q] = 0.0f;

#pragma unroll
    for (int ks = 0; ks < 6; ++ks) {
        uint32_t ah[2][4], al[2][4];
        ldsm4t(ah[0], aoffh[0] + ks * 16 * 272);
        ldsm4t(ah[1], aoffh[1] + ks * 16 * 272);
        ldsm4t(al[0], aoffl[0] + ks * 16 * 272);
        ldsm4t(al[1], aoffl[1] + ks * 16 * 272);
#pragma unroll
        for (int g4 = 0; g4 < 4; ++g4) {
            uint32_t bh[4], bl[4];
            ldsm4(bh, boffh[g4] + ks * 32);
            ldsm4(bl, boffl[g4] + ks * 32);
#pragma unroll
            for (int mt = 0; mt < 2; ++mt) {
                mma_bf16(acc[mt][2*g4],   ah[mt], bh[0], bh[1]);
                mma_bf16(acc[mt][2*g4+1], ah[mt], bh[2], bh[3]);
                mma_bf16(acc[mt][2*g4],   al[mt], bh[0], bh[1]);
                mma_bf16(acc[mt][2*g4+1], al[mt], bh[2], bh[3]);
                mma_bf16(acc[mt][2*g4],   ah[mt], bl[0], bl[1]);
                mma_bf16(acc[mt][2*g4+1], ah[mt], bl[2], bl[3]);
            }
        }
    }

    float p[2][2];
#pragma unroll
    for (int mt = 0; mt < 2; ++mt) { p[mt][0] = 0.0f; p[mt][1] = 0.0f; }
#pragma unroll
    for (int nt = 0; nt < 8; ++nt) {
        int c = ng * 64 + nt * 8 + 2 * (lane & 3);
        float bx = sBias[c], by = sBias[c + 1];
#pragma unroll
        for (int mt = 0; mt < 2; ++mt) {
            acc[mt][nt][0] += bx; acc[mt][nt][1] += by;
            acc[mt][nt][2] += bx; acc[mt][nt][3] += by;
            p[mt][0] += acc[mt][nt][0]*acc[mt][nt][0] + acc[mt][nt][1]*acc[mt][nt][1];
            p[mt][1] += acc[mt][nt][2]*acc[mt][nt][2] + acc[mt][nt][3]*acc[mt][nt][3];
        }
    }
#pragma unroll
    for (int mt = 0; mt < 2; ++mt) {
#pragma unroll
        for (int h = 0; h < 2; ++h) {
            p[mt][h] += __shfl_xor_sync(0xffffffffu, p[mt][h], 1);
            p[mt][h] += __shfl_xor_sync(0xffffffffu, p[mt][h], 2);
        }
        if ((lane & 3) == 0) {
            int r0 = mg * 32 + mt * 16 + (lane >> 2);
            sPart[r0 * 2 + ng]       = p[mt][0];
            sPart[(r0 + 8) * 2 + ng] = p[mt][1];
        }
    }
    __syncthreads();

    float* gz = &g_z[((size_t)slot * NROWS + (size_t)b * 128) * DDIM];
#pragma unroll
    for (int mt = 0; mt < 2; ++mt) {
        int r0 = mg * 32 + mt * 16 + (lane >> 2);
        float sq0 = sPart[r0 * 2] + sPart[r0 * 2 + 1];
        float sq1 = sPart[(r0 + 8) * 2] + sPart[(r0 + 8) * 2 + 1];
        float n0 = sqrtf(fmaxf(sq0, EPS2));
        float n1 = sqrtf(fmaxf(sq1, EPS2));
        float t0 = tanhf(n0), t1 = tanhf(n1);
        float sc0 = (t0 > MAXNC ? MAXNC : t0) / n0;
        float sc1 = (t1 > MAXNC ? MAXNC : t1) / n1;
#pragma unroll
        for (int nt = 0; nt < 8; ++nt) {
            int c = ng * 64 + nt * 8 + 2 * (lane & 3);
            *reinterpret_cast<float2*>(&gz[r0 * 128 + c]) =
                make_float2(acc[mt][nt][0] * sc0, acc[mt][nt][1] * sc0);
            *reinterpret_cast<float2*>(&gz[(r0 + 8) * 128 + c]) =
                make_float2(acc[mt][nt][2] * sc1, acc[mt][nt][3] * sc1);
        }
    }
}

// ============================================================================
// Kernel 1b: hyperbolic chain (unchanged)
// ============================================================================
static __device__ __forceinline__ F4 ldz(int slot, int row, int lane) {
    float4 v = __ldg(reinterpret_cast<const float4*>(
        &g_z[((size_t)slot * NROWS + row) * DDIM + lane * 4]));
    F4 r = { v.x, v.y, v.z, v.w };
    return r;
}

static __device__ __forceinline__ void store_split(float v0, float v1, float v2, float v3,
                                                   __nv_bfloat16* hi, __nv_bfloat16* lo,
                                                   size_t off) {
    __nv_bfloat162 h01 = __floats2bfloat162_rn(v0, v1);
    __nv_bfloat162 h23 = __floats2bfloat162_rn(v2, v3);
    float r0 = v0 - __bfloat162float(__low2bfloat16(h01));
    float r1 = v1 - __bfloat162float(__high2bfloat16(h01));
    float r2 = v2 - __bfloat162float(__low2bfloat16(h23));
    float r3 = v3 - __bfloat162float(__high2bfloat16(h23));
    __nv_bfloat162 l01 = __floats2bfloat162_rn(r0, r1);
    __nv_bfloat162 l23 = __floats2bfloat162_rn(r2, r3);
    uint2 uh = make_uint2(*reinterpret_cast<uint32_t*>(&h01),
                          *reinterpret_cast<uint32_t*>(&h23));
    uint2 ul = make_uint2(*reinterpret_cast<uint32_t*>(&l01),
                          *reinterpret_cast<uint32_t*>(&l23));
    *reinterpret_cast<uint2*>(hi + off) = uh;
    *reinterpret_cast<uint2*>(lo + off) = ul;
}

__global__ void __launch_bounds__(256, 3)
chain_kernel(const float* __restrict__ alpha_p)
{
    const int tid  = threadIdx.x;
    const int wid  = tid >> 5;
    const int lane = tid & 31;
    const int row  = blockIdx.x * 8 + wid;

    float s = 0.0f, wv = 1.0f;
#pragma unroll
    for (int j = 13; j >= 0; --j) { s += wv; if (j > 0) wv *= DECAYF; }
    const float w0  = wv / s;
    const float w13 = 1.0f / s;
    const float invd = 1.0f / DECAYF;

    F4 za = ldz(0, row, lane);
    F4 zb = ldz(1, row, lane);
    F4 zc = ldz(2, row, lane);
    float sqa = dotred(za, za);
    float sqb = dotred(zb, zb);

    F4 avg = {0,0,0,0};
    F4 vel0, vel1, vel2;
    float wj = w0;

#pragma unroll
    for (int j = 0; j < 14; ++j) {
        F4 vel = logmap_f(za, sqa, zb, sqb);
        avg.x += wj * vel.x; avg.y += wj * vel.y;
        avg.z += wj * vel.z; avg.w += wj * vel.w;
        if (j == 0) vel0 = vel;
        else if (j == 1) vel1 = vel;
        else if (j == 2) vel2 = vel;
        wj *= invd;
        za = zb; sqa = sqb;
        zb = zc; sqb = dotred(zb, zb);
        if (j + 3 < WINN) zc = ldz(j + 3, row, lane);
    }

    const float alpha = __ldg(alpha_p);
    F4 zl = za; float sql = sqa;
#pragma unroll
    for (int k = 0; k < NPREDK; ++k) {
        F4 v = { avg.x * alpha, avg.y * alpha, avg.z * alpha, avg.w * alpha };
        F4 zn; float sqn;
        expmap_f(zl, sql, v, zn, sqn);

        float n  = sqrtf(fmaxf(sqn, EPS2));
        float sc = atanhf(fminf(n, CLIPC)) / n;
        const size_t m = (size_t)k * NROWS + row;
        store_split(zn.x * sc, zn.y * sc, zn.z * sc, zn.w * sc,
                    g_Ah, g_Al, m * DDIM + lane * 4);

        if (k < 3) {
            F4 vn = logmap_f(zl, sql, zn, sqn);
            F4 vk = (k == 0 ? vel0 : (k == 1 ? vel1 : vel2));
            avg.x = (avg.x - w0 * vk.x) * DECAYF + w13 * vn.x;
            avg.y = (avg.y - w0 * vk.y) * DECAYF + w13 * vn.y;
            avg.z = (avg.z - w0 * vk.z) * DECAYF + w13 * vn.z;
            avg.w = (avg.w - w0 * vk.w) * DECAYF + w13 * vn.w;
        }
        zl = zn; sql = sqn;
    }
}

// ============================================================================
// Prep: W1 -> bf16 hi/lo PRE-SWIZZLED dense chunks; W2 packed pairs.
// swizzled elem index within chunk: n*128 + (k ^ ((n&7)<<3))
// ============================================================================
__global__ void w1split_kernel(const float* __restrict__ W1) {
    int idx = blockIdx.x * 256 + threadIdx.x;   // 65536 total
    if (idx >= 4 * 16384) return;
    int nc = idx >> 14;
    int n  = (idx >> 7) & 127;
    int k  = idx & 127;
    float v = __ldg(&W1[(size_t)k * HDIM + nc * 128 + n]);
    __nv_bfloat16 hi = __float2bfloat16(v);
    __nv_bfloat16 lo = __float2bfloat16(v - __bfloat162float(hi));
    size_t off = (size_t)nc * 16384 + n * 128 + (k ^ ((n & 7) << 3));
    g_Bh[off] = hi;
    g_Bl[off] = lo;
}

__global__ void w2p_kernel(const float* __restrict__ W2) {
    int idx = blockIdx.x * 256 + threadIdx.x;   // 6144 total
    if (idx >= HDIM * 12) return;
    int c  = idx / 12;
    int jp = idx - c * 12;
    float a = __ldg(&W2[(size_t)c * 24 + 2 * jp]);
    float b = __ldg(&W2[(size_t)c * 24 + 2 * jp + 1]);
    g_W2p[idx] = pack2(a, b);
}

// ============================================================================
// Kernel 2: MLP via mma.sync, M-tile 64, swizzled tiles, GEMM2 direct from
// fragments.  smem 112.6KB -> 2 CTAs/SM.
// ============================================================================
#define SM_AH 0
#define SM_AL 16384
#define SM_BH 32768
#define SM_BL 65536
#define SM_W2 98304
#define MLP_SMEM (98304 + 14336)      // 112640 B

__global__ void __launch_bounds__(256, 2)
mlp_mma_kernel(const float* __restrict__ b1, const float* __restrict__ b2,
               float* __restrict__ out)
{
    extern __shared__ char smem[];
    const uint32_t sbase = smem_to_u32(smem);
    const int tid  = threadIdx.x;
    const int lane = tid & 31;
    const int wid  = tid >> 5;
    const int mg   = wid >> 1;          // 0..3 : rows mg*16
    const int ng   = wid & 1;           // 0..1 : cols ng*64
    const int m0   = blockIdx.x * 64;

    unsigned long long* W2s = reinterpret_cast<unsigned long long*>(smem + SM_W2);

    // ---- stage A hi/lo (apply swizzle) ----
    {
        const uint4* gah = reinterpret_cast<const uint4*>(&g_Ah[(size_t)m0 * DDIM]);
        const uint4* gal = reinterpret_cast<const uint4*>(&g_Al[(size_t)m0 * DDIM]);
#pragma unroll
        for (int i = tid; i < 1024; i += 256) {
            int r = i >> 4, kc = i & 15;
            uint32_t off = (uint32_t)(r * 256 + ((kc * 16) ^ ((r & 7) << 4)));
            *reinterpret_cast<uint4*>(smem + SM_AH + off) = __ldg(gah + i);
            *reinterpret_cast<uint4*>(smem + SM_AL + off) = __ldg(gal + i);
        }
    }
    // ---- stage B chunk 0 (pre-swizzled: dense copy) + W2 chunk 0 ----
    {
        const uint4* gbh = reinterpret_cast<const uint4*>(g_Bh);
        const uint4* gbl = reinterpret_cast<const uint4*>(g_Bl);
#pragma unroll
        for (int i = tid; i < 2048; i += 256) {
            *reinterpret_cast<uint4*>(smem + SM_BH + i * 16) = __ldg(gbh + i);
            *reinterpret_cast<uint4*>(smem + SM_BL + i * 16) = __ldg(gbl + i);
        }
        for (int i = tid; i < 1536; i += 256) {
            int c = i / 12, q = i - c * 12;
            W2s[c * 14 + q] = __ldg(&g_W2p[i]);
        }
    }
    __syncthreads();

    // ---- fragment addresses (XOR-swizzled) ----
    const int rA = mg * 16 + (lane & 15);
    const uint32_t tmask_a = (uint32_t)((((lane >> 4) << 4)) ^ ((rA & 7) << 4));
    const uint32_t abase_h = sbase + SM_AH + rA * 256;
    const uint32_t abase_l = sbase + SM_AL + rA * 256;
    uint32_t bbase_h[4], bbase_l[4], tmask_b[4];
    {
        int kb16 = ((lane >> 3) & 1) << 4;
#pragma unroll
        for (int g4 = 0; g4 < 4; ++g4) {
            int n = ng * 64 + g4 * 16 + ((lane >> 4) << 3) + (lane & 7);
            tmask_b[g4] = (uint32_t)(kb16 ^ ((n & 7) << 4));
            bbase_h[g4] = sbase + SM_BH + n * 256;
            bbase_l[g4] = sbase + SM_BL + n * 256;
        }
    }

    unsigned long long outp[2][12];
#pragma unroll
    for (int r = 0; r < 2; ++r)
#pragma unroll
        for (int q = 0; q < 12; ++q) outp[r][q] = 0ull;

    for (int nc = 0; nc < 4; ++nc) {
        float acc[8][4];
#pragma unroll
        for (int nt = 0; nt < 8; ++nt)
#pragma unroll
            for (int q = 0; q < 4; ++q) acc[nt][q] = 0.0f;

        // ---- GEMM1 mma loop (3-term bf16 split) ----
#pragma unroll
        for (int ks = 0; ks < 8; ++ks) {
            const uint32_t xo = (uint32_t)(ks * 32);
            uint32_t ah[4], al[4];
            ldsm4(ah, abase_h + (xo ^ tmask_a));
            ldsm4(al, abase_l + (xo ^ tmask_a));
#pragma unroll
            for (int g4 = 0; g4 < 4; ++g4) {
                uint32_t bh[4], bl[4];
                ldsm4(bh, bbase_h[g4] + (xo ^ tmask_b[g4]));
                ldsm4(bl, bbase_l[g4] + (xo ^ tmask_b[g4]));
                mma_bf16(acc[2*g4],   ah, bh[0], bh[1]);
                mma_bf16(acc[2*g4+1], ah, bh[2], bh[3]);
                mma_bf16(acc[2*g4],   al, bh[0], bh[1]);
                mma_bf16(acc[2*g4+1], al, bh[2], bh[3]);
                mma_bf16(acc[2*g4],   ah, bl[0], bl[1]);
                mma_bf16(acc[2*g4+1], ah, bl[2], bl[3]);
            }
        }

        // ---- epilogue: bias + relu + GEMM2 directly from fragments ----
#pragma unroll
        for (int nt = 0; nt < 8; ++nt) {
            int cB = ng * 64 + nt * 8 + 2 * (lane & 3);
            float2 b1v = __ldg(reinterpret_cast<const float2*>(&b1[nc * 128 + cB]));
            float h0 = fmaxf(acc[nt][0] + b1v.x, 0.0f);   // (r0, cB)
            float h1 = fmaxf(acc[nt][1] + b1v.y, 0.0f);   // (r0, cB+1)
            float h2 = fmaxf(acc[nt][2] + b1v.x, 0.0f);   // (r1, cB)
            float h3 = fmaxf(acc[nt][3] + b1v.y, 0.0f);   // (r1, cB+1)
            unsigned long long hh0 = pack2(h0, h0);
            unsigned long long hh1 = pack2(h1, h1);
            unsigned long long hh2 = pack2(h2, h2);
            unsigned long long hh3 = pack2(h3, h3);
            const ulonglong2* wpA = reinterpret_cast<const ulonglong2*>(&W2s[cB * 14]);
            const ulonglong2* wpB = reinterpret_cast<const ulonglong2*>(&W2s[(cB + 1) * 14]);
#pragma unroll
            for (int q = 0; q < 6; ++q) {
                ulonglong2 wa = wpA[q];
                ulonglong2 wb = wpB[q];
                fma2(outp[0][2*q],   hh0, wa.x); fma2(outp[0][2*q+1], hh0, wa.y);
                fma2(outp[0][2*q],   hh1, wb.x); fma2(outp[0][2*q+1], hh1, wb.y);
                fma2(outp[1][2*q],   hh2, wa.x); fma2(outp[1][2*q+1], hh2, wa.y);
                fma2(outp[1][2*q],   hh3, wb.x); fma2(outp[1][2*q+1], hh3, wb.y);
            }
        }

        if (nc < 3) {
            __syncthreads();   // all warps done with B(nc), W2s(nc)
            const uint4* gbh = reinterpret_cast<const uint4*>(
                g_Bh + (size_t)(nc + 1) * 16384);
            const uint4* gbl = reinterpret_cast<const uint4*>(
                g_Bl + (size_t)(nc + 1) * 16384);
#pragma unroll
            for (int i = tid; i < 2048; i += 256) {
                *reinterpret_cast<uint4*>(smem + SM_BH + i * 16) = __ldg(gbh + i);
                *reinterpret_cast<uint4*>(smem + SM_BL + i * 16) = __ldg(gbl + i);
            }
            for (int i = tid; i < 1536; i += 256) {
                int c = i / 12, q = i - c * 12;
                W2s[c * 14 + q] = __ldg(&g_W2p[(nc + 1) * 1536 + i]);
            }
            __syncthreads();
        }
    }

    // ---- reduction: quads (f32x2 adds) then cross-ng via smem ----
    __syncthreads();   // A region now reusable
#pragma unroll
    for (int d = 1; d <= 2; d <<= 1) {
#pragma unroll
        for (int r = 0; r < 2; ++r)
#pragma unroll
            for (int q = 0; q < 12; ++q) {
                unsigned long long o =
                    __shfl_xor_sync(0xffffffffu, outp[r][q], d);
                fadd2(outp[r][q], o);
            }
    }

    float* P1 = reinterpret_cast<float*>(smem);            // [64][24]
    float* Rb = reinterpret_cast<float*>(smem + 8192);     // [64][24]
    if (ng == 1 && (lane & 3) == 0) {
        int r0 = mg * 16 + (lane >> 2);
#pragma unroll
        for (int r = 0; r < 2; ++r) {
            int row = r0 + r * 8;
#pragma unroll
            for (int q = 0; q < 12; ++q) {
                float s0, s1;
                unpack2(outp[r][q], s0, s1);
                P1[row * 24 + 2 * q]     = s0;
                P1[row * 24 + 2 * q + 1] = s1;
            }
        }
    }
    __syncthreads();
    if (ng == 0 && (lane & 3) == 0) {
        int r0 = mg * 16 + (lane >> 2);
#pragma unroll
        for (int r = 0; r < 2; ++r) {
            int row = r0 + r * 8;
#pragma unroll
            for (int q = 0; q < 12; ++q) {
                float s0, s1;
                unpack2(outp[r][q], s0, s1);
                Rb[row * 24 + 2 * q]     = s0 + P1[row * 24 + 2 * q];
                Rb[row * 24 + 2 * q + 1] = s1 + P1[row * 24 + 2 * q + 1];
            }
        }
    }
    __syncthreads();

    // ---- coalesced output write: out[bb, kidx*24 + j, f0 + f] ----
    {
        const int kidx = m0 >> 14;
        const int bf0  = m0 & 16383;
        const int bb   = bf0 >> 7;
        const int f0   = bf0 & 127;
#pragma unroll
        for (int i = tid; i < 1536; i += 256) {
            int j = i >> 6, f = i & 63;
            out[((size_t)bb * 96 + kidx * 24 + j) * 128 + f0 + f] =
                Rb[f * 24 + j] + __ldg(&b2[j]);
        }
    }
}

// ============================================================================
extern "C" void kernel_launch(void* const* d_in, const int* in_sizes, int n_in,
                              void* d_out, int out_size) {
    const float* trend   = (const float*)d_in[0];
    const float* scoarse = (const float*)d_in[1];
    const float* sfine   = (const float*)d_in[2];
    const float* resid   = (const float*)d_in[3];
    const float* W_t = (const float*)d_in[4];
    const float* b_t = (const float*)d_in[5];
    const float* W_c = (const float*)d_in[6];
    const float* b_c = (const float*)d_in[7];
    const float* W_f = (const float*)d_in[8];
    const float* b_f = (const float*)d_in[9];
    const float* W_r = (const float*)d_in[10];
    const float* b_r = (const float*)d_in[11];
    const float* alpha = (const float*)d_in[12];
    const float* W1 = (const float*)d_in[13];
    const float* b1 = (const float*)d_in[14];
    const float* W2 = (const float*)d_in[15];
    const float* b2 = (const float*)d_in[16];

    cudaFuncSetAttribute(mlp_mma_kernel,
                         cudaFuncAttributeMaxDynamicSharedMemorySize, MLP_SMEM);
    cudaFuncSetAttribute(gemv_mma_kernel,
                         cudaFuncAttributeMaxDynamicSharedMemorySize, GEMV_SMEM);

    wcomb_kernel<<<48, 256>>>(W_t, W_c, W_f, W_r);
    w1split_kernel<<<256, 256>>>(W1);
    w2p_kernel<<<24, 256>>>(W2);
    gemv_mma_kernel<<<1920, 256, GEMV_SMEM>>>(trend, scoarse, sfine, resid,
                                              b_t, b_c, b_f, b_r);
    chain_kernel<<<NROWS / 8, 256>>>(alpha);
    mlp_mma_kernel<<<MTOT / 64, 256, MLP_SMEM>>>(b1, b2, (float*)d_out);
}

// round 10
// speedup vs baseline: 2.5455x; 1.2008x over previous
#include <cuda_runtime.h>
#include <cuda_bf16.h>
#include <cstdint>

// ---------------- problem constants ----------------
#define BATCH   128
#define LTOT    720
#define FEAT    128
#define SEGL    24
#define WINN    15
#define NPREDK  4
#define DDIM    128
#define HDIM    512
#define NROWS   (BATCH*FEAT)          // 16384
#define MTOT    (NPREDK*NROWS)        // 65536
#define EPSC    1e-6f
#define EPS2    1e-12f
#define MAXNC   0.99999f
#define CLIPC   0.99999988f
#define DECAYF  0.9f

// global scratch (static __device__, no allocs)
__device__ float g_z[(size_t)WINN * NROWS * DDIM];                  // window z
__device__ float g_zn[(size_t)WINN * NROWS];                        // ||z||^2
__device__ __align__(16) __nv_bfloat16 g_Ah[(size_t)MTOT * DDIM];   // MLP A hi
__device__ __align__(16) __nv_bfloat16 g_Al[(size_t)MTOT * DDIM];   // MLP A lo
// W1 chunk images, PRE-SWIZZLED dense [nc][n=128][k=128] bf16 (32KB chunks)
__device__ __align__(16) __nv_bfloat16 g_Bh[4 * 128 * 128];
__device__ __align__(16) __nv_bfloat16 g_Bl[4 * 128 * 128];
// combined tan weights Wc images: [d=128][k pitch 104] bf16
__device__ __align__(16) __nv_bfloat16 g_Gh[128 * 104];
__device__ __align__(16) __nv_bfloat16 g_Gl[128 * 104];
// W2 B-fragment table: [kb=32][ntile=3][lane=32] uint4 = {b0h,b1h,b0l,b1l}
__device__ __align__(16) uint4 g_W2f[32 * 3 * 32];

// ---------------- mma.sync / ldmatrix helpers ----------------
static __device__ __forceinline__ uint32_t smem_to_u32(const void* p) {
    uint32_t a;
    asm("{ .reg .u64 t; cvta.to.shared.u64 t, %1; cvt.u32.u64 %0, t; }"
        : "=r"(a) : "l"(p));
    return a;
}
static __device__ __forceinline__ void ldsm4(uint32_t r[4], uint32_t addr) {
    asm volatile("ldmatrix.sync.aligned.m8n8.x4.shared.b16 {%0,%1,%2,%3}, [%4];"
                 : "=r"(r[0]), "=r"(r[1]), "=r"(r[2]), "=r"(r[3]) : "r"(addr));
}
static __device__ __forceinline__ void ldsm4t(uint32_t r[4], uint32_t addr) {
    asm volatile("ldmatrix.sync.aligned.m8n8.x4.trans.shared.b16 {%0,%1,%2,%3}, [%4];"
                 : "=r"(r[0]), "=r"(r[1]), "=r"(r[2]), "=r"(r[3]) : "r"(addr));
}
static __device__ __forceinline__ void mma_bf16(float d[4], const uint32_t a[4],
                                                uint32_t b0, uint32_t b1) {
    asm volatile(
        "mma.sync.aligned.m16n8k16.row.col.f32.bf16.bf16.f32 "
        "{%0,%1,%2,%3}, {%4,%5,%6,%7}, {%8,%9}, {%0,%1,%2,%3};"
        : "+f"(d[0]), "+f"(d[1]), "+f"(d[2]), "+f"(d[3])
        : "r"(a[0]), "r"(a[1]), "r"(a[2]), "r"(a[3]), "r"(b0), "r"(b1));
}
static __device__ __forceinline__ uint32_t bits2(__nv_bfloat162 v) {
    return *reinterpret_cast<uint32_t*>(&v);
}

// ---------------- warp math helpers ----------------
static __device__ __forceinline__ float wred(float v) {
#pragma unroll
    for (int o = 16; o > 0; o >>= 1) v += __shfl_xor_sync(0xffffffffu, v, o);
    return v;
}

struct F4 { float x, y, z, w; };

static __device__ __forceinline__ float dotred(const F4 &a, const F4 &b) {
    return wred(a.x*b.x + a.y*b.y + a.z*b.z + a.w*b.w);
}

static __device__ __forceinline__ F4 logmap_f(const F4 &x, float sqx,
                                              const F4 &y, float sqy) {
    float xy  = dotred(x, y);
    float txy = -2.0f * xy;
    float cx  = 1.0f + txy + sqy;
    float cy  = 1.0f - sqx;
    float den = fmaxf(1.0f + txy + sqx*sqy, EPSC);
    float inv = 1.0f / den;
    F4 d;
    d.x = (cy*y.x - cx*x.x) * inv;
    d.y = (cy*y.y - cx*x.y) * inv;
    d.z = (cy*y.z - cx*x.z) * inv;
    d.w = (cy*y.w - cx*x.w) * inv;
    float sqd = dotred(d, d);
    float nd  = sqrtf(fmaxf(sqd, EPS2));
    float s   = fmaxf(cy, EPSC) * atanhf(fminf(nd, CLIPC)) / nd;
    F4 r = { d.x*s, d.y*s, d.z*s, d.w*s };
    return r;
}

static __device__ __forceinline__ void expmap_f(const F4 &x, float sqx, const F4 &v,
                                                F4 &zout, float &sqout) {
    float m   = fmaxf(1.0f - sqx, EPSC);
    float sqv = dotred(v, v);
    float nv  = sqrtf(fmaxf(sqv, EPS2));
    float th  = tanhf(nv / m);
    float sc  = th / nv;
    F4 sec = { v.x*sc, v.y*sc, v.z*sc, v.w*sc };
    float xy = dotred(x, sec);
    float y2 = dotred(sec, sec);
    float ca  = 1.0f + 2.0f*xy + y2;
    float cb  = 1.0f - sqx;
    float den = fmaxf(1.0f + 2.0f*xy + sqx*y2, EPSC);
    float inv = 1.0f / den;
    F4 r = { (ca*x.x + cb*sec.x)*inv, (ca*x.y + cb*sec.y)*inv,
             (ca*x.z + cb*sec.z)*inv, (ca*x.w + cb*sec.w)*inv };
    float sqr = dotred(r, r);
    float nr  = sqrtf(fmaxf(sqr, EPS2));
    if (nr > MAXNC) {
        float s = MAXNC / nr;
        r.x *= s; r.y *= s; r.z *= s; r.w *= s;
        sqr *= s * s;
    }
    zout = r; sqout = sqr;
}

// ============================================================================
// Prep: combined tan weights -> bf16 hi/lo images [d=128][k pitch 104]
// ============================================================================
__global__ void wcomb_kernel(const float* __restrict__ W_t, const float* __restrict__ W_c,
                             const float* __restrict__ W_f, const float* __restrict__ W_r)
{
    int idx = blockIdx.x * 256 + threadIdx.x;   // 12288 total
    if (idx >= 128 * 96) return;
    int d = idx / 96;
    int k = idx - d * 96;
    int st = k / 24, s = k - st * 24;
    const float* W = (st == 0 ? W_t : st == 1 ? W_c : st == 2 ? W_f : W_r);
    float v = __ldg(&W[s * DDIM + d]);
    __nv_bfloat16 hi = __float2bfloat16(v);
    __nv_bfloat16 lo = __float2bfloat16(v - __bfloat162float(hi));
    g_Gh[d * 104 + k] = hi;
    g_Gl[d * 104 + k] = lo;
}

// ============================================================================
// Kernel 1a: tan GEMM on tensor cores + fused expmap0 -> g_z (+ norms g_zn).
// ============================================================================
#define SM2_AH   0
#define SM2_AL   26112
#define SM2_BH   52224
#define SM2_BL   78848
#define SM2_P    105472
#define SM2_BIAS 106496
#define GEMV_SMEM (106496 + 512)      // 107008 B -> 2 blocks/SM

__global__ void __launch_bounds__(256, 2)
gemv_mma_kernel(const float* __restrict__ trend,  const float* __restrict__ scoarse,
                const float* __restrict__ sfine,  const float* __restrict__ resid,
                const float* __restrict__ b_t, const float* __restrict__ b_c,
                const float* __restrict__ b_f, const float* __restrict__ b_r)
{
    extern __shared__ char smem[];
    const uint32_t sbase = smem_to_u32(smem);
    const int tid  = threadIdx.x;
    const int lane = tid & 31;
    const int wid  = tid >> 5;
    const int mg   = wid >> 1;
    const int ng   = wid & 1;
    const int b    = blockIdx.x / 15;
    const int slot = blockIdx.x - b * 15;

    float* sPart = reinterpret_cast<float*>(smem + SM2_P);
    float* sBias = reinterpret_cast<float*>(smem + SM2_BIAS);

    {
        const uint4* gh = reinterpret_cast<const uint4*>(g_Gh);
        const uint4* gl = reinterpret_cast<const uint4*>(g_Gl);
        for (int i = tid; i < 1664; i += 256) {
            *reinterpret_cast<uint4*>(smem + SM2_BH + i * 16) = __ldg(gh + i);
            *reinterpret_cast<uint4*>(smem + SM2_BL + i * 16) = __ldg(gl + i);
        }
        if (tid < 128)
            sBias[tid] = __ldg(&b_t[tid]) + __ldg(&b_c[tid]) +
                         __ldg(&b_f[tid]) + __ldg(&b_r[tid]);
    }

    const size_t base_b = (size_t)b * LTOT * FEAT;
#pragma unroll
    for (int it = 0; it < 12; ++it) {
        int i  = tid + it * 256;
        int k  = i >> 5;
        int c4 = i & 31;
        int st = k / 24, s = k - st * 24;
        const float* src = (st == 0 ? trend : st == 1 ? scoarse :
                            st == 2 ? sfine : resid);
        float4 v = __ldg(reinterpret_cast<const float4*>(
            &src[base_b + (size_t)(360 + slot * 24 + s) * FEAT]) + c4);
        __nv_bfloat162 h01 = __floats2bfloat162_rn(v.x, v.y);
        __nv_bfloat162 h23 = __floats2bfloat162_rn(v.z, v.w);
        float r0 = v.x - __bfloat162float(__low2bfloat16(h01));
        float r1 = v.y - __bfloat162float(__high2bfloat16(h01));
        float r2 = v.z - __bfloat162float(__low2bfloat16(h23));
        float r3 = v.w - __bfloat162float(__high2bfloat16(h23));
        __nv_bfloat162 l01 = __floats2bfloat162_rn(r0, r1);
        __nv_bfloat162 l23 = __floats2bfloat162_rn(r2, r3);
        uint32_t off = (uint32_t)(k * 136 + c4 * 4) * 2;
        *reinterpret_cast<uint2*>(smem + SM2_AH + off) =
            make_uint2(bits2(h01), bits2(h23));
        *reinterpret_cast<uint2*>(smem + SM2_AL + off) =
            make_uint2(bits2(l01), bits2(l23));
    }
    __syncthreads();

    uint32_t aoffh[2], aoffl[2], boffh[4], boffl[4];
    {
        int kRow = (lane & 7) + ((lane >> 4) << 3);
        int mC8  = ((lane >> 3) & 1) << 3;
#pragma unroll
        for (int mt = 0; mt < 2; ++mt) {
            uint32_t off = (uint32_t)(kRow * 136 + mg * 32 + mt * 16 + mC8) * 2;
            aoffh[mt] = sbase + SM2_AH + off;
            aoffl[mt] = sbase + SM2_AL + off;
        }
        int nB = ((lane >> 4) << 3) + (lane & 7);
        int kB = ((lane >> 3) & 1) << 3;
#pragma unroll
        for (int g4 = 0; g4 < 4; ++g4) {
            uint32_t off = (uint32_t)((ng * 64 + g4 * 16 + nB) * 104 + kB) * 2;
            boffh[g4] = sbase + SM2_BH + off;
            boffl[g4] = sbase + SM2_BL + off;
        }
    }

    float acc[2][8][4];
#pragma unroll
    for (int mt = 0; mt < 2; ++mt)
#pragma unroll
        for (int nt = 0; nt < 8; ++nt)
#pragma unroll
            for (int q = 0; q < 4; ++q) acc[mt][nt][q] = 0.0f;

#pragma unroll
    for (int ks = 0; ks < 6; ++ks) {
        uint32_t ah[2][4], al[2][4];
        ldsm4t(ah[0], aoffh[0] + ks * 16 * 272);
        ldsm4t(ah[1], aoffh[1] + ks * 16 * 272);
        ldsm4t(al[0], aoffl[0] + ks * 16 * 272);
        ldsm4t(al[1], aoffl[1] + ks * 16 * 272);
#pragma unroll
        for (int g4 = 0; g4 < 4; ++g4) {
            uint32_t bh[4], bl[4];
            ldsm4(bh, boffh[g4] + ks * 32);
            ldsm4(bl, boffl[g4] + ks * 32);
#pragma unroll
            for (int mt = 0; mt < 2; ++mt) {
                mma_bf16(acc[mt][2*g4],   ah[mt], bh[0], bh[1]);
                mma_bf16(acc[mt][2*g4+1], ah[mt], bh[2], bh[3]);
                mma_bf16(acc[mt][2*g4],   al[mt], bh[0], bh[1]);
                mma_bf16(acc[mt][2*g4+1], al[mt], bh[2], bh[3]);
                mma_bf16(acc[mt][2*g4],   ah[mt], bl[0], bl[1]);
                mma_bf16(acc[mt][2*g4+1], ah[mt], bl[2], bl[3]);
            }
        }
    }

    float p[2][2];
#pragma unroll
    for (int mt = 0; mt < 2; ++mt) { p[mt][0] = 0.0f; p[mt][1] = 0.0f; }
#pragma unroll
    for (int nt = 0; nt < 8; ++nt) {
        int c = ng * 64 + nt * 8 + 2 * (lane & 3);
        float bx = sBias[c], by = sBias[c + 1];
#pragma unroll
        for (int mt = 0; mt < 2; ++mt) {
            acc[mt][nt][0] += bx; acc[mt][nt][1] += by;
            acc[mt][nt][2] += bx; acc[mt][nt][3] += by;
            p[mt][0] += acc[mt][nt][0]*acc[mt][nt][0] + acc[mt][nt][1]*acc[mt][nt][1];
            p[mt][1] += acc[mt][nt][2]*acc[mt][nt][2] + acc[mt][nt][3]*acc[mt][nt][3];
        }
    }
#pragma unroll
    for (int mt = 0; mt < 2; ++mt) {
#pragma unroll
        for (int h = 0; h < 2; ++h) {
            p[mt][h] += __shfl_xor_sync(0xffffffffu, p[mt][h], 1);
            p[mt][h] += __shfl_xor_sync(0xffffffffu, p[mt][h], 2);
        }
        if ((lane & 3) == 0) {
            int r0 = mg * 32 + mt * 16 + (lane >> 2);
            sPart[r0 * 2 + ng]       = p[mt][0];
            sPart[(r0 + 8) * 2 + ng] = p[mt][1];
        }
    }
    __syncthreads();

    float* gz = &g_z[((size_t)slot * NROWS + (size_t)b * 128) * DDIM];
    float* gn = &g_zn[(size_t)slot * NROWS + (size_t)b * 128];
#pragma unroll
    for (int mt = 0; mt < 2; ++mt) {
        int r0 = mg * 32 + mt * 16 + (lane >> 2);
        float sq0 = sPart[r0 * 2] + sPart[r0 * 2 + 1];
        float sq1 = sPart[(r0 + 8) * 2] + sPart[(r0 + 8) * 2 + 1];
        float n0 = sqrtf(fmaxf(sq0, EPS2));
        float n1 = sqrtf(fmaxf(sq1, EPS2));
        float t0 = tanhf(n0), t1 = tanhf(n1);
        float sc0 = (t0 > MAXNC ? MAXNC : t0) / n0;
        float sc1 = (t1 > MAXNC ? MAXNC : t1) / n1;
        if (ng == 0 && (lane & 3) == 0) {
            gn[r0]     = sq0 * sc0 * sc0;
            gn[r0 + 8] = sq1 * sc1 * sc1;
        }
#pragma unroll
        for (int nt = 0; nt < 8; ++nt) {
            int c = ng * 64 + nt * 8 + 2 * (lane & 3);
            *reinterpret_cast<float2*>(&gz[r0 * 128 + c]) =
                make_float2(acc[mt][nt][0] * sc0, acc[mt][nt][1] * sc0);
            *reinterpret_cast<float2*>(&gz[(r0 + 8) * 128 + c]) =
                make_float2(acc[mt][nt][2] * sc1, acc[mt][nt][3] * sc1);
        }
    }
}

// ============================================================================
// Kernel 1b: hyperbolic chain (uses precomputed norms g_zn)
// ============================================================================
static __device__ __forceinline__ F4 ldz(int slot, int row, int lane) {
    float4 v = __ldg(reinterpret_cast<const float4*>(
        &g_z[((size_t)slot * NROWS + row) * DDIM + lane * 4]));
    F4 r = { v.x, v.y, v.z, v.w };
    return r;
}
static __device__ __forceinline__ float ldn(int slot, int row) {
    return __ldg(&g_zn[(size_t)slot * NROWS + row]);
}

static __device__ __forceinline__ void store_split(float v0, float v1, float v2, float v3,
                                                   __nv_bfloat16* hi, __nv_bfloat16* lo,
                                                   size_t off) {
    __nv_bfloat162 h01 = __floats2bfloat162_rn(v0, v1);
    __nv_bfloat162 h23 = __floats2bfloat162_rn(v2, v3);
    float r0 = v0 - __bfloat162float(__low2bfloat16(h01));
    float r1 = v1 - __bfloat162float(__high2bfloat16(h01));
    float r2 = v2 - __bfloat162float(__low2bfloat16(h23));
    float r3 = v3 - __bfloat162float(__high2bfloat16(h23));
    __nv_bfloat162 l01 = __floats2bfloat162_rn(r0, r1);
    __nv_bfloat162 l23 = __floats2bfloat162_rn(r2, r3);
    *reinterpret_cast<uint2*>(hi + off) = make_uint2(bits2(h01), bits2(h23));
    *reinterpret_cast<uint2*>(lo + off) = make_uint2(bits2(l01), bits2(l23));
}

__global__ void __launch_bounds__(256, 3)
chain_kernel(const float* __restrict__ alpha_p)
{
    const int tid  = threadIdx.x;
    const int wid  = tid >> 5;
    const int lane = tid & 31;
    const int row  = blockIdx.x * 8 + wid;

    float s = 0.0f, wv = 1.0f;
#pragma unroll
    for (int j = 13; j >= 0; --j) { s += wv; if (j > 0) wv *= DECAYF; }
    const float w0  = wv / s;
    const float w13 = 1.0f / s;
    const float invd = 1.0f / DECAYF;

    F4 za = ldz(0, row, lane);
    F4 zb = ldz(1, row, lane);
    F4 zc = ldz(2, row, lane);
    float sqa = ldn(0, row);
    float sqb = ldn(1, row);
    float sqc = ldn(2, row);

    F4 avg = {0,0,0,0};
    F4 vel0, vel1, vel2;
    float wj = w0;

#pragma unroll
    for (int j = 0; j < 14; ++j) {
        F4 vel = logmap_f(za, sqa, zb, sqb);
        avg.x += wj * vel.x; avg.y += wj * vel.y;
        avg.z += wj * vel.z; avg.w += wj * vel.w;
        if (j == 0) vel0 = vel;
        else if (j == 1) vel1 = vel;
        else if (j == 2) vel2 = vel;
        wj *= invd;
        za = zb; sqa = sqb;
        zb = zc; sqb = sqc;
        if (j + 3 < WINN) { zc = ldz(j + 3, row, lane); sqc = ldn(j + 3, row); }
    }

    const float alpha = __ldg(alpha_p);
    F4 zl = za; float sql = sqa;
#pragma unroll
    for (int k = 0; k < NPREDK; ++k) {
        F4 v = { avg.x * alpha, avg.y * alpha, avg.z * alpha, avg.w * alpha };
        F4 zn; float sqn;
        expmap_f(zl, sql, v, zn, sqn);

        float n  = sqrtf(fmaxf(sqn, EPS2));
        float sc = atanhf(fminf(n, CLIPC)) / n;
        const size_t m = (size_t)k * NROWS + row;
        store_split(zn.x * sc, zn.y * sc, zn.z * sc, zn.w * sc,
                    g_Ah, g_Al, m * DDIM + lane * 4);

        if (k < 3) {
            F4 vn = logmap_f(zl, sql, zn, sqn);
            F4 vk = (k == 0 ? vel0 : (k == 1 ? vel1 : vel2));
            avg.x = (avg.x - w0 * vk.x) * DECAYF + w13 * vn.x;
            avg.y = (avg.y - w0 * vk.y) * DECAYF + w13 * vn.y;
            avg.z = (avg.z - w0 * vk.z) * DECAYF + w13 * vn.z;
            avg.w = (avg.w - w0 * vk.w) * DECAYF + w13 * vn.w;
        }
        zl = zn; sql = sqn;
    }
}

// ============================================================================
// Prep: W1 -> bf16 hi/lo PRE-SWIZZLED dense chunks; W2 -> B-fragment table.
// ============================================================================
__global__ void w1split_kernel(const float* __restrict__ W1) {
    int idx = blockIdx.x * 256 + threadIdx.x;   // 65536 total
    if (idx >= 4 * 16384) return;
    int nc = idx >> 14;
    int n  = (idx >> 7) & 127;
    int k  = idx & 127;
    float v = __ldg(&W1[(size_t)k * HDIM + nc * 128 + n]);
    __nv_bfloat16 hi = __float2bfloat16(v);
    __nv_bfloat16 lo = __float2bfloat16(v - __bfloat162float(hi));
    size_t off = (size_t)nc * 16384 + n * 128 + (k ^ ((n & 7) << 3));
    g_Bh[off] = hi;
    g_Bl[off] = lo;
}

// g_W2f[(kb*3 + t)*32 + lane] = {b0h, b1h, b0l, b1l} for mma m16n8k16 B frags.
// kb = k-tile (16 hidden dims), t = output n8 tile (j = t*8 + lane>>2).
__global__ void w2f_kernel(const float* __restrict__ W2) {
    int idx = blockIdx.x * 256 + threadIdx.x;   // 3072 total
    if (idx >= 32 * 3 * 32) return;
    int lane = idx & 31;
    int t    = (idx >> 5) % 3;
    int kb   = idx / 96;
    int k0   = kb * 16 + 2 * (lane & 3);
    int n    = t * 8 + (lane >> 2);
    float w00 = __ldg(&W2[(size_t)(k0    ) * 24 + n]);
    float w01 = __ldg(&W2[(size_t)(k0 + 1) * 24 + n]);
    float w08 = __ldg(&W2[(size_t)(k0 + 8) * 24 + n]);
    float w09 = __ldg(&W2[(size_t)(k0 + 9) * 24 + n]);
    __nv_bfloat162 h0 = __floats2bfloat162_rn(w00, w01);
    __nv_bfloat162 h1 = __floats2bfloat162_rn(w08, w09);
    float e00 = w00 - __bfloat162float(__low2bfloat16(h0));
    float e01 = w01 - __bfloat162float(__high2bfloat16(h0));
    float e08 = w08 - __bfloat162float(__low2bfloat16(h1));
    float e09 = w09 - __bfloat162float(__high2bfloat16(h1));
    __nv_bfloat162 l0 = __floats2bfloat162_rn(e00, e01);
    __nv_bfloat162 l1 = __floats2bfloat162_rn(e08, e09);
    uint4 v;
    v.x = bits2(h0); v.y = bits2(h1); v.z = bits2(l0); v.w = bits2(l1);
    g_W2f[(kb * 3 + t) * 32 + lane] = v;
}

// ============================================================================
// Kernel 2: MLP fully on tensor cores.  GEMM1 bf16-split (3 terms) + GEMM2
// via fragment relay (acc -> bf16 hi/lo A-frags -> mma vs W2 B-frag table).
// M-tile 64, swizzled smem tiles, smem 96KB -> 2 CTAs/SM.
// ============================================================================
#define SM_AH 0
#define SM_AL 16384
#define SM_BH 32768
#define SM_BL 65536
#define MLP_SMEM 98304

__global__ void __launch_bounds__(256, 2)
mlp_mma_kernel(const float* __restrict__ b1, const float* __restrict__ b2,
               float* __restrict__ out)
{
    extern __shared__ char smem[];
    const uint32_t sbase = smem_to_u32(smem);
    const int tid  = threadIdx.x;
    const int lane = tid & 31;
    const int wid  = tid >> 5;
    const int mg   = wid >> 1;          // 0..3 : rows mg*16
    const int ng   = wid & 1;           // 0..1 : hidden cols ng*64
    const int m0   = blockIdx.x * 64;

    // ---- stage A hi/lo (apply swizzle) ----
    {
        const uint4* gah = reinterpret_cast<const uint4*>(&g_Ah[(size_t)m0 * DDIM]);
        const uint4* gal = reinterpret_cast<const uint4*>(&g_Al[(size_t)m0 * DDIM]);
#pragma unroll
        for (int i = tid; i < 1024; i += 256) {
            int r = i >> 4, kc = i & 15;
            uint32_t off = (uint32_t)(r * 256 + ((kc * 16) ^ ((r & 7) << 4)));
            *reinterpret_cast<uint4*>(smem + SM_AH + off) = __ldg(gah + i);
            *reinterpret_cast<uint4*>(smem + SM_AL + off) = __ldg(gal + i);
        }
    }
    // ---- stage B chunk 0 (pre-swizzled: dense copy) ----
    {
        const uint4* gbh = reinterpret_cast<const uint4*>(g_Bh);
        const uint4* gbl = reinterpret_cast<const uint4*>(g_Bl);
#pragma unroll
        for (int i = tid; i < 2048; i += 256) {
            *reinterpret_cast<uint4*>(smem + SM_BH + i * 16) = __ldg(gbh + i);
            *reinterpret_cast<uint4*>(smem + SM_BL + i * 16) = __ldg(gbl + i);
        }
    }
    __syncthreads();

    // ---- fragment addresses (XOR-swizzled) ----
    const int rA = mg * 16 + (lane & 15);
    const uint32_t tmask_a = (uint32_t)((((lane >> 4) << 4)) ^ ((rA & 7) << 4));
    const uint32_t abase_h = sbase + SM_AH + rA * 256;
    const uint32_t abase_l = sbase + SM_AL + rA * 256;
    uint32_t bbase_h[4], bbase_l[4], tmask_b[4];
    {
        int kb16 = ((lane >> 3) & 1) << 4;
#pragma unroll
        for (int g4 = 0; g4 < 4; ++g4) {
            int n = ng * 64 + g4 * 16 + ((lane >> 4) << 3) + (lane & 7);
            tmask_b[g4] = (uint32_t)(kb16 ^ ((n & 7) << 4));
            bbase_h[g4] = sbase + SM_BH + n * 256;
            bbase_l[g4] = sbase + SM_BL + n * 256;
        }
    }

    float cacc[3][4];
#pragma unroll
    for (int t = 0; t < 3; ++t)
#pragma unroll
        for (int q = 0; q < 4; ++q) cacc[t][q] = 0.0f;

    for (int nc = 0; nc < 4; ++nc) {
        float acc[8][4];
#pragma unroll
        for (int nt = 0; nt < 8; ++nt)
#pragma unroll
            for (int q = 0; q < 4; ++q) acc[nt][q] = 0.0f;

        // ---- GEMM1 mma loop (3-term bf16 split) ----
#pragma unroll
        for (int ks = 0; ks < 8; ++ks) {
            const uint32_t xo = (uint32_t)(ks * 32);
            uint32_t ah[4], al[4];
            ldsm4(ah, abase_h + (xo ^ tmask_a));
            ldsm4(al, abase_l + (xo ^ tmask_a));
#pragma unroll
            for (int g4 = 0; g4 < 4; ++g4) {
                uint32_t bh[4], bl[4];
                ldsm4(bh, bbase_h[g4] + (xo ^ tmask_b[g4]));
                ldsm4(bl, bbase_l[g4] + (xo ^ tmask_b[g4]));
                mma_bf16(acc[2*g4],   ah, bh[0], bh[1]);
                mma_bf16(acc[2*g4+1], ah, bh[2], bh[3]);
                mma_bf16(acc[2*g4],   al, bh[0], bh[1]);
                mma_bf16(acc[2*g4+1], al, bh[2], bh[3]);
                mma_bf16(acc[2*g4],   ah, bl[0], bl[1]);
                mma_bf16(acc[2*g4+1], ah, bl[2], bl[3]);
            }
        }

        // ---- epilogue: bias + relu -> bf16 hi/lo A-frags -> GEMM2 mma ----
        const int kb0 = nc * 8 + ng * 4;
#pragma unroll
        for (int ks = 0; ks < 4; ++ks) {
            uint32_t ah[4], al[4];
#pragma unroll
            for (int half = 0; half < 2; ++half) {
                int nt = 2 * ks + half;
                int cB = ng * 64 + nt * 8 + 2 * (lane & 3);
                float2 b1v = __ldg(reinterpret_cast<const float2*>(&b1[nc * 128 + cB]));
                float h0 = fmaxf(acc[nt][0] + b1v.x, 0.0f);
                float h1 = fmaxf(acc[nt][1] + b1v.y, 0.0f);
                float h2 = fmaxf(acc[nt][2] + b1v.x, 0.0f);
                float h3 = fmaxf(acc[nt][3] + b1v.y, 0.0f);
                __nv_bfloat162 p01 = __floats2bfloat162_rn(h0, h1);
                __nv_bfloat162 p23 = __floats2bfloat162_rn(h2, h3);
                float e0 = h0 - __bfloat162float(__low2bfloat16(p01));
                float e1 = h1 - __bfloat162float(__high2bfloat16(p01));
                float e2 = h2 - __bfloat162float(__low2bfloat16(p23));
                float e3 = h3 - __bfloat162float(__high2bfloat16(p23));
                __nv_bfloat162 q01 = __floats2bfloat162_rn(e0, e1);
                __nv_bfloat162 q23 = __floats2bfloat162_rn(e2, e3);
                ah[2*half]     = bits2(p01);
                ah[2*half + 1] = bits2(p23);
                al[2*half]     = bits2(q01);
                al[2*half + 1] = bits2(q23);
            }
            // hmm: a-frag order is {rlow-klow, rhigh-klow, rlow-khigh, rhigh-khigh}
            // half=0 wrote indices 0,1 (klow) and half=1 wrote 2,3 (khigh)  ✓
#pragma unroll
            for (int t = 0; t < 3; ++t) {
                uint4 bw = __ldg(&g_W2f[((kb0 + ks) * 3 + t) * 32 + lane]);
                mma_bf16(cacc[t], ah, bw.x, bw.y);
                mma_bf16(cacc[t], al, bw.x, bw.y);
                mma_bf16(cacc[t], ah, bw.z, bw.w);
            }
        }

        if (nc < 3) {
            __syncthreads();   // all warps done with B(nc)
            const uint4* gbh = reinterpret_cast<const uint4*>(
                g_Bh + (size_t)(nc + 1) * 16384);
            const uint4* gbl = reinterpret_cast<const uint4*>(
                g_Bl + (size_t)(nc + 1) * 16384);
#pragma unroll
            for (int i = tid; i < 2048; i += 256) {
                *reinterpret_cast<uint4*>(smem + SM_BH + i * 16) = __ldg(gbh + i);
                *reinterpret_cast<uint4*>(smem + SM_BL + i * 16) = __ldg(gbl + i);
            }
            __syncthreads();
        }
    }

    // ---- cross-ng reduction (smem, reuse A region) + output write ----
    __syncthreads();
    float* P1 = reinterpret_cast<float*>(smem);            // [64][26]
    float* Rb = reinterpret_cast<float*>(smem + 8192);     // [64][26]
    const int r0 = mg * 16 + (lane >> 2);
    if (ng == 1) {
#pragma unroll
        for (int t = 0; t < 3; ++t) {
            int j0 = t * 8 + 2 * (lane & 3);
            P1[r0 * 26 + j0]           = cacc[t][0];
            P1[r0 * 26 + j0 + 1]       = cacc[t][1];
            P1[(r0 + 8) * 26 + j0]     = cacc[t][2];
            P1[(r0 + 8) * 26 + j0 + 1] = cacc[t][3];
        }
    }
    __syncthreads();
    if (ng == 0) {
#pragma unroll
        for (int t = 0; t < 3; ++t) {
            int j0 = t * 8 + 2 * (lane & 3);
            Rb[r0 * 26 + j0]           = cacc[t][0] + P1[r0 * 26 + j0];
            Rb[r0 * 26 + j0 + 1]       = cacc[t][1] + P1[r0 * 26 + j0 + 1];
            Rb[(r0 + 8) * 26 + j0]     = cacc[t][2] + P1[(r0 + 8) * 26 + j0];
            Rb[(r0 + 8) * 26 + j0 + 1] = cacc[t][3] + P1[(r0 + 8) * 26 + j0 + 1];
        }
    }
    __syncthreads();

    {
        const int kidx = m0 >> 14;
        const int bf0  = m0 & 16383;
        const int bb   = bf0 >> 7;
        const int f0   = bf0 & 127;
#pragma unroll
        for (int i = tid; i < 1536; i += 256) {
            int j = i >> 6, f = i & 63;
            out[((size_t)bb * 96 + kidx * 24 + j) * 128 + f0 + f] =
                Rb[f * 26 + j] + __ldg(&b2[j]);
        }
    }
}

// ============================================================================
extern "C" void kernel_launch(void* const* d_in, const int* in_sizes, int n_in,
                              void* d_out, int out_size) {
    const float* trend   = (const float*)d_in[0];
    const float* scoarse = (const float*)d_in[1];
    const float* sfine   = (const float*)d_in[2];
    const float* resid   = (const float*)d_in[3];
    const float* W_t = (const float*)d_in[4];
    const float* b_t = (const float*)d_in[5];
    const float* W_c = (const float*)d_in[6];
    const float* b_c = (const float*)d_in[7];
    const float* W_f = (const float*)d_in[8];
    const float* b_f = (const float*)d_in[9];
    const float* W_r = (const float*)d_in[10];
    const float* b_r = (const float*)d_in[11];
    const float* alpha = (const float*)d_in[12];
    const float* W1 = (const float*)d_in[13];
    const float* b1 = (const float*)d_in[14];
    const float* W2 = (const float*)d_in[15];
    const float* b2 = (const float*)d_in[16];

    cudaFuncSetAttribute(mlp_mma_kernel,
                         cudaFuncAttributeMaxDynamicSharedMemorySize, MLP_SMEM);
    cudaFuncSetAttribute(gemv_mma_kernel,
                         cudaFuncAttributeMaxDynamicSharedMemorySize, GEMV_SMEM);

    wcomb_kernel<<<48, 256>>>(W_t, W_c, W_f, W_r);
    w1split_kernel<<<256, 256>>>(W1);
    w2f_kernel<<<12, 256>>>(W2);
    gemv_mma_kernel<<<1920, 256, GEMV_SMEM>>>(trend, scoarse, sfine, resid,
                                              b_t, b_c, b_f, b_r);
    chain_kernel<<<NROWS / 8, 256>>>(alpha);
    mlp_mma_kernel<<<MTOT / 64, 256, MLP_SMEM>>>(b1, b2, (float*)d_out);
}

// round 11
// speedup vs baseline: 2.8575x; 1.1225x over previous
#include <cuda_runtime.h>
#include <cuda_bf16.h>
#include <cstdint>

// ---------------- problem constants ----------------
#define BATCH   128
#define LTOT    720
#define FEAT    128
#define SEGL    24
#define WINN    15
#define NPREDK  4
#define DDIM    128
#define HDIM    512
#define NROWS   (BATCH*FEAT)          // 16384
#define MTOT    (NPREDK*NROWS)        // 65536
#define EPSC    1e-6f
#define EPS2    1e-12f
#define MAXNC   0.99999f
#define CLIPC   0.99999988f
#define DECAYF  0.9f

// global scratch (static __device__, no allocs)
__device__ float g_z[(size_t)WINN * NROWS * DDIM];                  // window z
__device__ float g_zn[(size_t)WINN * NROWS];                        // ||z||^2
__device__ __align__(16) __nv_bfloat16 g_Ah[(size_t)MTOT * DDIM];   // MLP A hi
__device__ __align__(16) __nv_bfloat16 g_Al[(size_t)MTOT * DDIM];   // MLP A lo
// W1 chunk images, PRE-SWIZZLED dense [nc][n=128][k=128] bf16 (32KB chunks)
__device__ __align__(16) __nv_bfloat16 g_Bh[4 * 128 * 128];
__device__ __align__(16) __nv_bfloat16 g_Bl[4 * 128 * 128];
// W2 B-fragment table: [kb=32][ntile=3][lane=32] uint4 = {b0h,b1h,b0l,b1l}
__device__ __align__(16) uint4 g_W2f[32 * 3 * 32];
// tan combined-weight B-fragment table: [ks=6][t=16][lane=32]
__device__ __align__(16) uint4 g_Gf[6 * 16 * 32];

// ---------------- mma.sync / ldmatrix helpers ----------------
static __device__ __forceinline__ uint32_t smem_to_u32(const void* p) {
    uint32_t a;
    asm("{ .reg .u64 t; cvta.to.shared.u64 t, %1; cvt.u32.u64 %0, t; }"
        : "=r"(a) : "l"(p));
    return a;
}
static __device__ __forceinline__ void ldsm4(uint32_t r[4], uint32_t addr) {
    asm volatile("ldmatrix.sync.aligned.m8n8.x4.shared.b16 {%0,%1,%2,%3}, [%4];"
                 : "=r"(r[0]), "=r"(r[1]), "=r"(r[2]), "=r"(r[3]) : "r"(addr));
}
static __device__ __forceinline__ void ldsm4t(uint32_t r[4], uint32_t addr) {
    asm volatile("ldmatrix.sync.aligned.m8n8.x4.trans.shared.b16 {%0,%1,%2,%3}, [%4];"
                 : "=r"(r[0]), "=r"(r[1]), "=r"(r[2]), "=r"(r[3]) : "r"(addr));
}
static __device__ __forceinline__ void mma_bf16(float d[4], const uint32_t a[4],
                                                uint32_t b0, uint32_t b1) {
    asm volatile(
        "mma.sync.aligned.m16n8k16.row.col.f32.bf16.bf16.f32 "
        "{%0,%1,%2,%3}, {%4,%5,%6,%7}, {%8,%9}, {%0,%1,%2,%3};"
        : "+f"(d[0]), "+f"(d[1]), "+f"(d[2]), "+f"(d[3])
        : "r"(a[0]), "r"(a[1]), "r"(a[2]), "r"(a[3]), "r"(b0), "r"(b1));
}
static __device__ __forceinline__ uint32_t bits2(__nv_bfloat162 v) {
    return *reinterpret_cast<uint32_t*>(&v);
}

// ---------------- warp math helpers ----------------
static __device__ __forceinline__ float wred(float v) {
#pragma unroll
    for (int o = 16; o > 0; o >>= 1) v += __shfl_xor_sync(0xffffffffu, v, o);
    return v;
}

struct F4 { float x, y, z, w; };

static __device__ __forceinline__ float dotred(const F4 &a, const F4 &b) {
    return wred(a.x*b.x + a.y*b.y + a.z*b.z + a.w*b.w);
}

static __device__ __forceinline__ F4 logmap_f(const F4 &x, float sqx,
                                              const F4 &y, float sqy) {
    float xy  = dotred(x, y);
    float txy = -2.0f * xy;
    float cx  = 1.0f + txy + sqy;
    float cy  = 1.0f - sqx;
    float den = fmaxf(1.0f + txy + sqx*sqy, EPSC);
    float inv = 1.0f / den;
    F4 d;
    d.x = (cy*y.x - cx*x.x) * inv;
    d.y = (cy*y.y - cx*x.y) * inv;
    d.z = (cy*y.z - cx*x.z) * inv;
    d.w = (cy*y.w - cx*x.w) * inv;
    float sqd = dotred(d, d);
    float nd  = sqrtf(fmaxf(sqd, EPS2));
    float s   = fmaxf(cy, EPSC) * atanhf(fminf(nd, CLIPC)) / nd;
    F4 r = { d.x*s, d.y*s, d.z*s, d.w*s };
    return r;
}

static __device__ __forceinline__ void expmap_f(const F4 &x, float sqx, const F4 &v,
                                                F4 &zout, float &sqout) {
    float m   = fmaxf(1.0f - sqx, EPSC);
    float sqv = dotred(v, v);
    float nv  = sqrtf(fmaxf(sqv, EPS2));
    float th  = tanhf(nv / m);
    float sc  = th / nv;
    F4 sec = { v.x*sc, v.y*sc, v.z*sc, v.w*sc };
    float xy = dotred(x, sec);
    float y2 = dotred(sec, sec);
    float ca  = 1.0f + 2.0f*xy + y2;
    float cb  = 1.0f - sqx;
    float den = fmaxf(1.0f + 2.0f*xy + sqx*y2, EPSC);
    float inv = 1.0f / den;
    F4 r = { (ca*x.x + cb*sec.x)*inv, (ca*x.y + cb*sec.y)*inv,
             (ca*x.z + cb*sec.z)*inv, (ca*x.w + cb*sec.w)*inv };
    float sqr = dotred(r, r);
    float nr  = sqrtf(fmaxf(sqr, EPS2));
    if (nr > MAXNC) {
        float s = MAXNC / nr;
        r.x *= s; r.y *= s; r.z *= s; r.w *= s;
        sqr *= s * s;
    }
    zout = r; sqout = sqr;
}

// ============================================================================
// Merged prep kernel:
//  [0, 65536)           : W1 -> bf16 hi/lo pre-swizzled dense chunks
//  [65536, 65536+3072)  : W2 -> B-fragment table g_W2f
//  [68608, 68608+3072)  : combined tan weights -> B-fragment table g_Gf
// ============================================================================
__global__ void prep_kernel(const float* __restrict__ W1, const float* __restrict__ W2,
                            const float* __restrict__ W_t, const float* __restrict__ W_c,
                            const float* __restrict__ W_f, const float* __restrict__ W_r)
{
    int idx = blockIdx.x * 256 + threadIdx.x;
    if (idx < 65536) {
        int nc = idx >> 14;
        int n  = (idx >> 7) & 127;
        int k  = idx & 127;
        float v = __ldg(&W1[(size_t)k * HDIM + nc * 128 + n]);
        __nv_bfloat16 hi = __float2bfloat16(v);
        __nv_bfloat16 lo = __float2bfloat16(v - __bfloat162float(hi));
        size_t off = (size_t)nc * 16384 + n * 128 + (k ^ ((n & 7) << 3));
        g_Bh[off] = hi;
        g_Bl[off] = lo;
    } else if (idx < 65536 + 3072) {
        int e = idx - 65536;
        int lane = e & 31;
        int t    = (e >> 5) % 3;
        int kb   = e / 96;
        int k0   = kb * 16 + 2 * (lane & 3);
        int n    = t * 8 + (lane >> 2);
        float w00 = __ldg(&W2[(size_t)(k0    ) * 24 + n]);
        float w01 = __ldg(&W2[(size_t)(k0 + 1) * 24 + n]);
        float w08 = __ldg(&W2[(size_t)(k0 + 8) * 24 + n]);
        float w09 = __ldg(&W2[(size_t)(k0 + 9) * 24 + n]);
        __nv_bfloat162 h0 = __floats2bfloat162_rn(w00, w01);
        __nv_bfloat162 h1 = __floats2bfloat162_rn(w08, w09);
        float e00 = w00 - __bfloat162float(__low2bfloat16(h0));
        float e01 = w01 - __bfloat162float(__high2bfloat16(h0));
        float e08 = w08 - __bfloat162float(__low2bfloat16(h1));
        float e09 = w09 - __bfloat162float(__high2bfloat16(h1));
        __nv_bfloat162 l0 = __floats2bfloat162_rn(e00, e01);
        __nv_bfloat162 l1 = __floats2bfloat162_rn(e08, e09);
        uint4 v;
        v.x = bits2(h0); v.y = bits2(h1); v.z = bits2(l0); v.w = bits2(l1);
        g_W2f[(kb * 3 + t) * 32 + lane] = v;
    } else if (idx < 68608 + 3072) {
        int e = idx - 68608;
        int lane = e & 31;
        int t    = (e >> 5) & 15;
        int ks   = e >> 9;            // 0..5
        int d    = t * 8 + (lane >> 2);
        int k0   = ks * 16 + 2 * (lane & 3);
        float v0, v1, v2, v3;
        {
            int kk[4] = { k0, k0 + 1, k0 + 8, k0 + 9 };
            float vv[4];
#pragma unroll
            for (int q = 0; q < 4; ++q) {
                int k = kk[q];
                int st = k / 24, s = k - st * 24;
                const float* W = (st == 0 ? W_t : st == 1 ? W_c :
                                  st == 2 ? W_f : W_r);
                vv[q] = __ldg(&W[s * DDIM + d]);
            }
            v0 = vv[0]; v1 = vv[1]; v2 = vv[2]; v3 = vv[3];
        }
        __nv_bfloat162 h0 = __floats2bfloat162_rn(v0, v1);
        __nv_bfloat162 h1 = __floats2bfloat162_rn(v2, v3);
        float e0 = v0 - __bfloat162float(__low2bfloat16(h0));
        float e1 = v1 - __bfloat162float(__high2bfloat16(h0));
        float e2 = v2 - __bfloat162float(__low2bfloat16(h1));
        float e3 = v3 - __bfloat162float(__high2bfloat16(h1));
        __nv_bfloat162 l0 = __floats2bfloat162_rn(e0, e1);
        __nv_bfloat162 l1 = __floats2bfloat162_rn(e2, e3);
        uint4 v;
        v.x = bits2(h0); v.y = bits2(h1); v.z = bits2(l0); v.w = bits2(l1);
        g_Gf[(ks * 16 + t) * 32 + lane] = v;
    }
}

// ============================================================================
// Kernel 1a: tan GEMM on tensor cores + fused expmap0 -> g_z (+ norms g_zn).
// B comes from the precomputed fragment table g_Gf (no B smem at all).
// smem 53.8KB -> 2 CTAs/SM with a fat 174KB L1 carveout.
// ============================================================================
#define SM2_AH   0
#define SM2_AL   26112
#define SM2_P    52224
#define SM2_BIAS 53248
#define GEMV_SMEM (53248 + 512)       // 53760 B

__global__ void __launch_bounds__(256, 2)
gemv_mma_kernel(const float* __restrict__ trend,  const float* __restrict__ scoarse,
                const float* __restrict__ sfine,  const float* __restrict__ resid,
                const float* __restrict__ b_t, const float* __restrict__ b_c,
                const float* __restrict__ b_f, const float* __restrict__ b_r)
{
    extern __shared__ char smem[];
    const uint32_t sbase = smem_to_u32(smem);
    const int tid  = threadIdx.x;
    const int lane = tid & 31;
    const int wid  = tid >> 5;
    const int mg   = wid >> 1;
    const int ng   = wid & 1;
    const int b    = blockIdx.x / 15;
    const int slot = blockIdx.x - b * 15;

    float* sPart = reinterpret_cast<float*>(smem + SM2_P);
    float* sBias = reinterpret_cast<float*>(smem + SM2_BIAS);

    if (tid < 128)
        sBias[tid] = __ldg(&b_t[tid]) + __ldg(&b_c[tid]) +
                     __ldg(&b_f[tid]) + __ldg(&b_r[tid]);

    // ---- stage A^T hi/lo: row k = st*24+s is x_st[b][360+slot*24+s][:] ----
    const size_t base_b = (size_t)b * LTOT * FEAT;
#pragma unroll
    for (int it = 0; it < 12; ++it) {
        int i  = tid + it * 256;
        int k  = i >> 5;
        int c4 = i & 31;
        int st = k / 24, s = k - st * 24;
        const float* src = (st == 0 ? trend : st == 1 ? scoarse :
                            st == 2 ? sfine : resid);
        float4 v = __ldg(reinterpret_cast<const float4*>(
            &src[base_b + (size_t)(360 + slot * 24 + s) * FEAT]) + c4);
        __nv_bfloat162 h01 = __floats2bfloat162_rn(v.x, v.y);
        __nv_bfloat162 h23 = __floats2bfloat162_rn(v.z, v.w);
        float r0 = v.x - __bfloat162float(__low2bfloat16(h01));
        float r1 = v.y - __bfloat162float(__high2bfloat16(h01));
        float r2 = v.z - __bfloat162float(__low2bfloat16(h23));
        float r3 = v.w - __bfloat162float(__high2bfloat16(h23));
        __nv_bfloat162 l01 = __floats2bfloat162_rn(r0, r1);
        __nv_bfloat162 l23 = __floats2bfloat162_rn(r2, r3);
        uint32_t off = (uint32_t)(k * 136 + c4 * 4) * 2;
        *reinterpret_cast<uint2*>(smem + SM2_AH + off) =
            make_uint2(bits2(h01), bits2(h23));
        *reinterpret_cast<uint2*>(smem + SM2_AL + off) =
            make_uint2(bits2(l01), bits2(l23));
    }
    __syncthreads();

    // A ldmatrix addresses (trans frags)
    uint32_t aoffh[2], aoffl[2];
    {
        int kRow = (lane & 7) + ((lane >> 4) << 3);
        int mC8  = ((lane >> 3) & 1) << 3;
#pragma unroll
        for (int mt = 0; mt < 2; ++mt) {
            uint32_t off = (uint32_t)(kRow * 136 + mg * 32 + mt * 16 + mC8) * 2;
            aoffh[mt] = sbase + SM2_AH + off;
            aoffl[mt] = sbase + SM2_AL + off;
        }
    }

    float acc[2][8][4];
#pragma unroll
    for (int mt = 0; mt < 2; ++mt)
#pragma unroll
        for (int nt = 0; nt < 8; ++nt)
#pragma unroll
            for (int q = 0; q < 4; ++q) acc[mt][nt][q] = 0.0f;

#pragma unroll
    for (int ks = 0; ks < 6; ++ks) {
        uint32_t ah[2][4], al[2][4];
        ldsm4t(ah[0], aoffh[0] + ks * 16 * 272);
        ldsm4t(ah[1], aoffh[1] + ks * 16 * 272);
        ldsm4t(al[0], aoffl[0] + ks * 16 * 272);
        ldsm4t(al[1], aoffl[1] + ks * 16 * 272);
#pragma unroll
        for (int g4 = 0; g4 < 4; ++g4) {
            const int t0 = ng * 8 + 2 * g4;
            uint4 e0 = __ldg(&g_Gf[(ks * 16 + t0) * 32 + lane]);
            uint4 e1 = __ldg(&g_Gf[(ks * 16 + t0 + 1) * 32 + lane]);
#pragma unroll
            for (int mt = 0; mt < 2; ++mt) {
                mma_bf16(acc[mt][2*g4],   ah[mt], e0.x, e0.y);
                mma_bf16(acc[mt][2*g4+1], ah[mt], e1.x, e1.y);
                mma_bf16(acc[mt][2*g4],   al[mt], e0.x, e0.y);
                mma_bf16(acc[mt][2*g4+1], al[mt], e1.x, e1.y);
                mma_bf16(acc[mt][2*g4],   ah[mt], e0.z, e0.w);
                mma_bf16(acc[mt][2*g4+1], ah[mt], e1.z, e1.w);
            }
        }
    }

    // ---- + bias; row sum-of-squares partials ----
    float p[2][2];
#pragma unroll
    for (int mt = 0; mt < 2; ++mt) { p[mt][0] = 0.0f; p[mt][1] = 0.0f; }
#pragma unroll
    for (int nt = 0; nt < 8; ++nt) {
        int c = ng * 64 + nt * 8 + 2 * (lane & 3);
        float bx = sBias[c], by = sBias[c + 1];
#pragma unroll
        for (int mt = 0; mt < 2; ++mt) {
            acc[mt][nt][0] += bx; acc[mt][nt][1] += by;
            acc[mt][nt][2] += bx; acc[mt][nt][3] += by;
            p[mt][0] += acc[mt][nt][0]*acc[mt][nt][0] + acc[mt][nt][1]*acc[mt][nt][1];
            p[mt][1] += acc[mt][nt][2]*acc[mt][nt][2] + acc[mt][nt][3]*acc[mt][nt][3];
        }
    }
#pragma unroll
    for (int mt = 0; mt < 2; ++mt) {
#pragma unroll
        for (int h = 0; h < 2; ++h) {
            p[mt][h] += __shfl_xor_sync(0xffffffffu, p[mt][h], 1);
            p[mt][h] += __shfl_xor_sync(0xffffffffu, p[mt][h], 2);
        }
        if ((lane & 3) == 0) {
            int r0 = mg * 32 + mt * 16 + (lane >> 2);
            sPart[r0 * 2 + ng]       = p[mt][0];
            sPart[(r0 + 8) * 2 + ng] = p[mt][1];
        }
    }
    __syncthreads();

    float* gz = &g_z[((size_t)slot * NROWS + (size_t)b * 128) * DDIM];
    float* gn = &g_zn[(size_t)slot * NROWS + (size_t)b * 128];
#pragma unroll
    for (int mt = 0; mt < 2; ++mt) {
        int r0 = mg * 32 + mt * 16 + (lane >> 2);
        float sq0 = sPart[r0 * 2] + sPart[r0 * 2 + 1];
        float sq1 = sPart[(r0 + 8) * 2] + sPart[(r0 + 8) * 2 + 1];
        float n0 = sqrtf(fmaxf(sq0, EPS2));
        float n1 = sqrtf(fmaxf(sq1, EPS2));
        float t0 = tanhf(n0), t1 = tanhf(n1);
        float sc0 = (t0 > MAXNC ? MAXNC : t0) / n0;
        float sc1 = (t1 > MAXNC ? MAXNC : t1) / n1;
        if (ng == 0 && (lane & 3) == 0) {
            gn[r0]     = sq0 * sc0 * sc0;
            gn[r0 + 8] = sq1 * sc1 * sc1;
        }
#pragma unroll
        for (int nt = 0; nt < 8; ++nt) {
            int c = ng * 64 + nt * 8 + 2 * (lane & 3);
            *reinterpret_cast<float2*>(&gz[r0 * 128 + c]) =
                make_float2(acc[mt][nt][0] * sc0, acc[mt][nt][1] * sc0);
            *reinterpret_cast<float2*>(&gz[(r0 + 8) * 128 + c]) =
                make_float2(acc[mt][nt][2] * sc1, acc[mt][nt][3] * sc1);
        }
    }
}

// ============================================================================
// Kernel 1b: hyperbolic chain (uses precomputed norms g_zn)
// ============================================================================
static __device__ __forceinline__ F4 ldz(int slot, int row, int lane) {
    float4 v = __ldg(reinterpret_cast<const float4*>(
        &g_z[((size_t)slot * NROWS + row) * DDIM + lane * 4]));
    F4 r = { v.x, v.y, v.z, v.w };
    return r;
}
static __device__ __forceinline__ float ldn(int slot, int row) {
    return __ldg(&g_zn[(size_t)slot * NROWS + row]);
}

static __device__ __forceinline__ void store_split(float v0, float v1, float v2, float v3,
                                                   __nv_bfloat16* hi, __nv_bfloat16* lo,
                                                   size_t off) {
    __nv_bfloat162 h01 = __floats2bfloat162_rn(v0, v1);
    __nv_bfloat162 h23 = __floats2bfloat162_rn(v2, v3);
    float r0 = v0 - __bfloat162float(__low2bfloat16(h01));
    float r1 = v1 - __bfloat162float(__high2bfloat16(h01));
    float r2 = v2 - __bfloat162float(__low2bfloat16(h23));
    float r3 = v3 - __bfloat162float(__high2bfloat16(h23));
    __nv_bfloat162 l01 = __floats2bfloat162_rn(r0, r1);
    __nv_bfloat162 l23 = __floats2bfloat162_rn(r2, r3);
    *reinterpret_cast<uint2*>(hi + off) = make_uint2(bits2(h01), bits2(h23));
    *reinterpret_cast<uint2*>(lo + off) = make_uint2(bits2(l01), bits2(l23));
}

__global__ void __launch_bounds__(256, 3)
chain_kernel(const float* __restrict__ alpha_p)
{
    const int tid  = threadIdx.x;
    const int wid  = tid >> 5;
    const int lane = tid & 31;
    const int row  = blockIdx.x * 8 + wid;

    float s = 0.0f, wv = 1.0f;
#pragma unroll
    for (int j = 13; j >= 0; --j) { s += wv; if (j > 0) wv *= DECAYF; }
    const float w0  = wv / s;
    const float w13 = 1.0f / s;
    const float invd = 1.0f / DECAYF;

    F4 za = ldz(0, row, lane);
    F4 zb = ldz(1, row, lane);
    F4 zc = ldz(2, row, lane);
    float sqa = ldn(0, row);
    float sqb = ldn(1, row);
    float sqc = ldn(2, row);

    F4 avg = {0,0,0,0};
    F4 vel0, vel1, vel2;
    float wj = w0;

#pragma unroll
    for (int j = 0; j < 14; ++j) {
        F4 vel = logmap_f(za, sqa, zb, sqb);
        avg.x += wj * vel.x; avg.y += wj * vel.y;
        avg.z += wj * vel.z; avg.w += wj * vel.w;
        if (j == 0) vel0 = vel;
        else if (j == 1) vel1 = vel;
        else if (j == 2) vel2 = vel;
        wj *= invd;
        za = zb; sqa = sqb;
        zb = zc; sqb = sqc;
        if (j + 3 < WINN) { zc = ldz(j + 3, row, lane); sqc = ldn(j + 3, row); }
    }

    const float alpha = __ldg(alpha_p);
    F4 zl = za; float sql = sqa;
#pragma unroll
    for (int k = 0; k < NPREDK; ++k) {
        F4 v = { avg.x * alpha, avg.y * alpha, avg.z * alpha, avg.w * alpha };
        F4 zn; float sqn;
        expmap_f(zl, sql, v, zn, sqn);

        float n  = sqrtf(fmaxf(sqn, EPS2));
        float sc = atanhf(fminf(n, CLIPC)) / n;
        const size_t m = (size_t)k * NROWS + row;
        store_split(zn.x * sc, zn.y * sc, zn.z * sc, zn.w * sc,
                    g_Ah, g_Al, m * DDIM + lane * 4);

        if (k < 3) {
            F4 vn = logmap_f(zl, sql, zn, sqn);
            F4 vk = (k == 0 ? vel0 : (k == 1 ? vel1 : vel2));
            avg.x = (avg.x - w0 * vk.x) * DECAYF + w13 * vn.x;
            avg.y = (avg.y - w0 * vk.y) * DECAYF + w13 * vn.y;
            avg.z = (avg.z - w0 * vk.z) * DECAYF + w13 * vn.z;
            avg.w = (avg.w - w0 * vk.w) * DECAYF + w13 * vn.w;
        }
        zl = zn; sql = sqn;
    }
}

// ============================================================================
// Kernel 2: MLP fully on tensor cores (GEMM1 split-bf16 + GEMM2 frag relay).
// ============================================================================
#define SM_AH 0
#define SM_AL 16384
#define SM_BH 32768
#define SM_BL 65536
#define MLP_SMEM 98304

__global__ void __launch_bounds__(256, 2)
mlp_mma_kernel(const float* __restrict__ b1, const float* __restrict__ b2,
               float* __restrict__ out)
{
    extern __shared__ char smem[];
    const uint32_t sbase = smem_to_u32(smem);
    const int tid  = threadIdx.x;
    const int lane = tid & 31;
    const int wid  = tid >> 5;
    const int mg   = wid >> 1;          // 0..3 : rows mg*16
    const int ng   = wid & 1;           // 0..1 : hidden cols ng*64
    const int m0   = blockIdx.x * 64;

    // ---- stage A hi/lo (apply swizzle) ----
    {
        const uint4* gah = reinterpret_cast<const uint4*>(&g_Ah[(size_t)m0 * DDIM]);
        const uint4* gal = reinterpret_cast<const uint4*>(&g_Al[(size_t)m0 * DDIM]);
#pragma unroll
        for (int i = tid; i < 1024; i += 256) {
            int r = i >> 4, kc = i & 15;
            uint32_t off = (uint32_t)(r * 256 + ((kc * 16) ^ ((r & 7) << 4)));
            *reinterpret_cast<uint4*>(smem + SM_AH + off) = __ldg(gah + i);
            *reinterpret_cast<uint4*>(smem + SM_AL + off) = __ldg(gal + i);
        }
    }
    // ---- stage B chunk 0 (pre-swizzled: dense copy) ----
    {
        const uint4* gbh = reinterpret_cast<const uint4*>(g_Bh);
        const uint4* gbl = reinterpret_cast<const uint4*>(g_Bl);
#pragma unroll
        for (int i = tid; i < 2048; i += 256) {
            *reinterpret_cast<uint4*>(smem + SM_BH + i * 16) = __ldg(gbh + i);
            *reinterpret_cast<uint4*>(smem + SM_BL + i * 16) = __ldg(gbl + i);
        }
    }
    __syncthreads();

    // ---- fragment addresses (XOR-swizzled) ----
    const int rA = mg * 16 + (lane & 15);
    const uint32_t tmask_a = (uint32_t)((((lane >> 4) << 4)) ^ ((rA & 7) << 4));
    const uint32_t abase_h = sbase + SM_AH + rA * 256;
    const uint32_t abase_l = sbase + SM_AL + rA * 256;
    uint32_t bbase_h[4], bbase_l[4], tmask_b[4];
    {
        int kb16 = ((lane >> 3) & 1) << 4;
#pragma unroll
        for (int g4 = 0; g4 < 4; ++g4) {
            int n = ng * 64 + g4 * 16 + ((lane >> 4) << 3) + (lane & 7);
            tmask_b[g4] = (uint32_t)(kb16 ^ ((n & 7) << 4));
            bbase_h[g4] = sbase + SM_BH + n * 256;
            bbase_l[g4] = sbase + SM_BL + n * 256;
        }
    }

    float cacc[3][4];
#pragma unroll
    for (int t = 0; t < 3; ++t)
#pragma unroll
        for (int q = 0; q < 4; ++q) cacc[t][q] = 0.0f;

    for (int nc = 0; nc < 4; ++nc) {
        float acc[8][4];
#pragma unroll
        for (int nt = 0; nt < 8; ++nt)
#pragma unroll
            for (int q = 0; q < 4; ++q) acc[nt][q] = 0.0f;

        // ---- GEMM1 mma loop (3-term bf16 split) ----
#pragma unroll
        for (int ks = 0; ks < 8; ++ks) {
            const uint32_t xo = (uint32_t)(ks * 32);
            uint32_t ah[4], al[4];
            ldsm4(ah, abase_h + (xo ^ tmask_a));
            ldsm4(al, abase_l + (xo ^ tmask_a));
#pragma unroll
            for (int g4 = 0; g4 < 4; ++g4) {
                uint32_t bh[4], bl[4];
                ldsm4(bh, bbase_h[g4] + (xo ^ tmask_b[g4]));
                ldsm4(bl, bbase_l[g4] + (xo ^ tmask_b[g4]));
                mma_bf16(acc[2*g4],   ah, bh[0], bh[1]);
                mma_bf16(acc[2*g4+1], ah, bh[2], bh[3]);
                mma_bf16(acc[2*g4],   al, bh[0], bh[1]);
                mma_bf16(acc[2*g4+1], al, bh[2], bh[3]);
                mma_bf16(acc[2*g4],   ah, bl[0], bl[1]);
                mma_bf16(acc[2*g4+1], ah, bl[2], bl[3]);
            }
        }

        // ---- epilogue: bias + relu -> bf16 hi/lo A-frags -> GEMM2 mma ----
        const int kb0 = nc * 8 + ng * 4;
#pragma unroll
        for (int ks = 0; ks < 4; ++ks) {
            uint32_t ah[4], al[4];
#pragma unroll
            for (int half = 0; half < 2; ++half) {
                int nt = 2 * ks + half;
                int cB = ng * 64 + nt * 8 + 2 * (lane & 3);
                float2 b1v = __ldg(reinterpret_cast<const float2*>(&b1[nc * 128 + cB]));
                float h0 = fmaxf(acc[nt][0] + b1v.x, 0.0f);
                float h1 = fmaxf(acc[nt][1] + b1v.y, 0.0f);
                float h2 = fmaxf(acc[nt][2] + b1v.x, 0.0f);
                float h3 = fmaxf(acc[nt][3] + b1v.y, 0.0f);
                __nv_bfloat162 p01 = __floats2bfloat162_rn(h0, h1);
                __nv_bfloat162 p23 = __floats2bfloat162_rn(h2, h3);
                float e0 = h0 - __bfloat162float(__low2bfloat16(p01));
                float e1 = h1 - __bfloat162float(__high2bfloat16(p01));
                float e2 = h2 - __bfloat162float(__low2bfloat16(p23));
                float e3 = h3 - __bfloat162float(__high2bfloat16(p23));
                __nv_bfloat162 q01 = __floats2bfloat162_rn(e0, e1);
                __nv_bfloat162 q23 = __floats2bfloat162_rn(e2, e3);
                ah[2*half]     = bits2(p01);
                ah[2*half + 1] = bits2(p23);
                al[2*half]     = bits2(q01);
                al[2*half + 1] = bits2(q23);
            }
#pragma unroll
            for (int t = 0; t < 3; ++t) {
                uint4 bw = __ldg(&g_W2f[((kb0 + ks) * 3 + t) * 32 + lane]);
                mma_bf16(cacc[t], ah, bw.x, bw.y);
                mma_bf16(cacc[t], al, bw.x, bw.y);
                mma_bf16(cacc[t], ah, bw.z, bw.w);
            }
        }

        if (nc < 3) {
            __syncthreads();   // all warps done with B(nc)
            const uint4* gbh = reinterpret_cast<const uint4*>(
                g_Bh + (size_t)(nc + 1) * 16384);
            const uint4* gbl = reinterpret_cast<const uint4*>(
                g_Bl + (size_t)(nc + 1) * 16384);
#pragma unroll
            for (int i = tid; i < 2048; i += 256) {
                *reinterpret_cast<uint4*>(smem + SM_BH + i * 16) = __ldg(gbh + i);
                *reinterpret_cast<uint4*>(smem + SM_BL + i * 16) = __ldg(gbl + i);
            }
            __syncthreads();
        }
    }

    // ---- cross-ng reduction (smem, reuse A region) + output write ----
    __syncthreads();
    float* P1 = reinterpret_cast<float*>(smem);            // [64][26]
    float* Rb = reinterpret_cast<float*>(smem + 8192);     // [64][26]
    const int r0 = mg * 16 + (lane >> 2);
    if (ng == 1) {
#pragma unroll
        for (int t = 0; t < 3; ++t) {
            int j0 = t * 8 + 2 * (lane & 3);
            P1[r0 * 26 + j0]           = cacc[t][0];
            P1[r0 * 26 + j0 + 1]       = cacc[t][1];
            P1[(r0 + 8) * 26 + j0]     = cacc[t][2];
            P1[(r0 + 8) * 26 + j0 + 1] = cacc[t][3];
        }
    }
    __syncthreads();
    if (ng == 0) {
#pragma unroll
        for (int t = 0; t < 3; ++t) {
            int j0 = t * 8 + 2 * (lane & 3);
            Rb[r0 * 26 + j0]           = cacc[t][0] + P1[r0 * 26 + j0];
            Rb[r0 * 26 + j0 + 1]       = cacc[t][1] + P1[r0 * 26 + j0 + 1];
            Rb[(r0 + 8) * 26 + j0]     = cacc[t][2] + P1[(r0 + 8) * 26 + j0];
            Rb[(r0 + 8) * 26 + j0 + 1] = cacc[t][3] + P1[(r0 + 8) * 26 + j0 + 1];
        }
    }
    __syncthreads();

    {
        const int kidx = m0 >> 14;
        const int bf0  = m0 & 16383;
        const int bb   = bf0 >> 7;
        const int f0   = bf0 & 127;
#pragma unroll
        for (int i = tid; i < 1536; i += 256) {
            int j = i >> 6, f = i & 63;
            out[((size_t)bb * 96 + kidx * 24 + j) * 128 + f0 + f] =
                Rb[f * 26 + j] + __ldg(&b2[j]);
        }
    }
}

// ============================================================================
extern "C" void kernel_launch(void* const* d_in, const int* in_sizes, int n_in,
                              void* d_out, int out_size) {
    const float* trend   = (const float*)d_in[0];
    const float* scoarse = (const float*)d_in[1];
    const float* sfine   = (const float*)d_in[2];
    const float* resid   = (const float*)d_in[3];
    const float* W_t = (const float*)d_in[4];
    const float* b_t = (const float*)d_in[5];
    const float* W_c = (const float*)d_in[6];
    const float* b_c = (const float*)d_in[7];
    const float* W_f = (const float*)d_in[8];
    const float* b_f = (const float*)d_in[9];
    const float* W_r = (const float*)d_in[10];
    const float* b_r = (const float*)d_in[11];
    const float* alpha = (const float*)d_in[12];
    const float* W1 = (const float*)d_in[13];
    const float* b1 = (const float*)d_in[14];
    const float* W2 = (const float*)d_in[15];
    const float* b2 = (const float*)d_in[16];

    cudaFuncSetAttribute(mlp_mma_kernel,
                         cudaFuncAttributeMaxDynamicSharedMemorySize, MLP_SMEM);
    cudaFuncSetAttribute(gemv_mma_kernel,
                         cudaFuncAttributeMaxDynamicSharedMemorySize, GEMV_SMEM);

    prep_kernel<<<280, 256>>>(W1, W2, W_t, W_c, W_f, W_r);
    gemv_mma_kernel<<<1920, 256, GEMV_SMEM>>>(trend, scoarse, sfine, resid,
                                              b_t, b_c, b_f, b_r);
    chain_kernel<<<NROWS / 8, 256>>>(alpha);
    mlp_mma_kernel<<<MTOT / 64, 256, MLP_SMEM>>>(b1, b2, (float*)d_out);
}

// round 12
// speedup vs baseline: 2.9166x; 1.0207x over previous
#include <cuda_runtime.h>
#include <cuda_bf16.h>
#include <cstdint>

// ---------------- problem constants ----------------
#define BATCH   128
#define LTOT    720
#define FEAT    128
#define SEGL    24
#define WINN    15
#define NPREDK  4
#define DDIM    128
#define HDIM    512
#define NROWS   (BATCH*FEAT)          // 16384
#define MTOT    (NPREDK*NROWS)        // 65536
#define EPSC    1e-6f
#define EPS2    1e-12f
#define MAXNC   0.99999f
#define CLIPC   0.99999988f
#define DECAYF  0.9f

// global scratch (static __device__, no allocs)
__device__ float g_z[(size_t)WINN * NROWS * DDIM];                  // window z
__device__ float g_zn[(size_t)WINN * NROWS];                        // ||z||^2
__device__ __align__(16) __nv_bfloat16 g_Ah[(size_t)MTOT * DDIM];   // MLP A hi
__device__ __align__(16) __nv_bfloat16 g_Al[(size_t)MTOT * DDIM];   // MLP A lo
// W1 B-fragment table: [nc=4][ks=8][nt=16][lane=32] uint4 = {b0h,b1h,b0l,b1l}
__device__ __align__(16) uint4 g_B1f[4 * 8 * 16 * 32];
// W2 B-fragment table: [kb=32][ntile=3][lane=32]
__device__ __align__(16) uint4 g_W2f[32 * 3 * 32];
// tan combined-weight B-fragment table: [ks=6][t=16][lane=32]
__device__ __align__(16) uint4 g_Gf[6 * 16 * 32];

// ---------------- mma.sync / ldmatrix helpers ----------------
static __device__ __forceinline__ uint32_t smem_to_u32(const void* p) {
    uint32_t a;
    asm("{ .reg .u64 t; cvta.to.shared.u64 t, %1; cvt.u32.u64 %0, t; }"
        : "=r"(a) : "l"(p));
    return a;
}
static __device__ __forceinline__ void ldsm4(uint32_t r[4], uint32_t addr) {
    asm volatile("ldmatrix.sync.aligned.m8n8.x4.shared.b16 {%0,%1,%2,%3}, [%4];"
                 : "=r"(r[0]), "=r"(r[1]), "=r"(r[2]), "=r"(r[3]) : "r"(addr));
}
static __device__ __forceinline__ void ldsm4t(uint32_t r[4], uint32_t addr) {
    asm volatile("ldmatrix.sync.aligned.m8n8.x4.trans.shared.b16 {%0,%1,%2,%3}, [%4];"
                 : "=r"(r[0]), "=r"(r[1]), "=r"(r[2]), "=r"(r[3]) : "r"(addr));
}
static __device__ __forceinline__ void mma_bf16(float d[4], const uint32_t a[4],
                                                uint32_t b0, uint32_t b1) {
    asm volatile(
        "mma.sync.aligned.m16n8k16.row.col.f32.bf16.bf16.f32 "
        "{%0,%1,%2,%3}, {%4,%5,%6,%7}, {%8,%9}, {%0,%1,%2,%3};"
        : "+f"(d[0]), "+f"(d[1]), "+f"(d[2]), "+f"(d[3])
        : "r"(a[0]), "r"(a[1]), "r"(a[2]), "r"(a[3]), "r"(b0), "r"(b1));
}
static __device__ __forceinline__ uint32_t bits2(__nv_bfloat162 v) {
    return *reinterpret_cast<uint32_t*>(&v);
}

// ---------------- warp math helpers ----------------
static __device__ __forceinline__ float wred(float v) {
#pragma unroll
    for (int o = 16; o > 0; o >>= 1) v += __shfl_xor_sync(0xffffffffu, v, o);
    return v;
}

struct F4 { float x, y, z, w; };

static __device__ __forceinline__ float dotred(const F4 &a, const F4 &b) {
    return wred(a.x*b.x + a.y*b.y + a.z*b.z + a.w*b.w);
}

static __device__ __forceinline__ F4 logmap_f(const F4 &x, float sqx,
                                              const F4 &y, float sqy) {
    float xy  = dotred(x, y);
    float txy = -2.0f * xy;
    float cx  = 1.0f + txy + sqy;
    float cy  = 1.0f - sqx;
    float den = fmaxf(1.0f + txy + sqx*sqy, EPSC);
    float inv = 1.0f / den;
    F4 d;
    d.x = (cy*y.x - cx*x.x) * inv;
    d.y = (cy*y.y - cx*x.y) * inv;
    d.z = (cy*y.z - cx*x.z) * inv;
    d.w = (cy*y.w - cx*x.w) * inv;
    float sqd = dotred(d, d);
    float nd  = sqrtf(fmaxf(sqd, EPS2));
    float s   = fmaxf(cy, EPSC) * atanhf(fminf(nd, CLIPC)) / nd;
    F4 r = { d.x*s, d.y*s, d.z*s, d.w*s };
    return r;
}

static __device__ __forceinline__ void expmap_f(const F4 &x, float sqx, const F4 &v,
                                                F4 &zout, float &sqout) {
    float m   = fmaxf(1.0f - sqx, EPSC);
    float sqv = dotred(v, v);
    float nv  = sqrtf(fmaxf(sqv, EPS2));
    float th  = tanhf(nv / m);
    float sc  = th / nv;
    F4 sec = { v.x*sc, v.y*sc, v.z*sc, v.w*sc };
    float xy = dotred(x, sec);
    float y2 = dotred(sec, sec);
    float ca  = 1.0f + 2.0f*xy + y2;
    float cb  = 1.0f - sqx;
    float den = fmaxf(1.0f + 2.0f*xy + sqx*y2, EPSC);
    float inv = 1.0f / den;
    F4 r = { (ca*x.x + cb*sec.x)*inv, (ca*x.y + cb*sec.y)*inv,
             (ca*x.z + cb*sec.z)*inv, (ca*x.w + cb*sec.w)*inv };
    float sqr = dotred(r, r);
    float nr  = sqrtf(fmaxf(sqr, EPS2));
    if (nr > MAXNC) {
        float s = MAXNC / nr;
        r.x *= s; r.y *= s; r.z *= s; r.w *= s;
        sqr *= s * s;
    }
    zout = r; sqout = sqr;
}

// ---------------- hi/lo split of 4 floats into two bf16x2 pairs ------------
static __device__ __forceinline__ void split4(float v0, float v1, float v2, float v3,
                                              uint32_t &h0, uint32_t &h1,
                                              uint32_t &l0, uint32_t &l1) {
    __nv_bfloat162 a = __floats2bfloat162_rn(v0, v1);
    __nv_bfloat162 b = __floats2bfloat162_rn(v2, v3);
    float e0 = v0 - __bfloat162float(__low2bfloat16(a));
    float e1 = v1 - __bfloat162float(__high2bfloat16(a));
    float e2 = v2 - __bfloat162float(__low2bfloat16(b));
    float e3 = v3 - __bfloat162float(__high2bfloat16(b));
    __nv_bfloat162 c = __floats2bfloat162_rn(e0, e1);
    __nv_bfloat162 d = __floats2bfloat162_rn(e2, e3);
    h0 = bits2(a); h1 = bits2(b); l0 = bits2(c); l1 = bits2(d);
}

// ============================================================================
// Merged prep kernel:
//  [0, 16384)             : W1 -> B-fragment table g_B1f
//  [16384, 16384+3072)    : W2 -> B-fragment table g_W2f
//  [19456, 19456+3072)    : combined tan weights -> B-fragment table g_Gf
// ============================================================================
__global__ void prep_kernel(const float* __restrict__ W1, const float* __restrict__ W2,
                            const float* __restrict__ W_t, const float* __restrict__ W_c,
                            const float* __restrict__ W_f, const float* __restrict__ W_r)
{
    int idx = blockIdx.x * 256 + threadIdx.x;
    if (idx < 16384) {
        int lane = idx & 31;
        int nt   = (idx >> 5) & 15;
        int ks   = (idx >> 9) & 7;
        int nc   = idx >> 12;
        int n    = nc * 128 + nt * 8 + (lane >> 2);
        int k0   = ks * 16 + 2 * (lane & 3);
        float w00 = __ldg(&W1[(size_t)(k0    ) * HDIM + n]);
        float w01 = __ldg(&W1[(size_t)(k0 + 1) * HDIM + n]);
        float w08 = __ldg(&W1[(size_t)(k0 + 8) * HDIM + n]);
        float w09 = __ldg(&W1[(size_t)(k0 + 9) * HDIM + n]);
        uint4 v;
        split4(w00, w01, w08, w09, v.x, v.y, v.z, v.w);
        g_B1f[idx] = v;
    } else if (idx < 16384 + 3072) {
        int e = idx - 16384;
        int lane = e & 31;
        int t    = (e >> 5) % 3;
        int kb   = e / 96;
        int k0   = kb * 16 + 2 * (lane & 3);
        int n    = t * 8 + (lane >> 2);
        float w00 = __ldg(&W2[(size_t)(k0    ) * 24 + n]);
        float w01 = __ldg(&W2[(size_t)(k0 + 1) * 24 + n]);
        float w08 = __ldg(&W2[(size_t)(k0 + 8) * 24 + n]);
        float w09 = __ldg(&W2[(size_t)(k0 + 9) * 24 + n]);
        uint4 v;
        split4(w00, w01, w08, w09, v.x, v.y, v.z, v.w);
        g_W2f[(kb * 3 + t) * 32 + lane] = v;
    } else if (idx < 19456 + 3072) {
        int e = idx - 19456;
        int lane = e & 31;
        int t    = (e >> 5) & 15;
        int ks   = e >> 9;            // 0..5
        int d    = t * 8 + (lane >> 2);
        int k0   = ks * 16 + 2 * (lane & 3);
        float vv[4];
        int kk[4] = { k0, k0 + 1, k0 + 8, k0 + 9 };
#pragma unroll
        for (int q = 0; q < 4; ++q) {
            int k = kk[q];
            int st = k / 24, s = k - st * 24;
            const float* W = (st == 0 ? W_t : st == 1 ? W_c :
                              st == 2 ? W_f : W_r);
            vv[q] = __ldg(&W[s * DDIM + d]);
        }
        uint4 v;
        split4(vv[0], vv[1], vv[2], vv[3], v.x, v.y, v.z, v.w);
        g_Gf[(ks * 16 + t) * 32 + lane] = v;
    }
}

// ============================================================================
// Kernel 1a: tan GEMM on tensor cores + fused expmap0 -> g_z (+ norms g_zn).
// B comes from the precomputed fragment table g_Gf (no B smem at all).
// ============================================================================
#define SM2_AH   0
#define SM2_AL   26112
#define SM2_P    52224
#define SM2_BIAS 53248
#define GEMV_SMEM (53248 + 512)       // 53760 B

__global__ void __launch_bounds__(256, 2)
gemv_mma_kernel(const float* __restrict__ trend,  const float* __restrict__ scoarse,
                const float* __restrict__ sfine,  const float* __restrict__ resid,
                const float* __restrict__ b_t, const float* __restrict__ b_c,
                const float* __restrict__ b_f, const float* __restrict__ b_r)
{
    extern __shared__ char smem[];
    const uint32_t sbase = smem_to_u32(smem);
    const int tid  = threadIdx.x;
    const int lane = tid & 31;
    const int wid  = tid >> 5;
    const int mg   = wid >> 1;
    const int ng   = wid & 1;
    const int b    = blockIdx.x / 15;
    const int slot = blockIdx.x - b * 15;

    float* sPart = reinterpret_cast<float*>(smem + SM2_P);
    float* sBias = reinterpret_cast<float*>(smem + SM2_BIAS);

    if (tid < 128)
        sBias[tid] = __ldg(&b_t[tid]) + __ldg(&b_c[tid]) +
                     __ldg(&b_f[tid]) + __ldg(&b_r[tid]);

    // ---- stage A^T hi/lo ----
    const size_t base_b = (size_t)b * LTOT * FEAT;
#pragma unroll
    for (int it = 0; it < 12; ++it) {
        int i  = tid + it * 256;
        int k  = i >> 5;
        int c4 = i & 31;
        int st = k / 24, s = k - st * 24;
        const float* src = (st == 0 ? trend : st == 1 ? scoarse :
                            st == 2 ? sfine : resid);
        float4 v = __ldg(reinterpret_cast<const float4*>(
            &src[base_b + (size_t)(360 + slot * 24 + s) * FEAT]) + c4);
        uint32_t h0, h1, l0, l1;
        split4(v.x, v.y, v.z, v.w, h0, h1, l0, l1);
        uint32_t off = (uint32_t)(k * 136 + c4 * 4) * 2;
        *reinterpret_cast<uint2*>(smem + SM2_AH + off) = make_uint2(h0, h1);
        *reinterpret_cast<uint2*>(smem + SM2_AL + off) = make_uint2(l0, l1);
    }
    __syncthreads();

    uint32_t aoffh[2], aoffl[2];
    {
        int kRow = (lane & 7) + ((lane >> 4) << 3);
        int mC8  = ((lane >> 3) & 1) << 3;
#pragma unroll
        for (int mt = 0; mt < 2; ++mt) {
            uint32_t off = (uint32_t)(kRow * 136 + mg * 32 + mt * 16 + mC8) * 2;
            aoffh[mt] = sbase + SM2_AH + off;
            aoffl[mt] = sbase + SM2_AL + off;
        }
    }

    float acc[2][8][4];
#pragma unroll
    for (int mt = 0; mt < 2; ++mt)
#pragma unroll
        for (int nt = 0; nt < 8; ++nt)
#pragma unroll
            for (int q = 0; q < 4; ++q) acc[mt][nt][q] = 0.0f;

#pragma unroll
    for (int ks = 0; ks < 6; ++ks) {
        uint32_t ah[2][4], al[2][4];
        ldsm4t(ah[0], aoffh[0] + ks * 16 * 272);
        ldsm4t(ah[1], aoffh[1] + ks * 16 * 272);
        ldsm4t(al[0], aoffl[0] + ks * 16 * 272);
        ldsm4t(al[1], aoffl[1] + ks * 16 * 272);
#pragma unroll
        for (int g4 = 0; g4 < 4; ++g4) {
            const int t0 = ng * 8 + 2 * g4;
            uint4 e0 = __ldg(&g_Gf[(ks * 16 + t0) * 32 + lane]);
            uint4 e1 = __ldg(&g_Gf[(ks * 16 + t0 + 1) * 32 + lane]);
#pragma unroll
            for (int mt = 0; mt < 2; ++mt) {
                mma_bf16(acc[mt][2*g4],   ah[mt], e0.x, e0.y);
                mma_bf16(acc[mt][2*g4+1], ah[mt], e1.x, e1.y);
                mma_bf16(acc[mt][2*g4],   al[mt], e0.x, e0.y);
                mma_bf16(acc[mt][2*g4+1], al[mt], e1.x, e1.y);
                mma_bf16(acc[mt][2*g4],   ah[mt], e0.z, e0.w);
                mma_bf16(acc[mt][2*g4+1], ah[mt], e1.z, e1.w);
            }
        }
    }

    float p[2][2];
#pragma unroll
    for (int mt = 0; mt < 2; ++mt) { p[mt][0] = 0.0f; p[mt][1] = 0.0f; }
#pragma unroll
    for (int nt = 0; nt < 8; ++nt) {
        int c = ng * 64 + nt * 8 + 2 * (lane & 3);
        float bx = sBias[c], by = sBias[c + 1];
#pragma unroll
        for (int mt = 0; mt < 2; ++mt) {
            acc[mt][nt][0] += bx; acc[mt][nt][1] += by;
            acc[mt][nt][2] += bx; acc[mt][nt][3] += by;
            p[mt][0] += acc[mt][nt][0]*acc[mt][nt][0] + acc[mt][nt][1]*acc[mt][nt][1];
            p[mt][1] += acc[mt][nt][2]*acc[mt][nt][2] + acc[mt][nt][3]*acc[mt][nt][3];
        }
    }
#pragma unroll
    for (int mt = 0; mt < 2; ++mt) {
#pragma unroll
        for (int h = 0; h < 2; ++h) {
            p[mt][h] += __shfl_xor_sync(0xffffffffu, p[mt][h], 1);
            p[mt][h] += __shfl_xor_sync(0xffffffffu, p[mt][h], 2);
        }
        if ((lane & 3) == 0) {
            int r0 = mg * 32 + mt * 16 + (lane >> 2);
            sPart[r0 * 2 + ng]       = p[mt][0];
            sPart[(r0 + 8) * 2 + ng] = p[mt][1];
        }
    }
    __syncthreads();

    float* gz = &g_z[((size_t)slot * NROWS + (size_t)b * 128) * DDIM];
    float* gn = &g_zn[(size_t)slot * NROWS + (size_t)b * 128];
#pragma unroll
    for (int mt = 0; mt < 2; ++mt) {
        int r0 = mg * 32 + mt * 16 + (lane >> 2);
        float sq0 = sPart[r0 * 2] + sPart[r0 * 2 + 1];
        float sq1 = sPart[(r0 + 8) * 2] + sPart[(r0 + 8) * 2 + 1];
        float n0 = sqrtf(fmaxf(sq0, EPS2));
        float n1 = sqrtf(fmaxf(sq1, EPS2));
        float t0 = tanhf(n0), t1 = tanhf(n1);
        float sc0 = (t0 > MAXNC ? MAXNC : t0) / n0;
        float sc1 = (t1 > MAXNC ? MAXNC : t1) / n1;
        if (ng == 0 && (lane & 3) == 0) {
            gn[r0]     = sq0 * sc0 * sc0;
            gn[r0 + 8] = sq1 * sc1 * sc1;
        }
#pragma unroll
        for (int nt = 0; nt < 8; ++nt) {
            int c = ng * 64 + nt * 8 + 2 * (lane & 3);
            *reinterpret_cast<float2*>(&gz[r0 * 128 + c]) =
                make_float2(acc[mt][nt][0] * sc0, acc[mt][nt][1] * sc0);
            *reinterpret_cast<float2*>(&gz[(r0 + 8) * 128 + c]) =
                make_float2(acc[mt][nt][2] * sc1, acc[mt][nt][3] * sc1);
        }
    }
}

// ============================================================================
// Kernel 1b: hyperbolic chain (uses precomputed norms g_zn)
// ============================================================================
static __device__ __forceinline__ F4 ldz(int slot, int row, int lane) {
    float4 v = __ldg(reinterpret_cast<const float4*>(
        &g_z[((size_t)slot * NROWS + row) * DDIM + lane * 4]));
    F4 r = { v.x, v.y, v.z, v.w };
    return r;
}
static __device__ __forceinline__ float ldn(int slot, int row) {
    return __ldg(&g_zn[(size_t)slot * NROWS + row]);
}

__global__ void __launch_bounds__(256, 3)
chain_kernel(const float* __restrict__ alpha_p)
{
    const int tid  = threadIdx.x;
    const int wid  = tid >> 5;
    const int lane = tid & 31;
    const int row  = blockIdx.x * 8 + wid;

    float s = 0.0f, wv = 1.0f;
#pragma unroll
    for (int j = 13; j >= 0; --j) { s += wv; if (j > 0) wv *= DECAYF; }
    const float w0  = wv / s;
    const float w13 = 1.0f / s;
    const float invd = 1.0f / DECAYF;

    F4 za = ldz(0, row, lane);
    F4 zb = ldz(1, row, lane);
    F4 zc = ldz(2, row, lane);
    float sqa = ldn(0, row);
    float sqb = ldn(1, row);
    float sqc = ldn(2, row);

    F4 avg = {0,0,0,0};
    F4 vel0, vel1, vel2;
    float wj = w0;

#pragma unroll
    for (int j = 0; j < 14; ++j) {
        F4 vel = logmap_f(za, sqa, zb, sqb);
        avg.x += wj * vel.x; avg.y += wj * vel.y;
        avg.z += wj * vel.z; avg.w += wj * vel.w;
        if (j == 0) vel0 = vel;
        else if (j == 1) vel1 = vel;
        else if (j == 2) vel2 = vel;
        wj *= invd;
        za = zb; sqa = sqb;
        zb = zc; sqb = sqc;
        if (j + 3 < WINN) { zc = ldz(j + 3, row, lane); sqc = ldn(j + 3, row); }
    }

    const float alpha = __ldg(alpha_p);
    F4 zl = za; float sql = sqa;
#pragma unroll
    for (int k = 0; k < NPREDK; ++k) {
        F4 v = { avg.x * alpha, avg.y * alpha, avg.z * alpha, avg.w * alpha };
        F4 zn; float sqn;
        expmap_f(zl, sql, v, zn, sqn);

        float n  = sqrtf(fmaxf(sqn, EPS2));
        float sc = atanhf(fminf(n, CLIPC)) / n;
        const size_t m = (size_t)k * NROWS + row;
        uint32_t h0, h1, l0, l1;
        split4(zn.x * sc, zn.y * sc, zn.z * sc, zn.w * sc, h0, h1, l0, l1);
        size_t off = m * DDIM + lane * 4;
        *reinterpret_cast<uint2*>(g_Ah + off) = make_uint2(h0, h1);
        *reinterpret_cast<uint2*>(g_Al + off) = make_uint2(l0, l1);

        if (k < 3) {
            F4 vn = logmap_f(zl, sql, zn, sqn);
            F4 vk = (k == 0 ? vel0 : (k == 1 ? vel1 : vel2));
            avg.x = (avg.x - w0 * vk.x) * DECAYF + w13 * vn.x;
            avg.y = (avg.y - w0 * vk.y) * DECAYF + w13 * vn.y;
            avg.z = (avg.z - w0 * vk.z) * DECAYF + w13 * vn.z;
            avg.w = (avg.w - w0 * vk.w) * DECAYF + w13 * vn.w;
        }
        zl = zn; sql = sqn;
    }
}

// ============================================================================
// Kernel 2: MLP fully on tensor cores.  GEMM1 B comes straight from the
// g_B1f fragment table (no B smem, no staging, no per-chunk syncs);
// GEMM2 via fragment relay vs g_W2f.  smem = A only (32KB).
// ============================================================================
#define SM_AH 0
#define SM_AL 16384
#define MLP_SMEM 32768

__global__ void __launch_bounds__(256, 2)
mlp_mma_kernel(const float* __restrict__ b1, const float* __restrict__ b2,
               float* __restrict__ out)
{
    extern __shared__ char smem[];
    const uint32_t sbase = smem_to_u32(smem);
    const int tid  = threadIdx.x;
    const int lane = tid & 31;
    const int wid  = tid >> 5;
    const int mg   = wid >> 1;          // 0..3 : rows mg*16
    const int ng   = wid & 1;           // 0..1 : hidden cols ng*64
    const int m0   = blockIdx.x * 64;

    // ---- stage A hi/lo (apply swizzle) ----
    {
        const uint4* gah = reinterpret_cast<const uint4*>(&g_Ah[(size_t)m0 * DDIM]);
        const uint4* gal = reinterpret_cast<const uint4*>(&g_Al[(size_t)m0 * DDIM]);
#pragma unroll
        for (int i = tid; i < 1024; i += 256) {
            int r = i >> 4, kc = i & 15;
            uint32_t off = (uint32_t)(r * 256 + ((kc * 16) ^ ((r & 7) << 4)));
            *reinterpret_cast<uint4*>(smem + SM_AH + off) = __ldg(gah + i);
            *reinterpret_cast<uint4*>(smem + SM_AL + off) = __ldg(gal + i);
        }
    }
    __syncthreads();

    // ---- A fragment addresses (XOR-swizzled) ----
    const int rA = mg * 16 + (lane & 15);
    const uint32_t tmask_a = (uint32_t)((((lane >> 4) << 4)) ^ ((rA & 7) << 4));
    const uint32_t abase_h = sbase + SM_AH + rA * 256;
    const uint32_t abase_l = sbase + SM_AL + rA * 256;

    float cacc[3][4];
#pragma unroll
    for (int t = 0; t < 3; ++t)
#pragma unroll
        for (int q = 0; q < 4; ++q) cacc[t][q] = 0.0f;

#pragma unroll
    for (int nc = 0; nc < 4; ++nc) {
        float acc[8][4];
#pragma unroll
        for (int nt = 0; nt < 8; ++nt)
#pragma unroll
            for (int q = 0; q < 4; ++q) acc[nt][q] = 0.0f;

        // ---- GEMM1 mma loop: B frags straight from table ----
        const uint4* btab = &g_B1f[((size_t)nc * 8) * 16 * 32 + ng * 8 * 32 + lane];
#pragma unroll
        for (int ks = 0; ks < 8; ++ks) {
            const uint32_t xo = (uint32_t)(ks * 32);
            uint32_t ah[4], al[4];
            ldsm4(ah, abase_h + (xo ^ tmask_a));
            ldsm4(al, abase_l + (xo ^ tmask_a));
            const uint4* bk = btab + (size_t)ks * 16 * 32;
#pragma unroll
            for (int nt = 0; nt < 8; ++nt) {
                uint4 e = __ldg(bk + nt * 32);
                mma_bf16(acc[nt], ah, e.x, e.y);
                mma_bf16(acc[nt], al, e.x, e.y);
                mma_bf16(acc[nt], ah, e.z, e.w);
            }
        }

        // ---- epilogue: bias + relu -> bf16 hi/lo A-frags -> GEMM2 mma ----
        const int kb0 = nc * 8 + ng * 4;
#pragma unroll
        for (int ks = 0; ks < 4; ++ks) {
            uint32_t ah[4], al[4];
#pragma unroll
            for (int half = 0; half < 2; ++half) {
                int nt = 2 * ks + half;
                int cB = ng * 64 + nt * 8 + 2 * (lane & 3);
                float2 b1v = __ldg(reinterpret_cast<const float2*>(&b1[nc * 128 + cB]));
                float h0 = fmaxf(acc[nt][0] + b1v.x, 0.0f);
                float h1 = fmaxf(acc[nt][1] + b1v.y, 0.0f);
                float h2 = fmaxf(acc[nt][2] + b1v.x, 0.0f);
                float h3 = fmaxf(acc[nt][3] + b1v.y, 0.0f);
                uint32_t p0, p1, q0, q1;
                split4(h0, h1, h2, h3, p0, p1, q0, q1);
                ah[2*half]     = p0;
                ah[2*half + 1] = p1;
                al[2*half]     = q0;
                al[2*half + 1] = q1;
            }
#pragma unroll
            for (int t = 0; t < 3; ++t) {
                uint4 bw = __ldg(&g_W2f[((kb0 + ks) * 3 + t) * 32 + lane]);
                mma_bf16(cacc[t], ah, bw.x, bw.y);
                mma_bf16(cacc[t], al, bw.x, bw.y);
                mma_bf16(cacc[t], ah, bw.z, bw.w);
            }
        }
    }

    // ---- cross-ng reduction (smem, reuse A region) + output write ----
    __syncthreads();
    float* P1 = reinterpret_cast<float*>(smem);            // [64][26]
    float* Rb = reinterpret_cast<float*>(smem + 8192);     // [64][26]
    const int r0 = mg * 16 + (lane >> 2);
    if (ng == 1) {
#pragma unroll
        for (int t = 0; t < 3; ++t) {
            int j0 = t * 8 + 2 * (lane & 3);
            P1[r0 * 26 + j0]           = cacc[t][0];
            P1[r0 * 26 + j0 + 1]       = cacc[t][1];
            P1[(r0 + 8) * 26 + j0]     = cacc[t][2];
            P1[(r0 + 8) * 26 + j0 + 1] = cacc[t][3];
        }
    }
    __syncthreads();
    if (ng == 0) {
#pragma unroll
        for (int t = 0; t < 3; ++t) {
            int j0 = t * 8 + 2 * (lane & 3);
            Rb[r0 * 26 + j0]           = cacc[t][0] + P1[r0 * 26 + j0];
            Rb[r0 * 26 + j0 + 1]       = cacc[t][1] + P1[r0 * 26 + j0 + 1];
            Rb[(r0 + 8) * 26 + j0]     = cacc[t][2] + P1[(r0 + 8) * 26 + j0];
            Rb[(r0 + 8) * 26 + j0 + 1] = cacc[t][3] + P1[(r0 + 8) * 26 + j0 + 1];
        }
    }
    __syncthreads();

    {
        const int kidx = m0 >> 14;
        const int bf0  = m0 & 16383;
        const int bb   = bf0 >> 7;
        const int f0   = bf0 & 127;
#pragma unroll
        for (int i = tid; i < 1536; i += 256) {
            int j = i >> 6, f = i & 63;
            out[((size_t)bb * 96 + kidx * 24 + j) * 128 + f0 + f] =
                Rb[f * 26 + j] + __ldg(&b2[j]);
        }
    }
}

// ============================================================================
extern "C" void kernel_launch(void* const* d_in, const int* in_sizes, int n_in,
                              void* d_out, int out_size) {
    const float* trend   = (const float*)d_in[0];
    const float* scoarse = (const float*)d_in[1];
    const float* sfine   = (const float*)d_in[2];
    const float* resid   = (const float*)d_in[3];
    const float* W_t = (const float*)d_in[4];
    const float* b_t = (const float*)d_in[5];
    const float* W_c = (const float*)d_in[6];
    const float* b_c = (const float*)d_in[7];
    const float* W_f = (const float*)d_in[8];
    const float* b_f = (const float*)d_in[9];
    const float* W_r = (const float*)d_in[10];
    const float* b_r = (const float*)d_in[11];
    const float* alpha = (const float*)d_in[12];
    const float* W1 = (const float*)d_in[13];
    const float* b1 = (const float*)d_in[14];
    const float* W2 = (const float*)d_in[15];
    const float* b2 = (const float*)d_in[16];

    cudaFuncSetAttribute(mlp_mma_kernel,
                         cudaFuncAttributeMaxDynamicSharedMemorySize, MLP_SMEM);
    cudaFuncSetAttribute(gemv_mma_kernel,
                         cudaFuncAttributeMaxDynamicSharedMemorySize, GEMV_SMEM);

    prep_kernel<<<88, 256>>>(W1, W2, W_t, W_c, W_f, W_r);
    gemv_mma_kernel<<<1920, 256, GEMV_SMEM>>>(trend, scoarse, sfine, resid,
                                              b_t, b_c, b_f, b_r);
    chain_kernel<<<NROWS / 8, 256>>>(alpha);
    mlp_mma_kernel<<<MTOT / 64, 256, MLP_SMEM>>>(b1, b2, (float*)d_out);
}